// round 3
// baseline (speedup 1.0000x reference)
#include <cuda_runtime.h>
#include <math.h>

#define NN 50000
#define NE 800000
#define H  64

// ---- scratch (static device globals; no allocation) ----
__device__ float g_xb[2][NN * H];   // ping-pong node states
__device__ float g_e[NE * H];       // encoded edge features
__device__ float g_agg[NN * H];     // per-layer aggregation

typedef unsigned long long ull;

// packed fp32 FMA: d.lo += a.lo*b.lo ; d.hi += a.hi*b.hi
__device__ __forceinline__ void ffma2(ull& d, ull a, ull b) {
    asm("fma.rn.f32x2 %0, %1, %2, %0;" : "+l"(d) : "l"(a), "l"(b));
}
// fold K-parity partial sums + bias
__device__ __forceinline__ float fin(ull a, float b) {
    float lo = __uint_as_float((unsigned)a);
    float hi = __uint_as_float((unsigned)(a >> 32));
    return lo + hi + b;
}

// ============================================================
// Edge message MLP + scatter (the hot kernel)
//   in = [x[src], e, x[dst]] (192) -> relu(W1) -> W2 -> atomicAdd(agg[dst])
// block 256 (8 warps), T=8 edges per warp, f32x2 K-parity accumulation.
// Weight smem layout: per lane (covers cols 2l, 2l+1), per k-pair:
//   16B = {W[k0][c0], W[k1][c0], W[k0][c1], W[k1][c1]}
// lane stride padded (+4 words) -> conflict-free LDS.128.
// ============================================================
__global__ void __launch_bounds__(256) k_msg(const int* __restrict__ ei,
        const float* __restrict__ W1, const float* __restrict__ b1,
        const float* __restrict__ W2, const float* __restrict__ b2, int si) {
    extern __shared__ float sm[];
    float* W1p  = sm;                 // 32 * 388 = 12416
    float* W2p  = W1p + 12416;        // 32 * 132 = 4224
    float* winb = W2p + 4224;         // 8w * 8t * 192 = 12288
    float* hbb  = winb + 12288;       // 8w * 8t * 64  = 4096
    int tid = threadIdx.x;
    for (int i = tid; i < 192 * 64; i += 256) {
        int k = i >> 6, c = i & 63;
        W1p[(c >> 1) * 388 + (k >> 1) * 4 + ((c & 1) << 1) + (k & 1)] = W1[i];
    }
    for (int i = tid; i < 64 * 64; i += 256) {
        int k = i >> 6, c = i & 63;
        W2p[(c >> 1) * 132 + (k >> 1) * 4 + ((c & 1) << 1) + (k & 1)] = W2[i];
    }
    __syncthreads();

    int lane = tid & 31, wid = tid >> 5;
    float2 bb1 = ((const float2*)b1)[lane];
    float2 bb2 = ((const float2*)b2)[lane];
    float* win = winb + wid * 8 * 192;
    float* hb  = hbb  + wid * 8 * 64;
    const float* x = g_xb[si];
    const int* src = ei;
    const int* dst = ei + NE;
    const ulonglong2* w1l = (const ulonglong2*)(W1p + (size_t)lane * 388);
    const ulonglong2* w2l = (const ulonglong2*)(W2p + (size_t)lane * 132);
    int li = lane & 15, half = lane >> 4;

    int gw = blockIdx.x * 8 + wid;
    int nw = gridDim.x * 8;
    for (int base = gw * 8; base < NE; base += nw * 8) {
        // ---- stage 8 edges: [x[src] | e | x[dst]] into win ----
        int d8[8];
        #pragma unroll
        for (int t = 0; t < 8; t++) {
            int e = base + t;
            int s = __ldg(src + e);
            int d = __ldg(dst + e);
            d8[t] = d;
            const float* row = x + (size_t)(half ? d : s) * H;
            float4 v = *(const float4*)(row + li * 4);
            *(float4*)(win + t * 192 + half * 128 + li * 4) = v;
        }
        #pragma unroll
        for (int tp = 0; tp < 4; tp++) {
            int t = tp * 2 + half;
            float4 v = *(const float4*)(g_e + (size_t)(base + t) * H + li * 4);
            *(float4*)(win + t * 192 + 64 + li * 4) = v;
        }
        __syncwarp();

        // ---- layer 1: 192 -> 64, relu ----
        ull a0[8], a1[8];
        #pragma unroll
        for (int t = 0; t < 8; t++) { a0[t] = 0ull; a1[t] = 0ull; }
        #pragma unroll 4
        for (int c = 0; c < 48; c++) {           // 48 chunks of 4 k
            ulonglong2 wA = w1l[2 * c];
            ulonglong2 wB = w1l[2 * c + 1];
            #pragma unroll
            for (int t = 0; t < 8; t++) {
                ulonglong2 v = ((const ulonglong2*)(win + t * 192))[c];
                ffma2(a0[t], wA.x, v.x);
                ffma2(a1[t], wA.y, v.x);
                ffma2(a0[t], wB.x, v.y);
                ffma2(a1[t], wB.y, v.y);
            }
        }
        #pragma unroll
        for (int t = 0; t < 8; t++) {
            float h0 = fmaxf(fin(a0[t], bb1.x), 0.f);
            float h1 = fmaxf(fin(a1[t], bb1.y), 0.f);
            *(float2*)(hb + t * 64 + 2 * lane) = make_float2(h0, h1);
        }
        __syncwarp();

        // ---- layer 2: 64 -> 64 ----
        ull c0[8], c1[8];
        #pragma unroll
        for (int t = 0; t < 8; t++) { c0[t] = 0ull; c1[t] = 0ull; }
        #pragma unroll
        for (int c = 0; c < 16; c++) {
            ulonglong2 wA = w2l[2 * c];
            ulonglong2 wB = w2l[2 * c + 1];
            #pragma unroll
            for (int t = 0; t < 8; t++) {
                ulonglong2 v = ((const ulonglong2*)(hb + t * 64))[c];
                ffma2(c0[t], wA.x, v.x);
                ffma2(c1[t], wA.y, v.x);
                ffma2(c0[t], wB.x, v.y);
                ffma2(c1[t], wB.y, v.y);
            }
        }
        #pragma unroll
        for (int t = 0; t < 8; t++) {
            float o0 = fin(c0[t], bb2.x);
            float o1 = fin(c1[t], bb2.y);
            float* p = g_agg + (size_t)d8[t] * H + 2 * lane;
            atomicAdd(p, o0);
            atomicAdd(p + 1, o1);
        }
        __syncwarp();
    }
}

// ============================================================
// Node update MLP: in = [x, agg] (128) -> relu(W1) -> W2 -> x'
// ============================================================
__global__ void __launch_bounds__(256) k_upd(
        const float* __restrict__ W1, const float* __restrict__ b1,
        const float* __restrict__ W2, const float* __restrict__ b2,
        int si, int di) {
    extern __shared__ float sm[];
    float* W1p  = sm;                 // 32 * 260 = 8320
    float* W2p  = W1p + 8320;         // 4224
    float* winb = W2p + 4224;         // 8w * 8t * 128 = 8192
    float* hbb  = winb + 8192;        // 4096
    int tid = threadIdx.x;
    for (int i = tid; i < 128 * 64; i += 256) {
        int k = i >> 6, c = i & 63;
        W1p[(c >> 1) * 260 + (k >> 1) * 4 + ((c & 1) << 1) + (k & 1)] = W1[i];
    }
    for (int i = tid; i < 64 * 64; i += 256) {
        int k = i >> 6, c = i & 63;
        W2p[(c >> 1) * 132 + (k >> 1) * 4 + ((c & 1) << 1) + (k & 1)] = W2[i];
    }
    __syncthreads();

    int lane = tid & 31, wid = tid >> 5;
    float2 bb1 = ((const float2*)b1)[lane];
    float2 bb2 = ((const float2*)b2)[lane];
    float* win = winb + wid * 8 * 128;
    float* hb  = hbb  + wid * 8 * 64;
    const float* xs = g_xb[si];
    float* xd = g_xb[di];
    const ulonglong2* w1l = (const ulonglong2*)(W1p + (size_t)lane * 260);
    const ulonglong2* w2l = (const ulonglong2*)(W2p + (size_t)lane * 132);
    int li = lane & 15, half = lane >> 4;

    int gw = blockIdx.x * 8 + wid;
    int nw = gridDim.x * 8;
    for (int base = gw * 8; base < NN; base += nw * 8) {
        #pragma unroll
        for (int t = 0; t < 8; t++) {
            int n = base + t;
            const float* row = half ? (g_agg + (size_t)n * H) : (xs + (size_t)n * H);
            float4 v = *(const float4*)(row + li * 4);
            *(float4*)(win + t * 128 + half * 64 + li * 4) = v;
        }
        __syncwarp();

        ull a0[8], a1[8];
        #pragma unroll
        for (int t = 0; t < 8; t++) { a0[t] = 0ull; a1[t] = 0ull; }
        #pragma unroll 4
        for (int c = 0; c < 32; c++) {
            ulonglong2 wA = w1l[2 * c];
            ulonglong2 wB = w1l[2 * c + 1];
            #pragma unroll
            for (int t = 0; t < 8; t++) {
                ulonglong2 v = ((const ulonglong2*)(win + t * 128))[c];
                ffma2(a0[t], wA.x, v.x);
                ffma2(a1[t], wA.y, v.x);
                ffma2(a0[t], wB.x, v.y);
                ffma2(a1[t], wB.y, v.y);
            }
        }
        #pragma unroll
        for (int t = 0; t < 8; t++) {
            float h0 = fmaxf(fin(a0[t], bb1.x), 0.f);
            float h1 = fmaxf(fin(a1[t], bb1.y), 0.f);
            *(float2*)(hb + t * 64 + 2 * lane) = make_float2(h0, h1);
        }
        __syncwarp();

        ull c0[8], c1[8];
        #pragma unroll
        for (int t = 0; t < 8; t++) { c0[t] = 0ull; c1[t] = 0ull; }
        #pragma unroll
        for (int c = 0; c < 16; c++) {
            ulonglong2 wA = w2l[2 * c];
            ulonglong2 wB = w2l[2 * c + 1];
            #pragma unroll
            for (int t = 0; t < 8; t++) {
                ulonglong2 v = ((const ulonglong2*)(hb + t * 64))[c];
                ffma2(c0[t], wA.x, v.x);
                ffma2(c1[t], wA.y, v.x);
                ffma2(c0[t], wB.x, v.y);
                ffma2(c1[t], wB.y, v.y);
            }
        }
        #pragma unroll
        for (int t = 0; t < 8; t++) {
            float o0 = fin(c0[t], bb2.x);
            float o1 = fin(c1[t], bb2.y);
            *(float2*)(xd + (size_t)(base + t) * H + 2 * lane) = make_float2(o0, o1);
        }
        __syncwarp();
    }
}

// ============================================================
// Node encoder: x0 = nf @ W + b    [NN,128] x [128,64]
// ============================================================
__global__ void __launch_bounds__(256) k_enc_node(const float* __restrict__ nf,
        const float* __restrict__ W, const float* __restrict__ b) {
    extern __shared__ float sm[];
    float* Wp   = sm;                 // 8320
    float* winb = Wp + 8320;          // 8192
    int tid = threadIdx.x;
    for (int i = tid; i < 128 * 64; i += 256) {
        int k = i >> 6, c = i & 63;
        Wp[(c >> 1) * 260 + (k >> 1) * 4 + ((c & 1) << 1) + (k & 1)] = W[i];
    }
    __syncthreads();

    int lane = tid & 31, wid = tid >> 5;
    float2 bb = ((const float2*)b)[lane];
    float* win = winb + wid * 8 * 128;
    const ulonglong2* wl = (const ulonglong2*)(Wp + (size_t)lane * 260);

    int gw = blockIdx.x * 8 + wid;
    int nw = gridDim.x * 8;
    for (int base = gw * 8; base < NN; base += nw * 8) {
        #pragma unroll
        for (int t = 0; t < 8; t++) {
            float4 v = *(const float4*)(nf + (size_t)(base + t) * 128 + lane * 4);
            *(float4*)(win + t * 128 + lane * 4) = v;
        }
        __syncwarp();
        ull a0[8], a1[8];
        #pragma unroll
        for (int t = 0; t < 8; t++) { a0[t] = 0ull; a1[t] = 0ull; }
        #pragma unroll 4
        for (int c = 0; c < 32; c++) {
            ulonglong2 wA = wl[2 * c];
            ulonglong2 wB = wl[2 * c + 1];
            #pragma unroll
            for (int t = 0; t < 8; t++) {
                ulonglong2 v = ((const ulonglong2*)(win + t * 128))[c];
                ffma2(a0[t], wA.x, v.x);
                ffma2(a1[t], wA.y, v.x);
                ffma2(a0[t], wB.x, v.y);
                ffma2(a1[t], wB.y, v.y);
            }
        }
        #pragma unroll
        for (int t = 0; t < 8; t++) {
            float o0 = fin(a0[t], bb.x);
            float o1 = fin(a1[t], bb.y);
            *(float2*)(g_xb[0] + (size_t)(base + t) * H + 2 * lane) = make_float2(o0, o1);
        }
        __syncwarp();
    }
}

// ============================================================
// Edge encoder: e = ef @ W + b     [NE,64] x [64,64]
// ============================================================
__global__ void __launch_bounds__(256) k_enc_edge(const float* __restrict__ ef,
        const float* __restrict__ W, const float* __restrict__ b) {
    extern __shared__ float sm[];
    float* Wp   = sm;                 // 4224
    float* winb = Wp + 4224;          // 8w * 8t * 64 = 4096
    int tid = threadIdx.x;
    for (int i = tid; i < 64 * 64; i += 256) {
        int k = i >> 6, c = i & 63;
        Wp[(c >> 1) * 132 + (k >> 1) * 4 + ((c & 1) << 1) + (k & 1)] = W[i];
    }
    __syncthreads();

    int lane = tid & 31, wid = tid >> 5;
    float2 bb = ((const float2*)b)[lane];
    float* win = winb + wid * 8 * 64;
    const ulonglong2* wl = (const ulonglong2*)(Wp + (size_t)lane * 132);
    int li = lane & 15, half = lane >> 4;

    int gw = blockIdx.x * 8 + wid;
    int nw = gridDim.x * 8;
    for (int base = gw * 8; base < NE; base += nw * 8) {
        #pragma unroll
        for (int tp = 0; tp < 4; tp++) {
            int t = tp * 2 + half;
            float4 v = *(const float4*)(ef + (size_t)(base + t) * H + li * 4);
            *(float4*)(win + t * 64 + li * 4) = v;
        }
        __syncwarp();
        ull a0[8], a1[8];
        #pragma unroll
        for (int t = 0; t < 8; t++) { a0[t] = 0ull; a1[t] = 0ull; }
        #pragma unroll
        for (int c = 0; c < 16; c++) {
            ulonglong2 wA = wl[2 * c];
            ulonglong2 wB = wl[2 * c + 1];
            #pragma unroll
            for (int t = 0; t < 8; t++) {
                ulonglong2 v = ((const ulonglong2*)(win + t * 64))[c];
                ffma2(a0[t], wA.x, v.x);
                ffma2(a1[t], wA.y, v.x);
                ffma2(a0[t], wB.x, v.y);
                ffma2(a1[t], wB.y, v.y);
            }
        }
        #pragma unroll
        for (int t = 0; t < 8; t++) {
            float o0 = fin(a0[t], bb.x);
            float o1 = fin(a1[t], bb.y);
            *(float2*)(g_e + (size_t)(base + t) * H + 2 * lane) = make_float2(o0, o1);
        }
        __syncwarp();
    }
}

// ============================================================
// Zero the aggregation buffer
// ============================================================
__global__ void k_zero() {
    int i = blockIdx.x * blockDim.x + threadIdx.x;
    if (i < NN * H) g_agg[i] = 0.f;
}

// ============================================================
// Constraints head + output writeback
// ============================================================
__global__ void k_con(const float* __restrict__ W1, const float* __restrict__ b1,
                      const float* __restrict__ w2, const float* __restrict__ b2,
                      int si, float* __restrict__ out) {
    __shared__ float Ws[H * H];
    __shared__ float bs[H];
    __shared__ float w2s[H];
    __shared__ float xb[8][H];
    __shared__ float b2v;
    int tid = threadIdx.x;
    for (int i = tid; i < H * H; i += blockDim.x) Ws[i] = W1[i];
    if (tid < H) { bs[tid] = b1[tid]; w2s[tid] = w2[tid]; }
    if (tid == 0) b2v = b2[0];
    __syncthreads();

    const float* xs = g_xb[si];
    int lane = tid & 31, wid = tid >> 5;
    int gw = blockIdx.x * 8 + wid;
    int nw = gridDim.x * 8;
    for (int n = gw; n < NN; n += nw) {
        float xv0 = xs[(size_t)n * H + lane];
        float xv1 = xs[(size_t)n * H + lane + 32];
        out[(size_t)n * H + lane]      = xv0;
        out[(size_t)n * H + lane + 32] = xv1;
        xb[wid][lane]      = xv0;
        xb[wid][lane + 32] = xv1;
        __syncwarp();
        float a0 = bs[lane], a1 = bs[lane + 32];
        #pragma unroll 4
        for (int k = 0; k < H; k++) {
            float v = xb[wid][k];
            a0 += v * Ws[k * H + lane];
            a1 += v * Ws[k * H + lane + 32];
        }
        float p = fmaxf(a0, 0.f) * w2s[lane] + fmaxf(a1, 0.f) * w2s[lane + 32];
        #pragma unroll
        for (int o = 16; o; o >>= 1) p += __shfl_xor_sync(0xffffffffu, p, o);
        if (lane == 0)
            out[(size_t)NN * H + n] = 1.f / (1.f + expf(-(p + b2v)));
        __syncwarp();
    }
}

// ============================================================
// Launcher
// ============================================================
extern "C" void kernel_launch(void* const* d_in, const int* in_sizes, int n_in,
                              void* d_out, int out_size) {
    const float* nf  = (const float*)d_in[0];
    const float* ef  = (const float*)d_in[1];
    const int*   ei  = (const int*)d_in[2];
    const float* enW = (const float*)d_in[3];
    const float* enb = (const float*)d_in[4];
    const float* eeW = (const float*)d_in[5];
    const float* eeb = (const float*)d_in[6];
    const float* mW1 = (const float*)d_in[7];
    const float* mb1 = (const float*)d_in[8];
    const float* mW2 = (const float*)d_in[9];
    const float* mb2 = (const float*)d_in[10];
    const float* uW1 = (const float*)d_in[11];
    const float* ub1 = (const float*)d_in[12];
    const float* uW2 = (const float*)d_in[13];
    const float* ub2 = (const float*)d_in[14];
    const float* cW1 = (const float*)d_in[15];
    const float* cb1 = (const float*)d_in[16];
    const float* cW2 = (const float*)d_in[17];
    const float* cb2 = (const float*)d_in[18];
    float* out = (float*)d_out;

    int dev = 0, smc = 148;
    cudaGetDevice(&dev);
    cudaDeviceGetAttribute(&smc, cudaDevAttrMultiProcessorCount, dev);

    const int MSG_SMEM = (12416 + 4224 + 12288 + 4096) * 4;  // 132096
    const int UPD_SMEM = (8320 + 4224 + 8192 + 4096) * 4;    // 99328
    const int ENN_SMEM = (8320 + 8192) * 4;                  // 66048
    const int ENE_SMEM = (4224 + 4096) * 4;                  // 33280
    cudaFuncSetAttribute(k_msg,      cudaFuncAttributeMaxDynamicSharedMemorySize, MSG_SMEM);
    cudaFuncSetAttribute(k_upd,      cudaFuncAttributeMaxDynamicSharedMemorySize, UPD_SMEM);
    cudaFuncSetAttribute(k_enc_node, cudaFuncAttributeMaxDynamicSharedMemorySize, ENN_SMEM);
    cudaFuncSetAttribute(k_enc_edge, cudaFuncAttributeMaxDynamicSharedMemorySize, ENE_SMEM);

    k_enc_node<<<smc * 2, 256, ENN_SMEM>>>(nf, enW, enb);
    k_enc_edge<<<smc * 4, 256, ENE_SMEM>>>(ef, eeW, eeb);

    int cur = 0;
    for (int l = 0; l < 3; l++) {
        k_zero<<<(NN * H + 255) / 256, 256>>>();
        k_msg<<<smc, 256, MSG_SMEM>>>(ei,
                                      mW1 + (size_t)l * 192 * H, mb1 + l * H,
                                      mW2 + (size_t)l * H * H,   mb2 + l * H,
                                      cur);
        k_upd<<<smc * 2, 256, UPD_SMEM>>>(uW1 + (size_t)l * 128 * H, ub1 + l * H,
                                          uW2 + (size_t)l * H * H,   ub2 + l * H,
                                          cur, 1 - cur);
        cur = 1 - cur;
    }
    k_con<<<1184, 256>>>(cW1, cb1, cW2, cb2, cur, out);
}

// round 5
// speedup vs baseline: 1.4649x; 1.4649x over previous
#include <cuda_runtime.h>
#include <cuda_bf16.h>
#include <math.h>
#include <cstdint>

#define NN 50000
#define NE 800000
#define H  64
#define ND 128

__device__ float g_xb[2][NN * H];
__device__ float g_agg[NN * H];
__device__ unsigned g_eh[(size_t)NE * 32];
__device__ unsigned g_el[(size_t)NE * 32];
__device__ unsigned g_xh[NN * 32];
__device__ unsigned g_xl[NN * 32];

typedef unsigned long long ull;

__device__ __forceinline__ uint32_t smem_u32(const void* p) {
    uint32_t a;
    asm("{ .reg .u64 t; cvta.to.shared.u64 t, %1; cvt.u32.u64 %0, t; }" : "=r"(a) : "l"(p));
    return a;
}

#define LDSM4(r, addr) \
    asm volatile("ldmatrix.sync.aligned.m8n8.x4.shared.b16 {%0,%1,%2,%3}, [%4];" \
        : "=r"((r)[0]), "=r"((r)[1]), "=r"((r)[2]), "=r"((r)[3]) : "r"(addr))

#define MMA16816(c, a, b0v, b1v) \
    asm volatile("mma.sync.aligned.m16n8k16.row.col.f32.bf16.bf16.f32 " \
        "{%0,%1,%2,%3},{%4,%5,%6,%7},{%8,%9},{%0,%1,%2,%3};" \
        : "+f"((c)[0]), "+f"((c)[1]), "+f"((c)[2]), "+f"((c)[3]) \
        : "r"((a)[0]), "r"((a)[1]), "r"((a)[2]), "r"((a)[3]), "r"(b0v), "r"(b1v))

__device__ __forceinline__ void bf16_split(float v, __nv_bfloat16& h, __nv_bfloat16& l) {
    h = __float2bfloat16(v);
    l = __float2bfloat16(v - __bfloat162float(h));
}
__device__ __forceinline__ unsigned pack_bf2(__nv_bfloat16 a, __nv_bfloat16 b) {
    __nv_bfloat162 t; t.x = a; t.y = b;
    return *reinterpret_cast<unsigned*>(&t);
}
__device__ __forceinline__ unsigned pack_hi2(float a, float b) {
    return pack_bf2(__float2bfloat16(a), __float2bfloat16(b));
}

// ---- smem byte offsets for k_msg_mma ----
// B1 (W1^T as [n][k], stride 200 bf16 = 400B), split hi/lo
#define SM_B1H 0
#define SM_B1L 25600
#define SM_B2H 51200
#define SM_B2L 60416
#define SM_BIAS 69632
#define SM_A 70144
#define MSG_SMEM 172544
// per warp: Ah[16][200] at wid*12800, Al at +6400 (stride 400B, odd 16B units -> conflict-free ldmatrix)

// ============================================================
// Edge message MLP + scatter via mma.sync bf16 (split-bf16 x3)
//   Each warp processes 16 edges fully independently.
// ============================================================
__global__ void __launch_bounds__(256) k_msg_mma(const int* __restrict__ ei,
        const float* __restrict__ W1, const float* __restrict__ b1,
        const float* __restrict__ W2, const float* __restrict__ b2) {
    extern __shared__ char sm[];
    const uint32_t smb = smem_u32(sm);
    int tid = threadIdx.x, lane = tid & 31, wid = tid >> 5;

    // stage weights: B[n][k] = W[k][n], split bf16 hi/lo
    for (int i = tid; i < 192 * 64; i += 256) {
        int k = i >> 6, n = i & 63;
        __nv_bfloat16 h, l; bf16_split(W1[i], h, l);
        ((__nv_bfloat16*)(sm + SM_B1H))[n * 200 + k] = h;
        ((__nv_bfloat16*)(sm + SM_B1L))[n * 200 + k] = l;
    }
    for (int i = tid; i < 64 * 64; i += 256) {
        int k = i >> 6, n = i & 63;
        __nv_bfloat16 h, l; bf16_split(W2[i], h, l);
        ((__nv_bfloat16*)(sm + SM_B2H))[n * 72 + k] = h;
        ((__nv_bfloat16*)(sm + SM_B2L))[n * 72 + k] = l;
    }
    if (tid < 64) {
        ((float*)(sm + SM_BIAS))[tid] = b1[tid];
        ((float*)(sm + SM_BIAS + 256))[tid] = b2[tid];
    }
    __syncthreads();

    const float* b1s = (const float*)(sm + SM_BIAS);
    const float* b2s = (const float*)(sm + SM_BIAS + 256);

    const int tig = lane & 3, gid = lane >> 2;
    // ldmatrix addressing
    const uint32_t aBase = smb + SM_A + wid * 12800;
    const uint32_t aRowH = aBase + (lane & 15) * 400 + (lane & 16);        // col +8 bf16 = +16B for lanes>=16
    const uint32_t aRowL = aRowH + 6400;
    const uint32_t bRow  = ((lane & 7) + ((lane & 16) >> 1));              // row-in-group + 8 for lanes 16-31
    const uint32_t b1AddrH = smb + SM_B1H + bRow * 400 + (lane & 8) * 2;   // col +8 bf16 for lanes 8-15/24-31
    const uint32_t b1AddrL = b1AddrH + (SM_B1L - SM_B1H);
    const uint32_t b2AddrH = smb + SM_B2H + bRow * 144 + (lane & 8) * 2;
    const uint32_t b2AddrL = b2AddrH + (SM_B2L - SM_B2H);

    char* aRowPtr = sm + SM_A + wid * 12800;

    int gw = blockIdx.x * 8 + wid;
    int nw = gridDim.x * 8;
    const int nchunks = NN;  // 800000/16
    for (int chunk = gw; chunk < nchunks; chunk += nw) {
        int base16 = chunk * 16;
        int s = 0, d = 0;
        if (lane < 16) { s = ei[base16 + lane]; d = ei[NE + base16 + lane]; }

        // ---- stage 16 edges into this warp's A region ----
        #pragma unroll 4
        for (int t = 0; t < 16; t++) {
            int st = __shfl_sync(0xffffffffu, s, t);
            int dt = __shfl_sync(0xffffffffu, d, t);
            unsigned vxh = g_xh[st * 32 + lane];
            unsigned vxl = g_xl[st * 32 + lane];
            unsigned veh = g_eh[(size_t)(base16 + t) * 32 + lane];
            unsigned vel = g_el[(size_t)(base16 + t) * 32 + lane];
            unsigned vdh = g_xh[dt * 32 + lane];
            unsigned vdl = g_xl[dt * 32 + lane];
            char* rp = aRowPtr + t * 400;
            ((unsigned*)rp)[lane]                = vxh;   // k 0-63
            ((unsigned*)(rp + 128))[lane]        = veh;   // k 64-127
            ((unsigned*)(rp + 256))[lane]        = vdh;   // k 128-191
            ((unsigned*)(rp + 6400))[lane]       = vxl;
            ((unsigned*)(rp + 6528))[lane]       = vel;
            ((unsigned*)(rp + 6656))[lane]       = vdl;
        }
        __syncwarp();

        // ---- layer 1: acc[nt] (nt = 0..7, each 16x8) over K=192 ----
        float acc[8][4];
        #pragma unroll
        for (int n = 0; n < 8; n++)
            #pragma unroll
            for (int j = 0; j < 4; j++) acc[n][j] = 0.f;

        #pragma unroll 2
        for (int kt = 0; kt < 12; kt++) {
            uint32_t ah[4], al[4];
            LDSM4(ah, aRowH + kt * 32);
            LDSM4(al, aRowL + kt * 32);
            #pragma unroll
            for (int ng = 0; ng < 4; ng++) {
                uint32_t bh[4], bl[4];
                LDSM4(bh, b1AddrH + ng * 16 * 400 + kt * 32);
                LDSM4(bl, b1AddrL + ng * 16 * 400 + kt * 32);
                MMA16816(acc[2 * ng],     ah, bh[0], bh[1]);
                MMA16816(acc[2 * ng],     ah, bl[0], bl[1]);
                MMA16816(acc[2 * ng],     al, bh[0], bh[1]);
                MMA16816(acc[2 * ng + 1], ah, bh[2], bh[3]);
                MMA16816(acc[2 * ng + 1], ah, bl[2], bl[3]);
                MMA16816(acc[2 * ng + 1], al, bh[2], bh[3]);
            }
        }

        // ---- hidden: bias + relu + split -> layer2 A fragments (registers) ----
        uint32_t a2h[4][4], a2l[4][4];
        #pragma unroll
        for (int kt = 0; kt < 4; kt++) {
            #pragma unroll
            for (int j = 0; j < 2; j++) {
                int nt = kt * 2 + j;
                float2 bb = *(const float2*)(b1s + nt * 8 + 2 * tig);
                float v0 = fmaxf(acc[nt][0] + bb.x, 0.f);
                float v1 = fmaxf(acc[nt][1] + bb.y, 0.f);
                float v2 = fmaxf(acc[nt][2] + bb.x, 0.f);
                float v3 = fmaxf(acc[nt][3] + bb.y, 0.f);
                __nv_bfloat16 h0, l0, h1, l1, h2, l2, h3, l3;
                bf16_split(v0, h0, l0); bf16_split(v1, h1, l1);
                bf16_split(v2, h2, l2); bf16_split(v3, h3, l3);
                a2h[kt][2 * j]     = pack_bf2(h0, h1);
                a2h[kt][2 * j + 1] = pack_bf2(h2, h3);
                a2l[kt][2 * j]     = pack_bf2(l0, l1);
                a2l[kt][2 * j + 1] = pack_bf2(l2, l3);
            }
        }

        // ---- layer 2: K=64 ----
        float acc2[8][4];
        #pragma unroll
        for (int n = 0; n < 8; n++)
            #pragma unroll
            for (int j = 0; j < 4; j++) acc2[n][j] = 0.f;

        #pragma unroll
        for (int kt = 0; kt < 4; kt++) {
            #pragma unroll
            for (int ng = 0; ng < 4; ng++) {
                uint32_t bh[4], bl[4];
                LDSM4(bh, b2AddrH + ng * 16 * 144 + kt * 32);
                LDSM4(bl, b2AddrL + ng * 16 * 144 + kt * 32);
                MMA16816(acc2[2 * ng],     a2h[kt], bh[0], bh[1]);
                MMA16816(acc2[2 * ng],     a2h[kt], bl[0], bl[1]);
                MMA16816(acc2[2 * ng],     a2l[kt], bh[0], bh[1]);
                MMA16816(acc2[2 * ng + 1], a2h[kt], bh[2], bh[3]);
                MMA16816(acc2[2 * ng + 1], a2h[kt], bl[2], bl[3]);
                MMA16816(acc2[2 * ng + 1], a2l[kt], bh[2], bh[3]);
            }
        }

        // ---- epilogue: +b2, scatter-add rows gid & gid+8 ----
        int dlo = __shfl_sync(0xffffffffu, d, gid);
        int dhi = __shfl_sync(0xffffffffu, d, gid + 8);
        float* plo = g_agg + (size_t)dlo * H + 2 * tig;
        float* phi = g_agg + (size_t)dhi * H + 2 * tig;
        #pragma unroll
        for (int nt = 0; nt < 8; nt++) {
            float2 bb = *(const float2*)(b2s + nt * 8 + 2 * tig);
            float f0 = acc2[nt][0] + bb.x, f1 = acc2[nt][1] + bb.y;
            float f2 = acc2[nt][2] + bb.x, f3 = acc2[nt][3] + bb.y;
            asm volatile("red.global.add.v2.f32 [%0], {%1,%2};"
                :: "l"(plo + nt * 8), "f"(f0), "f"(f1) : "memory");
            asm volatile("red.global.add.v2.f32 [%0], {%1,%2};"
                :: "l"(phi + nt * 8), "f"(f2), "f"(f3) : "memory");
        }
        __syncwarp();
    }
}

// ============================================================
// split x (fp32) -> bf16 hi/lo word arrays
// ============================================================
__global__ void k_split(int si) {
    int i = blockIdx.x * blockDim.x + threadIdx.x;
    if (i < NN * 32) {
        float2 v = ((const float2*)g_xb[si])[i];
        __nv_bfloat16 h0, l0, h1, l1;
        bf16_split(v.x, h0, l0); bf16_split(v.y, h1, l1);
        g_xh[i] = pack_bf2(h0, h1);
        g_xl[i] = pack_bf2(l0, l1);
    }
}

// ---- fp32 f32x2 helpers (scalar kernels) ----
__device__ __forceinline__ void ffma2(ull& d, ull a, ull b) {
    asm("fma.rn.f32x2 %0, %1, %2, %0;" : "+l"(d) : "l"(a), "l"(b));
}
__device__ __forceinline__ float fin(ull a, float b) {
    return __uint_as_float((unsigned)a) + __uint_as_float((unsigned)(a >> 32)) + b;
}

__global__ void __launch_bounds__(256) k_upd(
        const float* __restrict__ W1, const float* __restrict__ b1,
        const float* __restrict__ W2, const float* __restrict__ b2,
        int si, int di) {
    extern __shared__ float smf[];
    float* W1p  = smf;
    float* W2p  = W1p + 8320;
    float* winb = W2p + 4224;
    float* hbb  = winb + 8192;
    int tid = threadIdx.x;
    for (int i = tid; i < 128 * 64; i += 256) {
        int k = i >> 6, c = i & 63;
        W1p[(c >> 1) * 260 + (k >> 1) * 4 + ((c & 1) << 1) + (k & 1)] = W1[i];
    }
    for (int i = tid; i < 64 * 64; i += 256) {
        int k = i >> 6, c = i & 63;
        W2p[(c >> 1) * 132 + (k >> 1) * 4 + ((c & 1) << 1) + (k & 1)] = W2[i];
    }
    __syncthreads();
    int lane = tid & 31, wid = tid >> 5;
    float2 bb1 = ((const float2*)b1)[lane];
    float2 bb2 = ((const float2*)b2)[lane];
    float* win = winb + wid * 8 * ND;
    float* hb  = hbb  + wid * 8 * H;
    const float* xs = g_xb[si];
    float* xd = g_xb[di];
    const ulonglong2* w1l = (const ulonglong2*)(W1p + (size_t)lane * 260);
    const ulonglong2* w2l = (const ulonglong2*)(W2p + (size_t)lane * 132);
    int li = lane & 15, half = lane >> 4;
    int gw = blockIdx.x * 8 + wid;
    int nw = gridDim.x * 8;
    for (int base = gw * 8; base < NN; base += nw * 8) {
        #pragma unroll
        for (int t = 0; t < 8; t++) {
            int n = base + t;
            const float* row = half ? (g_agg + (size_t)n * H) : (xs + (size_t)n * H);
            float4 v = *(const float4*)(row + li * 4);
            *(float4*)(win + t * ND + half * 64 + li * 4) = v;
        }
        __syncwarp();
        ull a0[8], a1[8];
        #pragma unroll
        for (int t = 0; t < 8; t++) { a0[t] = 0ull; a1[t] = 0ull; }
        #pragma unroll 4
        for (int c = 0; c < 32; c++) {
            ulonglong2 wA = w1l[2 * c];
            ulonglong2 wB = w1l[2 * c + 1];
            #pragma unroll
            for (int t = 0; t < 8; t++) {
                ulonglong2 v = ((const ulonglong2*)(win + t * ND))[c];
                ffma2(a0[t], wA.x, v.x); ffma2(a1[t], wA.y, v.x);
                ffma2(a0[t], wB.x, v.y); ffma2(a1[t], wB.y, v.y);
            }
        }
        #pragma unroll
        for (int t = 0; t < 8; t++) {
            *(float2*)(hb + t * H + 2 * lane) =
                make_float2(fmaxf(fin(a0[t], bb1.x), 0.f), fmaxf(fin(a1[t], bb1.y), 0.f));
        }
        __syncwarp();
        ull c0[8], c1[8];
        #pragma unroll
        for (int t = 0; t < 8; t++) { c0[t] = 0ull; c1[t] = 0ull; }
        #pragma unroll
        for (int c = 0; c < 16; c++) {
            ulonglong2 wA = w2l[2 * c];
            ulonglong2 wB = w2l[2 * c + 1];
            #pragma unroll
            for (int t = 0; t < 8; t++) {
                ulonglong2 v = ((const ulonglong2*)(hb + t * H))[c];
                ffma2(c0[t], wA.x, v.x); ffma2(c1[t], wA.y, v.x);
                ffma2(c0[t], wB.x, v.y); ffma2(c1[t], wB.y, v.y);
            }
        }
        #pragma unroll
        for (int t = 0; t < 8; t++) {
            *(float2*)(xd + (size_t)(base + t) * H + 2 * lane) =
                make_float2(fin(c0[t], bb2.x), fin(c1[t], bb2.y));
        }
        __syncwarp();
    }
}

__global__ void __launch_bounds__(256) k_enc_node(const float* __restrict__ nf,
        const float* __restrict__ W, const float* __restrict__ b) {
    extern __shared__ float smf[];
    float* Wp   = smf;
    float* winb = Wp + 8320;
    int tid = threadIdx.x;
    for (int i = tid; i < 128 * 64; i += 256) {
        int k = i >> 6, c = i & 63;
        Wp[(c >> 1) * 260 + (k >> 1) * 4 + ((c & 1) << 1) + (k & 1)] = W[i];
    }
    __syncthreads();
    int lane = tid & 31, wid = tid >> 5;
    float2 bb = ((const float2*)b)[lane];
    float* win = winb + wid * 8 * ND;
    const ulonglong2* wl = (const ulonglong2*)(Wp + (size_t)lane * 260);
    int gw = blockIdx.x * 8 + wid;
    int nw = gridDim.x * 8;
    for (int base = gw * 8; base < NN; base += nw * 8) {
        #pragma unroll
        for (int t = 0; t < 8; t++) {
            float4 v = *(const float4*)(nf + (size_t)(base + t) * ND + lane * 4);
            *(float4*)(win + t * ND + lane * 4) = v;
        }
        __syncwarp();
        ull a0[8], a1[8];
        #pragma unroll
        for (int t = 0; t < 8; t++) { a0[t] = 0ull; a1[t] = 0ull; }
        #pragma unroll 4
        for (int c = 0; c < 32; c++) {
            ulonglong2 wA = wl[2 * c];
            ulonglong2 wB = wl[2 * c + 1];
            #pragma unroll
            for (int t = 0; t < 8; t++) {
                ulonglong2 v = ((const ulonglong2*)(win + t * ND))[c];
                ffma2(a0[t], wA.x, v.x); ffma2(a1[t], wA.y, v.x);
                ffma2(a0[t], wB.x, v.y); ffma2(a1[t], wB.y, v.y);
            }
        }
        #pragma unroll
        for (int t = 0; t < 8; t++) {
            *(float2*)(g_xb[0] + (size_t)(base + t) * H + 2 * lane) =
                make_float2(fin(a0[t], bb.x), fin(a1[t], bb.y));
        }
        __syncwarp();
    }
}

// edge encoder -> split bf16 hi/lo directly
__global__ void __launch_bounds__(256) k_enc_edge(const float* __restrict__ ef,
        const float* __restrict__ W, const float* __restrict__ b) {
    extern __shared__ float smf[];
    float* Wp   = smf;
    float* winb = Wp + 4224;
    int tid = threadIdx.x;
    for (int i = tid; i < 64 * 64; i += 256) {
        int k = i >> 6, c = i & 63;
        Wp[(c >> 1) * 132 + (k >> 1) * 4 + ((c & 1) << 1) + (k & 1)] = W[i];
    }
    __syncthreads();
    int lane = tid & 31, wid = tid >> 5;
    float2 bb = ((const float2*)b)[lane];
    float* win = winb + wid * 8 * H;
    const ulonglong2* wl = (const ulonglong2*)(Wp + (size_t)lane * 132);
    int li = lane & 15, half = lane >> 4;
    int gw = blockIdx.x * 8 + wid;
    int nw = gridDim.x * 8;
    for (int base = gw * 8; base < NE; base += nw * 8) {
        #pragma unroll
        for (int tp = 0; tp < 4; tp++) {
            int t = tp * 2 + half;
            float4 v = *(const float4*)(ef + (size_t)(base + t) * H + li * 4);
            *(float4*)(win + t * H + li * 4) = v;
        }
        __syncwarp();
        ull a0[8], a1[8];
        #pragma unroll
        for (int t = 0; t < 8; t++) { a0[t] = 0ull; a1[t] = 0ull; }
        #pragma unroll
        for (int c = 0; c < 16; c++) {
            ulonglong2 wA = wl[2 * c];
            ulonglong2 wB = wl[2 * c + 1];
            #pragma unroll
            for (int t = 0; t < 8; t++) {
                ulonglong2 v = ((const ulonglong2*)(win + t * H))[c];
                ffma2(a0[t], wA.x, v.x); ffma2(a1[t], wA.y, v.x);
                ffma2(a0[t], wB.x, v.y); ffma2(a1[t], wB.y, v.y);
            }
        }
        #pragma unroll
        for (int t = 0; t < 8; t++) {
            float o0 = fin(a0[t], bb.x);
            float o1 = fin(a1[t], bb.y);
            __nv_bfloat16 h0, l0, h1, l1;
            bf16_split(o0, h0, l0); bf16_split(o1, h1, l1);
            size_t w = (size_t)(base + t) * 32 + lane;
            g_eh[w] = pack_bf2(h0, h1);
            g_el[w] = pack_bf2(l0, l1);
        }
        __syncwarp();
    }
}

__global__ void k_zero() {
    int i = blockIdx.x * blockDim.x + threadIdx.x;
    if (i < NN * H) g_agg[i] = 0.f;
}

__global__ void k_con(const float* __restrict__ W1, const float* __restrict__ b1,
                      const float* __restrict__ w2, const float* __restrict__ b2,
                      int si, float* __restrict__ out) {
    __shared__ float Ws[H * H];
    __shared__ float bs[H];
    __shared__ float w2s[H];
    __shared__ float xb[8][H];
    __shared__ float b2v;
    int tid = threadIdx.x;
    for (int i = tid; i < H * H; i += blockDim.x) Ws[i] = W1[i];
    if (tid < H) { bs[tid] = b1[tid]; w2s[tid] = w2[tid]; }
    if (tid == 0) b2v = b2[0];
    __syncthreads();
    const float* xs = g_xb[si];
    int lane = tid & 31, wid = tid >> 5;
    int gw = blockIdx.x * 8 + wid;
    int nw = gridDim.x * 8;
    for (int n = gw; n < NN; n += nw) {
        float xv0 = xs[(size_t)n * H + lane];
        float xv1 = xs[(size_t)n * H + lane + 32];
        out[(size_t)n * H + lane]      = xv0;
        out[(size_t)n * H + lane + 32] = xv1;
        xb[wid][lane]      = xv0;
        xb[wid][lane + 32] = xv1;
        __syncwarp();
        float a0 = bs[lane], a1 = bs[lane + 32];
        #pragma unroll 4
        for (int k = 0; k < H; k++) {
            float v = xb[wid][k];
            a0 += v * Ws[k * H + lane];
            a1 += v * Ws[k * H + lane + 32];
        }
        float p = fmaxf(a0, 0.f) * w2s[lane] + fmaxf(a1, 0.f) * w2s[lane + 32];
        #pragma unroll
        for (int o = 16; o; o >>= 1) p += __shfl_xor_sync(0xffffffffu, p, o);
        if (lane == 0)
            out[(size_t)NN * H + n] = 1.f / (1.f + expf(-(p + b2v)));
        __syncwarp();
    }
}

extern "C" void kernel_launch(void* const* d_in, const int* in_sizes, int n_in,
                              void* d_out, int out_size) {
    const float* nf  = (const float*)d_in[0];
    const float* ef  = (const float*)d_in[1];
    const int*   ei  = (const int*)d_in[2];
    const float* enW = (const float*)d_in[3];
    const float* enb = (const float*)d_in[4];
    const float* eeW = (const float*)d_in[5];
    const float* eeb = (const float*)d_in[6];
    const float* mW1 = (const float*)d_in[7];
    const float* mb1 = (const float*)d_in[8];
    const float* mW2 = (const float*)d_in[9];
    const float* mb2 = (const float*)d_in[10];
    const float* uW1 = (const float*)d_in[11];
    const float* ub1 = (const float*)d_in[12];
    const float* uW2 = (const float*)d_in[13];
    const float* ub2 = (const float*)d_in[14];
    const float* cW1 = (const float*)d_in[15];
    const float* cb1 = (const float*)d_in[16];
    const float* cW2 = (const float*)d_in[17];
    const float* cb2 = (const float*)d_in[18];
    float* out = (float*)d_out;

    int dev = 0, smc = 148;
    cudaGetDevice(&dev);
    cudaDeviceGetAttribute(&smc, cudaDevAttrMultiProcessorCount, dev);

    const int UPD_SMEM = (8320 + 4224 + 8192 + 4096) * 4;
    const int ENN_SMEM = (8320 + 8192) * 4;
    const int ENE_SMEM = (4224 + 4096) * 4;
    cudaFuncSetAttribute(k_msg_mma,  cudaFuncAttributeMaxDynamicSharedMemorySize, MSG_SMEM);
    cudaFuncSetAttribute(k_upd,      cudaFuncAttributeMaxDynamicSharedMemorySize, UPD_SMEM);
    cudaFuncSetAttribute(k_enc_node, cudaFuncAttributeMaxDynamicSharedMemorySize, ENN_SMEM);
    cudaFuncSetAttribute(k_enc_edge, cudaFuncAttributeMaxDynamicSharedMemorySize, ENE_SMEM);

    k_enc_node<<<smc * 2, 256, ENN_SMEM>>>(nf, enW, enb);
    k_enc_edge<<<smc * 4, 256, ENE_SMEM>>>(ef, eeW, eeb);

    int cur = 0;
    for (int l = 0; l < 3; l++) {
        k_zero<<<(NN * H + 255) / 256, 256>>>();
        k_split<<<(NN * 32 + 255) / 256, 256>>>(cur);
        k_msg_mma<<<smc, 256, MSG_SMEM>>>(ei,
                                          mW1 + (size_t)l * 192 * H, mb1 + l * H,
                                          mW2 + (size_t)l * H * H,   mb2 + l * H);
        k_upd<<<smc * 2, 256, UPD_SMEM>>>(uW1 + (size_t)l * 128 * H, ub1 + l * H,
                                          uW2 + (size_t)l * H * H,   ub2 + l * H,
                                          cur, 1 - cur);
        cur = 1 - cur;
    }
    k_con<<<1184, 256>>>(cW1, cb1, cW2, cb2, cur, out);
}

// round 6
// speedup vs baseline: 1.8972x; 1.2951x over previous
#include <cuda_runtime.h>
#include <cuda_bf16.h>
#include <math.h>
#include <cstdint>

#define NN 50000
#define NE 800000
#define H  64
#define ND 128

__device__ float g_xb[2][NN * H];
__device__ float g_agg[NN * H];
__device__ unsigned g_eh[(size_t)NE * 32];
__device__ unsigned g_el[(size_t)NE * 32];
__device__ unsigned g_xh[NN * 32];
__device__ unsigned g_xl[NN * 32];

typedef unsigned long long ull;

__device__ __forceinline__ uint32_t smem_u32(const void* p) {
    uint32_t a;
    asm("{ .reg .u64 t; cvta.to.shared.u64 t, %1; cvt.u32.u64 %0, t; }" : "=r"(a) : "l"(p));
    return a;
}

#define LDSM4(r, addr) \
    asm volatile("ldmatrix.sync.aligned.m8n8.x4.shared.b16 {%0,%1,%2,%3}, [%4];" \
        : "=r"((r)[0]), "=r"((r)[1]), "=r"((r)[2]), "=r"((r)[3]) : "r"(addr))

#define MMA16816(c, a, b0v, b1v) \
    asm volatile("mma.sync.aligned.m16n8k16.row.col.f32.bf16.bf16.f32 " \
        "{%0,%1,%2,%3},{%4,%5,%6,%7},{%8,%9},{%0,%1,%2,%3};" \
        : "+f"((c)[0]), "+f"((c)[1]), "+f"((c)[2]), "+f"((c)[3]) \
        : "r"((a)[0]), "r"((a)[1]), "r"((a)[2]), "r"((a)[3]), "r"(b0v), "r"(b1v))

__device__ __forceinline__ void bf16_split(float v, __nv_bfloat16& h, __nv_bfloat16& l) {
    h = __float2bfloat16(v);
    l = __float2bfloat16(v - __bfloat162float(h));
}
__device__ __forceinline__ unsigned pack_bf2(__nv_bfloat16 a, __nv_bfloat16 b) {
    __nv_bfloat162 t; t.x = a; t.y = b;
    return *reinterpret_cast<unsigned*>(&t);
}

// ============================================================
// k_msg_mma: edge MLP + scatter, 12 warps/CTA, 16 edges/warp
// ============================================================
#define SM_B1H 0
#define SM_B1L 25600
#define SM_B2H 51200
#define SM_B2L 60416
#define SM_BIAS 69632
#define SM_A 70144
#define MSG_WARPS 12
#define MSG_SMEM (70144 + MSG_WARPS * 12800)   // 223744

__global__ void __launch_bounds__(32 * MSG_WARPS) k_msg_mma(const int* __restrict__ ei,
        const float* __restrict__ W1, const float* __restrict__ b1,
        const float* __restrict__ W2, const float* __restrict__ b2) {
    extern __shared__ char sm[];
    const uint32_t smb = smem_u32(sm);
    int tid = threadIdx.x, lane = tid & 31, wid = tid >> 5;

    for (int i = tid; i < 192 * 64; i += blockDim.x) {
        int k = i >> 6, n = i & 63;
        __nv_bfloat16 h, l; bf16_split(W1[i], h, l);
        ((__nv_bfloat16*)(sm + SM_B1H))[n * 200 + k] = h;
        ((__nv_bfloat16*)(sm + SM_B1L))[n * 200 + k] = l;
    }
    for (int i = tid; i < 64 * 64; i += blockDim.x) {
        int k = i >> 6, n = i & 63;
        __nv_bfloat16 h, l; bf16_split(W2[i], h, l);
        ((__nv_bfloat16*)(sm + SM_B2H))[n * 72 + k] = h;
        ((__nv_bfloat16*)(sm + SM_B2L))[n * 72 + k] = l;
    }
    if (tid < 64) {
        ((float*)(sm + SM_BIAS))[tid] = b1[tid];
        ((float*)(sm + SM_BIAS + 256))[tid] = b2[tid];
    }
    __syncthreads();

    const float* b1s = (const float*)(sm + SM_BIAS);
    const float* b2s = (const float*)(sm + SM_BIAS + 256);

    const int tig = lane & 3, gid = lane >> 2;
    const uint32_t aBase = smb + SM_A + wid * 12800;
    const uint32_t aRowH = aBase + (lane & 15) * 400 + (lane & 16);
    const uint32_t aRowL = aRowH + 6400;
    const uint32_t bRow  = ((lane & 7) + ((lane & 16) >> 1));
    const uint32_t b1AddrH = smb + SM_B1H + bRow * 400 + (lane & 8) * 2;
    const uint32_t b1AddrL = b1AddrH + (SM_B1L - SM_B1H);
    const uint32_t b2AddrH = smb + SM_B2H + bRow * 144 + (lane & 8) * 2;
    const uint32_t b2AddrL = b2AddrH + (SM_B2L - SM_B2H);
    char* aRowPtr = sm + SM_A + wid * 12800;

    int gw = blockIdx.x * MSG_WARPS + wid;
    int nw = gridDim.x * MSG_WARPS;
    for (int chunk = gw; chunk < NE / 16; chunk += nw) {
        int base16 = chunk * 16;
        int s = 0, d = 0;
        if (lane < 16) { s = ei[base16 + lane]; d = ei[NE + base16 + lane]; }

        #pragma unroll 4
        for (int t = 0; t < 16; t++) {
            int st = __shfl_sync(0xffffffffu, s, t);
            int dt = __shfl_sync(0xffffffffu, d, t);
            unsigned vxh = g_xh[st * 32 + lane];
            unsigned vxl = g_xl[st * 32 + lane];
            unsigned veh = g_eh[(size_t)(base16 + t) * 32 + lane];
            unsigned vel = g_el[(size_t)(base16 + t) * 32 + lane];
            unsigned vdh = g_xh[dt * 32 + lane];
            unsigned vdl = g_xl[dt * 32 + lane];
            char* rp = aRowPtr + t * 400;
            ((unsigned*)rp)[lane]          = vxh;
            ((unsigned*)(rp + 128))[lane]  = veh;
            ((unsigned*)(rp + 256))[lane]  = vdh;
            ((unsigned*)(rp + 6400))[lane] = vxl;
            ((unsigned*)(rp + 6528))[lane] = vel;
            ((unsigned*)(rp + 6656))[lane] = vdl;
        }
        __syncwarp();

        float acc[8][4];
        #pragma unroll
        for (int n = 0; n < 8; n++)
            #pragma unroll
            for (int j = 0; j < 4; j++) acc[n][j] = 0.f;

        #pragma unroll 2
        for (int kt = 0; kt < 12; kt++) {
            uint32_t ah[4], al[4];
            LDSM4(ah, aRowH + kt * 32);
            LDSM4(al, aRowL + kt * 32);
            #pragma unroll
            for (int ng = 0; ng < 4; ng++) {
                uint32_t bh[4], bl[4];
                LDSM4(bh, b1AddrH + ng * 16 * 400 + kt * 32);
                LDSM4(bl, b1AddrL + ng * 16 * 400 + kt * 32);
                MMA16816(acc[2 * ng],     ah, bh[0], bh[1]);
                MMA16816(acc[2 * ng],     ah, bl[0], bl[1]);
                MMA16816(acc[2 * ng],     al, bh[0], bh[1]);
                MMA16816(acc[2 * ng + 1], ah, bh[2], bh[3]);
                MMA16816(acc[2 * ng + 1], ah, bl[2], bl[3]);
                MMA16816(acc[2 * ng + 1], al, bh[2], bh[3]);
            }
        }

        uint32_t a2h[4][4], a2l[4][4];
        #pragma unroll
        for (int kt = 0; kt < 4; kt++) {
            #pragma unroll
            for (int j = 0; j < 2; j++) {
                int nt = kt * 2 + j;
                float2 bb = *(const float2*)(b1s + nt * 8 + 2 * tig);
                float v0 = fmaxf(acc[nt][0] + bb.x, 0.f);
                float v1 = fmaxf(acc[nt][1] + bb.y, 0.f);
                float v2 = fmaxf(acc[nt][2] + bb.x, 0.f);
                float v3 = fmaxf(acc[nt][3] + bb.y, 0.f);
                __nv_bfloat16 h0, l0, h1, l1, h2, l2, h3, l3;
                bf16_split(v0, h0, l0); bf16_split(v1, h1, l1);
                bf16_split(v2, h2, l2); bf16_split(v3, h3, l3);
                a2h[kt][2 * j]     = pack_bf2(h0, h1);
                a2h[kt][2 * j + 1] = pack_bf2(h2, h3);
                a2l[kt][2 * j]     = pack_bf2(l0, l1);
                a2l[kt][2 * j + 1] = pack_bf2(l2, l3);
            }
        }

        float acc2[8][4];
        #pragma unroll
        for (int n = 0; n < 8; n++)
            #pragma unroll
            for (int j = 0; j < 4; j++) acc2[n][j] = 0.f;

        #pragma unroll
        for (int kt = 0; kt < 4; kt++) {
            #pragma unroll
            for (int ng = 0; ng < 4; ng++) {
                uint32_t bh[4], bl[4];
                LDSM4(bh, b2AddrH + ng * 16 * 144 + kt * 32);
                LDSM4(bl, b2AddrL + ng * 16 * 144 + kt * 32);
                MMA16816(acc2[2 * ng],     a2h[kt], bh[0], bh[1]);
                MMA16816(acc2[2 * ng],     a2h[kt], bl[0], bl[1]);
                MMA16816(acc2[2 * ng],     a2l[kt], bh[0], bh[1]);
                MMA16816(acc2[2 * ng + 1], a2h[kt], bh[2], bh[3]);
                MMA16816(acc2[2 * ng + 1], a2h[kt], bl[2], bl[3]);
                MMA16816(acc2[2 * ng + 1], a2l[kt], bh[2], bh[3]);
            }
        }

        int dlo = __shfl_sync(0xffffffffu, d, gid);
        int dhi = __shfl_sync(0xffffffffu, d, gid + 8);
        float* plo = g_agg + (size_t)dlo * H + 2 * tig;
        float* phi = g_agg + (size_t)dhi * H + 2 * tig;
        #pragma unroll
        for (int nt = 0; nt < 8; nt++) {
            float2 bb = *(const float2*)(b2s + nt * 8 + 2 * tig);
            float f0 = acc2[nt][0] + bb.x, f1 = acc2[nt][1] + bb.y;
            float f2 = acc2[nt][2] + bb.x, f3 = acc2[nt][3] + bb.y;
            asm volatile("red.global.add.v2.f32 [%0], {%1,%2};"
                :: "l"(plo + nt * 8), "f"(f0), "f"(f1) : "memory");
            asm volatile("red.global.add.v2.f32 [%0], {%1,%2};"
                :: "l"(phi + nt * 8), "f"(f2), "f"(f3) : "memory");
        }
        __syncwarp();
    }
}

// ============================================================
// k_upd_mma: node update MLP via HMMA, 16 nodes/warp
//   in = [x(split) | agg(split at stage)] K=128 -> relu -> K=64
//   writes fp32 x' AND its bf16 hi/lo split
// ============================================================
#define UB1H 0
#define UB1L 17408
#define UB2H 34816
#define UB2L 44032
#define UBIAS 53248
#define UA 53760
#define UPD_SMEM (53760 + 8 * 8704)    // 123392

__global__ void __launch_bounds__(256) k_upd_mma(
        const float* __restrict__ W1, const float* __restrict__ b1,
        const float* __restrict__ W2, const float* __restrict__ b2,
        int si, int di) {
    extern __shared__ char sm[];
    const uint32_t smb = smem_u32(sm);
    int tid = threadIdx.x, lane = tid & 31, wid = tid >> 5;

    for (int i = tid; i < 128 * 64; i += blockDim.x) {
        int k = i >> 6, n = i & 63;
        __nv_bfloat16 h, l; bf16_split(W1[i], h, l);
        ((__nv_bfloat16*)(sm + UB1H))[n * 136 + k] = h;
        ((__nv_bfloat16*)(sm + UB1L))[n * 136 + k] = l;
    }
    for (int i = tid; i < 64 * 64; i += blockDim.x) {
        int k = i >> 6, n = i & 63;
        __nv_bfloat16 h, l; bf16_split(W2[i], h, l);
        ((__nv_bfloat16*)(sm + UB2H))[n * 72 + k] = h;
        ((__nv_bfloat16*)(sm + UB2L))[n * 72 + k] = l;
    }
    if (tid < 64) {
        ((float*)(sm + UBIAS))[tid] = b1[tid];
        ((float*)(sm + UBIAS + 256))[tid] = b2[tid];
    }
    __syncthreads();

    const float* b1s = (const float*)(sm + UBIAS);
    const float* b2s = (const float*)(sm + UBIAS + 256);
    float* xd = g_xb[di];

    const int tig = lane & 3, gid = lane >> 2;
    const uint32_t aBase = smb + UA + wid * 8704;
    const uint32_t aRowH = aBase + (lane & 15) * 272 + (lane & 16);
    const uint32_t aRowL = aRowH + 4352;
    const uint32_t bRow  = ((lane & 7) + ((lane & 16) >> 1));
    const uint32_t b1AddrH = smb + UB1H + bRow * 272 + (lane & 8) * 2;
    const uint32_t b1AddrL = b1AddrH + (UB1L - UB1H);
    const uint32_t b2AddrH = smb + UB2H + bRow * 144 + (lane & 8) * 2;
    const uint32_t b2AddrL = b2AddrH + (UB2L - UB2H);
    char* aRowPtr = sm + UA + wid * 8704;

    int gw = blockIdx.x * 8 + wid;
    int nw = gridDim.x * 8;
    for (int chunk = gw; chunk < NN / 16; chunk += nw) {
        int base16 = chunk * 16;
        #pragma unroll 4
        for (int t = 0; t < 16; t++) {
            int n = base16 + t;
            unsigned vxh = g_xh[n * 32 + lane];
            unsigned vxl = g_xl[n * 32 + lane];
            float2 ag = ((const float2*)(g_agg + (size_t)n * H))[lane];
            __nv_bfloat16 h0, l0, h1, l1;
            bf16_split(ag.x, h0, l0); bf16_split(ag.y, h1, l1);
            char* rp = aRowPtr + t * 272;
            ((unsigned*)rp)[lane]          = vxh;
            ((unsigned*)(rp + 128))[lane]  = pack_bf2(h0, h1);
            ((unsigned*)(rp + 4352))[lane] = vxl;
            ((unsigned*)(rp + 4480))[lane] = pack_bf2(l0, l1);
        }
        __syncwarp();

        float acc[8][4];
        #pragma unroll
        for (int n = 0; n < 8; n++)
            #pragma unroll
            for (int j = 0; j < 4; j++) acc[n][j] = 0.f;

        #pragma unroll 2
        for (int kt = 0; kt < 8; kt++) {
            uint32_t ah[4], al[4];
            LDSM4(ah, aRowH + kt * 32);
            LDSM4(al, aRowL + kt * 32);
            #pragma unroll
            for (int ng = 0; ng < 4; ng++) {
                uint32_t bh[4], bl[4];
                LDSM4(bh, b1AddrH + ng * 16 * 272 + kt * 32);
                LDSM4(bl, b1AddrL + ng * 16 * 272 + kt * 32);
                MMA16816(acc[2 * ng],     ah, bh[0], bh[1]);
                MMA16816(acc[2 * ng],     ah, bl[0], bl[1]);
                MMA16816(acc[2 * ng],     al, bh[0], bh[1]);
                MMA16816(acc[2 * ng + 1], ah, bh[2], bh[3]);
                MMA16816(acc[2 * ng + 1], ah, bl[2], bl[3]);
                MMA16816(acc[2 * ng + 1], al, bh[2], bh[3]);
            }
        }

        uint32_t a2h[4][4], a2l[4][4];
        #pragma unroll
        for (int kt = 0; kt < 4; kt++) {
            #pragma unroll
            for (int j = 0; j < 2; j++) {
                int nt = kt * 2 + j;
                float2 bb = *(const float2*)(b1s + nt * 8 + 2 * tig);
                float v0 = fmaxf(acc[nt][0] + bb.x, 0.f);
                float v1 = fmaxf(acc[nt][1] + bb.y, 0.f);
                float v2 = fmaxf(acc[nt][2] + bb.x, 0.f);
                float v3 = fmaxf(acc[nt][3] + bb.y, 0.f);
                __nv_bfloat16 h0, l0, h1, l1, h2, l2, h3, l3;
                bf16_split(v0, h0, l0); bf16_split(v1, h1, l1);
                bf16_split(v2, h2, l2); bf16_split(v3, h3, l3);
                a2h[kt][2 * j]     = pack_bf2(h0, h1);
                a2h[kt][2 * j + 1] = pack_bf2(h2, h3);
                a2l[kt][2 * j]     = pack_bf2(l0, l1);
                a2l[kt][2 * j + 1] = pack_bf2(l2, l3);
            }
        }

        float acc2[8][4];
        #pragma unroll
        for (int n = 0; n < 8; n++)
            #pragma unroll
            for (int j = 0; j < 4; j++) acc2[n][j] = 0.f;

        #pragma unroll
        for (int kt = 0; kt < 4; kt++) {
            #pragma unroll
            for (int ng = 0; ng < 4; ng++) {
                uint32_t bh[4], bl[4];
                LDSM4(bh, b2AddrH + ng * 16 * 144 + kt * 32);
                LDSM4(bl, b2AddrL + ng * 16 * 144 + kt * 32);
                MMA16816(acc2[2 * ng],     a2h[kt], bh[0], bh[1]);
                MMA16816(acc2[2 * ng],     a2h[kt], bl[0], bl[1]);
                MMA16816(acc2[2 * ng],     a2l[kt], bh[0], bh[1]);
                MMA16816(acc2[2 * ng + 1], a2h[kt], bh[2], bh[3]);
                MMA16816(acc2[2 * ng + 1], a2h[kt], bl[2], bl[3]);
                MMA16816(acc2[2 * ng + 1], a2l[kt], bh[2], bh[3]);
            }
        }

        int n0 = base16 + gid, n1 = base16 + gid + 8;
        #pragma unroll
        for (int nt = 0; nt < 8; nt++) {
            float2 bb = *(const float2*)(b2s + nt * 8 + 2 * tig);
            float f0 = acc2[nt][0] + bb.x, f1 = acc2[nt][1] + bb.y;
            float f2 = acc2[nt][2] + bb.x, f3 = acc2[nt][3] + bb.y;
            *(float2*)(xd + (size_t)n0 * H + nt * 8 + 2 * tig) = make_float2(f0, f1);
            *(float2*)(xd + (size_t)n1 * H + nt * 8 + 2 * tig) = make_float2(f2, f3);
            __nv_bfloat16 h0, l0, h1, l1, h2, l2, h3, l3;
            bf16_split(f0, h0, l0); bf16_split(f1, h1, l1);
            bf16_split(f2, h2, l2); bf16_split(f3, h3, l3);
            g_xh[n0 * 32 + nt * 4 + tig] = pack_bf2(h0, h1);
            g_xl[n0 * 32 + nt * 4 + tig] = pack_bf2(l0, l1);
            g_xh[n1 * 32 + nt * 4 + tig] = pack_bf2(h2, h3);
            g_xl[n1 * 32 + nt * 4 + tig] = pack_bf2(l2, l3);
        }
        __syncwarp();
    }
}

// ============================================================
// k_enc_edge_mma: e = ef @ W + b via HMMA, writes split e
// ============================================================
#define EBH 0
#define EBL 9216
#define EBIAS 18432
#define EA 18944
#define ENC_SMEM (18944 + 8 * 4608)   // 55808

__global__ void __launch_bounds__(256) k_enc_edge_mma(const float* __restrict__ ef,
        const float* __restrict__ W, const float* __restrict__ b) {
    extern __shared__ char sm[];
    const uint32_t smb = smem_u32(sm);
    int tid = threadIdx.x, lane = tid & 31, wid = tid >> 5;

    for (int i = tid; i < 64 * 64; i += blockDim.x) {
        int k = i >> 6, n = i & 63;
        __nv_bfloat16 h, l; bf16_split(W[i], h, l);
        ((__nv_bfloat16*)(sm + EBH))[n * 72 + k] = h;
        ((__nv_bfloat16*)(sm + EBL))[n * 72 + k] = l;
    }
    if (tid < 64) ((float*)(sm + EBIAS))[tid] = b[tid];
    __syncthreads();

    const float* bs = (const float*)(sm + EBIAS);
    const int tig = lane & 3, gid = lane >> 4 ? 0 : 0; // placeholder
    const int gi = lane >> 2;
    const uint32_t aBase = smb + EA + wid * 4608;
    const uint32_t aRowH = aBase + (lane & 15) * 144 + (lane & 16);
    const uint32_t aRowL = aRowH + 2304;
    const uint32_t bRow  = ((lane & 7) + ((lane & 16) >> 1));
    const uint32_t bAddrH = smb + EBH + bRow * 144 + (lane & 8) * 2;
    const uint32_t bAddrL = bAddrH + (EBL - EBH);
    char* aRowPtr = sm + EA + wid * 4608;

    int gw = blockIdx.x * 8 + wid;
    int nw = gridDim.x * 8;
    for (int chunk = gw; chunk < NE / 16; chunk += nw) {
        int base16 = chunk * 16;
        #pragma unroll 4
        for (int t = 0; t < 16; t++) {
            float2 v = ((const float2*)(ef + (size_t)(base16 + t) * H))[lane];
            __nv_bfloat16 h0, l0, h1, l1;
            bf16_split(v.x, h0, l0); bf16_split(v.y, h1, l1);
            char* rp = aRowPtr + t * 144;
            ((unsigned*)rp)[lane]          = pack_bf2(h0, h1);
            ((unsigned*)(rp + 2304))[lane] = pack_bf2(l0, l1);
        }
        __syncwarp();

        float acc[8][4];
        #pragma unroll
        for (int n = 0; n < 8; n++)
            #pragma unroll
            for (int j = 0; j < 4; j++) acc[n][j] = 0.f;

        #pragma unroll
        for (int kt = 0; kt < 4; kt++) {
            uint32_t ah[4], al[4];
            LDSM4(ah, aRowH + kt * 32);
            LDSM4(al, aRowL + kt * 32);
            #pragma unroll
            for (int ng = 0; ng < 4; ng++) {
                uint32_t bh[4], bl[4];
                LDSM4(bh, bAddrH + ng * 16 * 144 + kt * 32);
                LDSM4(bl, bAddrL + ng * 16 * 144 + kt * 32);
                MMA16816(acc[2 * ng],     ah, bh[0], bh[1]);
                MMA16816(acc[2 * ng],     ah, bl[0], bl[1]);
                MMA16816(acc[2 * ng],     al, bh[0], bh[1]);
                MMA16816(acc[2 * ng + 1], ah, bh[2], bh[3]);
                MMA16816(acc[2 * ng + 1], ah, bl[2], bl[3]);
                MMA16816(acc[2 * ng + 1], al, bh[2], bh[3]);
            }
        }

        size_t e0 = (size_t)(base16 + gi), e1 = (size_t)(base16 + gi + 8);
        #pragma unroll
        for (int nt = 0; nt < 8; nt++) {
            float2 bb = *(const float2*)(bs + nt * 8 + 2 * tig);
            float f0 = acc[nt][0] + bb.x, f1 = acc[nt][1] + bb.y;
            float f2 = acc[nt][2] + bb.x, f3 = acc[nt][3] + bb.y;
            __nv_bfloat16 h0, l0, h1, l1, h2, l2, h3, l3;
            bf16_split(f0, h0, l0); bf16_split(f1, h1, l1);
            bf16_split(f2, h2, l2); bf16_split(f3, h3, l3);
            g_eh[e0 * 32 + nt * 4 + tig] = pack_bf2(h0, h1);
            g_el[e0 * 32 + nt * 4 + tig] = pack_bf2(l0, l1);
            g_eh[e1 * 32 + nt * 4 + tig] = pack_bf2(h2, h3);
            g_el[e1 * 32 + nt * 4 + tig] = pack_bf2(l2, l3);
        }
        __syncwarp();
    }
}

// ============================================================
// k_enc_node: scalar f32x2 (small), writes fp32 x + split
// ============================================================
__device__ __forceinline__ void ffma2(ull& d, ull a, ull b) {
    asm("fma.rn.f32x2 %0, %1, %2, %0;" : "+l"(d) : "l"(a), "l"(b));
}
__device__ __forceinline__ float fin(ull a, float b) {
    return __uint_as_float((unsigned)a) + __uint_as_float((unsigned)(a >> 32)) + b;
}

__global__ void __launch_bounds__(256) k_enc_node(const float* __restrict__ nf,
        const float* __restrict__ W, const float* __restrict__ b) {
    extern __shared__ float smf[];
    float* Wp   = smf;
    float* winb = Wp + 8320;
    int tid = threadIdx.x;
    for (int i = tid; i < 128 * 64; i += 256) {
        int k = i >> 6, c = i & 63;
        Wp[(c >> 1) * 260 + (k >> 1) * 4 + ((c & 1) << 1) + (k & 1)] = W[i];
    }
    __syncthreads();
    int lane = tid & 31, wid = tid >> 5;
    float2 bb = ((const float2*)b)[lane];
    float* win = winb + wid * 8 * ND;
    const ulonglong2* wl = (const ulonglong2*)(Wp + (size_t)lane * 260);
    int gw = blockIdx.x * 8 + wid;
    int nw = gridDim.x * 8;
    for (int base = gw * 8; base < NN; base += nw * 8) {
        #pragma unroll
        for (int t = 0; t < 8; t++) {
            float4 v = *(const float4*)(nf + (size_t)(base + t) * ND + lane * 4);
            *(float4*)(win + t * ND + lane * 4) = v;
        }
        __syncwarp();
        ull a0[8], a1[8];
        #pragma unroll
        for (int t = 0; t < 8; t++) { a0[t] = 0ull; a1[t] = 0ull; }
        #pragma unroll 4
        for (int c = 0; c < 32; c++) {
            ulonglong2 wA = wl[2 * c];
            ulonglong2 wB = wl[2 * c + 1];
            #pragma unroll
            for (int t = 0; t < 8; t++) {
                ulonglong2 v = ((const ulonglong2*)(win + t * ND))[c];
                ffma2(a0[t], wA.x, v.x); ffma2(a1[t], wA.y, v.x);
                ffma2(a0[t], wB.x, v.y); ffma2(a1[t], wB.y, v.y);
            }
        }
        #pragma unroll
        for (int t = 0; t < 8; t++) {
            float o0 = fin(a0[t], bb.x);
            float o1 = fin(a1[t], bb.y);
            int n = base + t;
            *(float2*)(g_xb[0] + (size_t)n * H + 2 * lane) = make_float2(o0, o1);
            __nv_bfloat16 h0, l0, h1, l1;
            bf16_split(o0, h0, l0); bf16_split(o1, h1, l1);
            g_xh[n * 32 + lane] = pack_bf2(h0, h1);
            g_xl[n * 32 + lane] = pack_bf2(l0, l1);
        }
        __syncwarp();
    }
}

__global__ void k_zero() {
    int i = blockIdx.x * blockDim.x + threadIdx.x;
    if (i < NN * H) g_agg[i] = 0.f;
}

__global__ void k_con(const float* __restrict__ W1, const float* __restrict__ b1,
                      const float* __restrict__ w2, const float* __restrict__ b2,
                      int si, float* __restrict__ out) {
    __shared__ float Ws[H * H];
    __shared__ float bs[H];
    __shared__ float w2s[H];
    __shared__ float xb[8][H];
    __shared__ float b2v;
    int tid = threadIdx.x;
    for (int i = tid; i < H * H; i += blockDim.x) Ws[i] = W1[i];
    if (tid < H) { bs[tid] = b1[tid]; w2s[tid] = w2[tid]; }
    if (tid == 0) b2v = b2[0];
    __syncthreads();
    const float* xs = g_xb[si];
    int lane = tid & 31, wid = tid >> 5;
    int gw = blockIdx.x * 8 + wid;
    int nw = gridDim.x * 8;
    for (int n = gw; n < NN; n += nw) {
        float xv0 = xs[(size_t)n * H + lane];
        float xv1 = xs[(size_t)n * H + lane + 32];
        out[(size_t)n * H + lane]      = xv0;
        out[(size_t)n * H + lane + 32] = xv1;
        xb[wid][lane]      = xv0;
        xb[wid][lane + 32] = xv1;
        __syncwarp();
        float a0 = bs[lane], a1 = bs[lane + 32];
        #pragma unroll 4
        for (int k = 0; k < H; k++) {
            float v = xb[wid][k];
            a0 += v * Ws[k * H + lane];
            a1 += v * Ws[k * H + lane + 32];
        }
        float p = fmaxf(a0, 0.f) * w2s[lane] + fmaxf(a1, 0.f) * w2s[lane + 32];
        #pragma unroll
        for (int o = 16; o; o >>= 1) p += __shfl_xor_sync(0xffffffffu, p, o);
        if (lane == 0)
            out[(size_t)NN * H + n] = 1.f / (1.f + expf(-(p + b2v)));
        __syncwarp();
    }
}

extern "C" void kernel_launch(void* const* d_in, const int* in_sizes, int n_in,
                              void* d_out, int out_size) {
    const float* nf  = (const float*)d_in[0];
    const float* ef  = (const float*)d_in[1];
    const int*   ei  = (const int*)d_in[2];
    const float* enW = (const float*)d_in[3];
    const float* enb = (const float*)d_in[4];
    const float* eeW = (const float*)d_in[5];
    const float* eeb = (const float*)d_in[6];
    const float* mW1 = (const float*)d_in[7];
    const float* mb1 = (const float*)d_in[8];
    const float* mW2 = (const float*)d_in[9];
    const float* mb2 = (const float*)d_in[10];
    const float* uW1 = (const float*)d_in[11];
    const float* ub1 = (const float*)d_in[12];
    const float* uW2 = (const float*)d_in[13];
    const float* ub2 = (const float*)d_in[14];
    const float* cW1 = (const float*)d_in[15];
    const float* cb1 = (const float*)d_in[16];
    const float* cW2 = (const float*)d_in[17];
    const float* cb2 = (const float*)d_in[18];
    float* out = (float*)d_out;

    int dev = 0, smc = 148;
    cudaGetDevice(&dev);
    cudaDeviceGetAttribute(&smc, cudaDevAttrMultiProcessorCount, dev);

    const int ENN_SMEM = (8320 + 8192) * 4;
    cudaFuncSetAttribute(k_msg_mma,      cudaFuncAttributeMaxDynamicSharedMemorySize, MSG_SMEM);
    cudaFuncSetAttribute(k_upd_mma,      cudaFuncAttributeMaxDynamicSharedMemorySize, UPD_SMEM);
    cudaFuncSetAttribute(k_enc_edge_mma, cudaFuncAttributeMaxDynamicSharedMemorySize, ENC_SMEM);
    cudaFuncSetAttribute(k_enc_node,     cudaFuncAttributeMaxDynamicSharedMemorySize, ENN_SMEM);

    k_enc_node<<<smc * 2, 256, ENN_SMEM>>>(nf, enW, enb);
    k_enc_edge_mma<<<smc * 2, 256, ENC_SMEM>>>(ef, eeW, eeb);

    int cur = 0;
    for (int l = 0; l < 3; l++) {
        k_zero<<<(NN * H + 255) / 256, 256>>>();
        k_msg_mma<<<smc, 32 * MSG_WARPS, MSG_SMEM>>>(ei,
                                          mW1 + (size_t)l * 192 * H, mb1 + l * H,
                                          mW2 + (size_t)l * H * H,   mb2 + l * H);
        k_upd_mma<<<smc * 2, 256, UPD_SMEM>>>(uW1 + (size_t)l * 128 * H, ub1 + l * H,
                                              uW2 + (size_t)l * H * H,   ub2 + l * H,
                                              cur, 1 - cur);
        cur = 1 - cur;
    }
    k_con<<<1184, 256>>>(cW1, cb1, cW2, cb2, cur, out);
}

// round 7
// speedup vs baseline: 2.4997x; 1.3176x over previous
#include <cuda_runtime.h>
#include <cuda_bf16.h>
#include <math.h>
#include <cstdint>

#define NN 50000
#define NE 800000
#define H  64
#define ND 128

__device__ float g_xb[2][NN * H];
__device__ float g_agg[NN * H];
__device__ float g_ps[NN * H];              // W1s^T x + b1 (per layer)
__device__ float g_pd[NN * H];              // W1d^T x
__device__ unsigned g_eh[(size_t)NE * 32];
__device__ unsigned g_el[(size_t)NE * 32];
__device__ unsigned g_xh[NN * 32];
__device__ unsigned g_xl[NN * 32];

typedef unsigned long long ull;

__device__ __forceinline__ uint32_t smem_u32(const void* p) {
    uint32_t a;
    asm("{ .reg .u64 t; cvta.to.shared.u64 t, %1; cvt.u32.u64 %0, t; }" : "=r"(a) : "l"(p));
    return a;
}

#define LDSM4(r, addr) \
    asm volatile("ldmatrix.sync.aligned.m8n8.x4.shared.b16 {%0,%1,%2,%3}, [%4];" \
        : "=r"((r)[0]), "=r"((r)[1]), "=r"((r)[2]), "=r"((r)[3]) : "r"(addr))

#define MMA16816(c, a, b0v, b1v) \
    asm volatile("mma.sync.aligned.m16n8k16.row.col.f32.bf16.bf16.f32 " \
        "{%0,%1,%2,%3},{%4,%5,%6,%7},{%8,%9},{%0,%1,%2,%3};" \
        : "+f"((c)[0]), "+f"((c)[1]), "+f"((c)[2]), "+f"((c)[3]) \
        : "r"((a)[0]), "r"((a)[1]), "r"((a)[2]), "r"((a)[3]), "r"(b0v), "r"(b1v))

__device__ __forceinline__ void bf16_split(float v, __nv_bfloat16& h, __nv_bfloat16& l) {
    h = __float2bfloat16(v);
    l = __float2bfloat16(v - __bfloat162float(h));
}
__device__ __forceinline__ unsigned pack_bf2(__nv_bfloat16 a, __nv_bfloat16 b) {
    __nv_bfloat162 t; t.x = a; t.y = b;
    return *reinterpret_cast<unsigned*>(&t);
}

// ============================================================
// k_pre: Ps = x@W1s + b1, Pd = x@W1d  (HMMA, 16 nodes/warp)
//        also zeroes g_agg rows
// ============================================================
#define PBSH 0
#define PBSL 9216
#define PBDH 18432
#define PBDL 27648
#define PBIAS 36864
#define PA 37120
#define PRE_SMEM (37120 + 8 * 4608)   // 73984

__global__ void __launch_bounds__(256) k_pre(const float* __restrict__ W1,
                                             const float* __restrict__ b1, int si) {
    extern __shared__ char sm[];
    const uint32_t smb = smem_u32(sm);
    int tid = threadIdx.x, lane = tid & 31, wid = tid >> 5;

    for (int i = tid; i < 64 * 64; i += blockDim.x) {
        int k = i >> 6, n = i & 63;
        __nv_bfloat16 h, l;
        bf16_split(W1[k * 64 + n], h, l);                    // rows 0..63 (src block)
        ((__nv_bfloat16*)(sm + PBSH))[n * 72 + k] = h;
        ((__nv_bfloat16*)(sm + PBSL))[n * 72 + k] = l;
        bf16_split(W1[(128 + k) * 64 + n], h, l);            // rows 128..191 (dst block)
        ((__nv_bfloat16*)(sm + PBDH))[n * 72 + k] = h;
        ((__nv_bfloat16*)(sm + PBDL))[n * 72 + k] = l;
    }
    if (tid < 64) ((float*)(sm + PBIAS))[tid] = b1[tid];
    __syncthreads();

    const float* b1s = (const float*)(sm + PBIAS);
    const int tig = lane & 3, gid = lane >> 2;
    const uint32_t aRowH = smb + PA + wid * 4608 + (lane & 15) * 144 + (lane & 16);
    const uint32_t aRowL = aRowH + 2304;
    const uint32_t bRow  = ((lane & 7) + ((lane & 16) >> 1));
    const uint32_t bsH = smb + PBSH + bRow * 144 + (lane & 8) * 2;
    const uint32_t bsL = bsH + (PBSL - PBSH);
    const uint32_t bdH = smb + PBDH + bRow * 144 + (lane & 8) * 2;
    const uint32_t bdL = bdH + (PBDL - PBDH);
    char* aRowPtr = sm + PA + wid * 4608;

    int gw = blockIdx.x * 8 + wid;
    int nw = gridDim.x * 8;
    for (int chunk = gw; chunk < NN / 16; chunk += nw) {
        int base16 = chunk * 16;
        #pragma unroll 4
        for (int t = 0; t < 16; t++) {
            int n = base16 + t;
            char* rp = aRowPtr + t * 144;
            ((unsigned*)rp)[lane]          = g_xh[n * 32 + lane];
            ((unsigned*)(rp + 2304))[lane] = g_xl[n * 32 + lane];
        }
        __syncwarp();

        float as[8][4], ad[8][4];
        #pragma unroll
        for (int n = 0; n < 8; n++)
            #pragma unroll
            for (int j = 0; j < 4; j++) { as[n][j] = 0.f; ad[n][j] = 0.f; }

        #pragma unroll
        for (int kt = 0; kt < 4; kt++) {
            uint32_t ah[4], al[4];
            LDSM4(ah, aRowH + kt * 32);
            LDSM4(al, aRowL + kt * 32);
            #pragma unroll
            for (int ng = 0; ng < 4; ng++) {
                uint32_t bh[4], bl[4];
                LDSM4(bh, bsH + ng * 16 * 144 + kt * 32);
                LDSM4(bl, bsL + ng * 16 * 144 + kt * 32);
                MMA16816(as[2 * ng],     ah, bh[0], bh[1]);
                MMA16816(as[2 * ng],     ah, bl[0], bl[1]);
                MMA16816(as[2 * ng],     al, bh[0], bh[1]);
                MMA16816(as[2 * ng + 1], ah, bh[2], bh[3]);
                MMA16816(as[2 * ng + 1], ah, bl[2], bl[3]);
                MMA16816(as[2 * ng + 1], al, bh[2], bh[3]);
                LDSM4(bh, bdH + ng * 16 * 144 + kt * 32);
                LDSM4(bl, bdL + ng * 16 * 144 + kt * 32);
                MMA16816(ad[2 * ng],     ah, bh[0], bh[1]);
                MMA16816(ad[2 * ng],     ah, bl[0], bl[1]);
                MMA16816(ad[2 * ng],     al, bh[0], bh[1]);
                MMA16816(ad[2 * ng + 1], ah, bh[2], bh[3]);
                MMA16816(ad[2 * ng + 1], ah, bl[2], bl[3]);
                MMA16816(ad[2 * ng + 1], al, bh[2], bh[3]);
            }
        }

        int n0 = base16 + gid, n1 = base16 + gid + 8;
        #pragma unroll
        for (int nt = 0; nt < 8; nt++) {
            float2 bb = *(const float2*)(b1s + nt * 8 + 2 * tig);
            int c = nt * 8 + 2 * tig;
            *(float2*)(g_ps + (size_t)n0 * H + c) = make_float2(as[nt][0] + bb.x, as[nt][1] + bb.y);
            *(float2*)(g_ps + (size_t)n1 * H + c) = make_float2(as[nt][2] + bb.x, as[nt][3] + bb.y);
            *(float2*)(g_pd + (size_t)n0 * H + c) = make_float2(ad[nt][0], ad[nt][1]);
            *(float2*)(g_pd + (size_t)n1 * H + c) = make_float2(ad[nt][2], ad[nt][3]);
            *(float2*)(g_agg + (size_t)n0 * H + c) = make_float2(0.f, 0.f);
            *(float2*)(g_agg + (size_t)n1 * H + c) = make_float2(0.f, 0.f);
        }
        __syncwarp();
    }
}

// ============================================================
// k_msg_mma: hidden = relu(Ps[src]+Pd[dst] + W1e^T e); out = W2^T hidden + b2
//            scatter-add to g_agg[dst].  8 warps/CTA, 74 KB smem -> 3 CTA/SM
// ============================================================
#define MB1H 0
#define MB1L 9216
#define MB2H 18432
#define MB2L 27648
#define MBIAS 36864
#define MA 37120
#define MSG_SMEM (37120 + 8 * 4608)   // 73984

__global__ void __launch_bounds__(256) k_msg_mma(const int* __restrict__ ei,
        const float* __restrict__ W1, const float* __restrict__ W2,
        const float* __restrict__ b2) {
    extern __shared__ char sm[];
    const uint32_t smb = smem_u32(sm);
    int tid = threadIdx.x, lane = tid & 31, wid = tid >> 5;

    for (int i = tid; i < 64 * 64; i += blockDim.x) {
        int k = i >> 6, n = i & 63;
        __nv_bfloat16 h, l;
        bf16_split(W1[(64 + k) * 64 + n], h, l);             // rows 64..127 (edge block)
        ((__nv_bfloat16*)(sm + MB1H))[n * 72 + k] = h;
        ((__nv_bfloat16*)(sm + MB1L))[n * 72 + k] = l;
        bf16_split(W2[k * 64 + n], h, l);
        ((__nv_bfloat16*)(sm + MB2H))[n * 72 + k] = h;
        ((__nv_bfloat16*)(sm + MB2L))[n * 72 + k] = l;
    }
    if (tid < 64) ((float*)(sm + MBIAS))[tid] = b2[tid];
    __syncthreads();

    const float* b2s = (const float*)(sm + MBIAS);
    const int tig = lane & 3, gid = lane >> 2;
    const uint32_t aRowH = smb + MA + wid * 4608 + (lane & 15) * 144 + (lane & 16);
    const uint32_t aRowL = aRowH + 2304;
    const uint32_t bRow  = ((lane & 7) + ((lane & 16) >> 1));
    const uint32_t b1H = smb + MB1H + bRow * 144 + (lane & 8) * 2;
    const uint32_t b1L = b1H + (MB1L - MB1H);
    const uint32_t b2H = smb + MB2H + bRow * 144 + (lane & 8) * 2;
    const uint32_t b2L = b2H + (MB2L - MB2H);
    char* aRowPtr = sm + MA + wid * 4608;

    int gw = blockIdx.x * 8 + wid;
    int nw = gridDim.x * 8;
    for (int chunk = gw; chunk < NE / 16; chunk += nw) {
        int base16 = chunk * 16;
        int s = 0, d = 0;
        if (lane < 16) { s = ei[base16 + lane]; d = ei[NE + base16 + lane]; }

        // stage e (split) for 16 edges
        #pragma unroll 4
        for (int t = 0; t < 16; t++) {
            char* rp = aRowPtr + t * 144;
            ((unsigned*)rp)[lane]          = g_eh[(size_t)(base16 + t) * 32 + lane];
            ((unsigned*)(rp + 2304))[lane] = g_el[(size_t)(base16 + t) * 32 + lane];
        }
        __syncwarp();

        // layer 1 (e-term only): K=64, 3-term split
        float acc[8][4];
        #pragma unroll
        for (int n = 0; n < 8; n++)
            #pragma unroll
            for (int j = 0; j < 4; j++) acc[n][j] = 0.f;

        #pragma unroll
        for (int kt = 0; kt < 4; kt++) {
            uint32_t ah[4], al[4];
            LDSM4(ah, aRowH + kt * 32);
            LDSM4(al, aRowL + kt * 32);
            #pragma unroll
            for (int ng = 0; ng < 4; ng++) {
                uint32_t bh[4], bl[4];
                LDSM4(bh, b1H + ng * 16 * 144 + kt * 32);
                LDSM4(bl, b1L + ng * 16 * 144 + kt * 32);
                MMA16816(acc[2 * ng],     ah, bh[0], bh[1]);
                MMA16816(acc[2 * ng],     ah, bl[0], bl[1]);
                MMA16816(acc[2 * ng],     al, bh[0], bh[1]);
                MMA16816(acc[2 * ng + 1], ah, bh[2], bh[3]);
                MMA16816(acc[2 * ng + 1], ah, bl[2], bl[3]);
                MMA16816(acc[2 * ng + 1], al, bh[2], bh[3]);
            }
        }

        // hidden: gather Ps[src]+Pd[dst] (fp32), relu, split -> A2 frags
        int s0 = __shfl_sync(0xffffffffu, s, gid);
        int s1 = __shfl_sync(0xffffffffu, s, gid + 8);
        int d0 = __shfl_sync(0xffffffffu, d, gid);
        int d1 = __shfl_sync(0xffffffffu, d, gid + 8);
        uint32_t a2h[4][4], a2l[4][4];
        #pragma unroll
        for (int kt = 0; kt < 4; kt++) {
            #pragma unroll
            for (int j = 0; j < 2; j++) {
                int nt = kt * 2 + j;
                int c = nt * 8 + 2 * tig;
                float2 ps0 = *(const float2*)(g_ps + (size_t)s0 * H + c);
                float2 pd0 = *(const float2*)(g_pd + (size_t)d0 * H + c);
                float2 ps1 = *(const float2*)(g_ps + (size_t)s1 * H + c);
                float2 pd1 = *(const float2*)(g_pd + (size_t)d1 * H + c);
                float v0 = fmaxf(acc[nt][0] + ps0.x + pd0.x, 0.f);
                float v1 = fmaxf(acc[nt][1] + ps0.y + pd0.y, 0.f);
                float v2 = fmaxf(acc[nt][2] + ps1.x + pd1.x, 0.f);
                float v3 = fmaxf(acc[nt][3] + ps1.y + pd1.y, 0.f);
                __nv_bfloat16 h0, l0, h1, l1, h2, l2, h3, l3;
                bf16_split(v0, h0, l0); bf16_split(v1, h1, l1);
                bf16_split(v2, h2, l2); bf16_split(v3, h3, l3);
                a2h[kt][2 * j]     = pack_bf2(h0, h1);
                a2h[kt][2 * j + 1] = pack_bf2(h2, h3);
                a2l[kt][2 * j]     = pack_bf2(l0, l1);
                a2l[kt][2 * j + 1] = pack_bf2(l2, l3);
            }
        }

        // layer 2: K=64
        float acc2[8][4];
        #pragma unroll
        for (int n = 0; n < 8; n++)
            #pragma unroll
            for (int j = 0; j < 4; j++) acc2[n][j] = 0.f;

        #pragma unroll
        for (int kt = 0; kt < 4; kt++) {
            #pragma unroll
            for (int ng = 0; ng < 4; ng++) {
                uint32_t bh[4], bl[4];
                LDSM4(bh, b2H + ng * 16 * 144 + kt * 32);
                LDSM4(bl, b2L + ng * 16 * 144 + kt * 32);
                MMA16816(acc2[2 * ng],     a2h[kt], bh[0], bh[1]);
                MMA16816(acc2[2 * ng],     a2h[kt], bl[0], bl[1]);
                MMA16816(acc2[2 * ng],     a2l[kt], bh[0], bh[1]);
                MMA16816(acc2[2 * ng + 1], a2h[kt], bh[2], bh[3]);
                MMA16816(acc2[2 * ng + 1], a2h[kt], bl[2], bl[3]);
                MMA16816(acc2[2 * ng + 1], a2l[kt], bh[2], bh[3]);
            }
        }

        float* plo = g_agg + (size_t)d0 * H + 2 * tig;
        float* phi = g_agg + (size_t)d1 * H + 2 * tig;
        #pragma unroll
        for (int nt = 0; nt < 8; nt++) {
            float2 bb = *(const float2*)(b2s + nt * 8 + 2 * tig);
            float f0 = acc2[nt][0] + bb.x, f1 = acc2[nt][1] + bb.y;
            float f2 = acc2[nt][2] + bb.x, f3 = acc2[nt][3] + bb.y;
            asm volatile("red.global.add.v2.f32 [%0], {%1,%2};"
                :: "l"(plo + nt * 8), "f"(f0), "f"(f1) : "memory");
            asm volatile("red.global.add.v2.f32 [%0], {%1,%2};"
                :: "l"(phi + nt * 8), "f"(f2), "f"(f3) : "memory");
        }
        __syncwarp();
    }
}

// ============================================================
// k_upd_mma: node update MLP via HMMA (unchanged from R6)
// ============================================================
#define UB1H 0
#define UB1L 17408
#define UB2H 34816
#define UB2L 44032
#define UBIAS 53248
#define UA 53760
#define UPD_SMEM (53760 + 8 * 8704)

__global__ void __launch_bounds__(256) k_upd_mma(
        const float* __restrict__ W1, const float* __restrict__ b1,
        const float* __restrict__ W2, const float* __restrict__ b2,
        int si, int di) {
    extern __shared__ char sm[];
    const uint32_t smb = smem_u32(sm);
    int tid = threadIdx.x, lane = tid & 31, wid = tid >> 5;

    for (int i = tid; i < 128 * 64; i += blockDim.x) {
        int k = i >> 6, n = i & 63;
        __nv_bfloat16 h, l; bf16_split(W1[i], h, l);
        ((__nv_bfloat16*)(sm + UB1H))[n * 136 + k] = h;
        ((__nv_bfloat16*)(sm + UB1L))[n * 136 + k] = l;
    }
    for (int i = tid; i < 64 * 64; i += blockDim.x) {
        int k = i >> 6, n = i & 63;
        __nv_bfloat16 h, l; bf16_split(W2[i], h, l);
        ((__nv_bfloat16*)(sm + UB2H))[n * 72 + k] = h;
        ((__nv_bfloat16*)(sm + UB2L))[n * 72 + k] = l;
    }
    if (tid < 64) {
        ((float*)(sm + UBIAS))[tid] = b1[tid];
        ((float*)(sm + UBIAS + 256))[tid] = b2[tid];
    }
    __syncthreads();

    const float* b1s = (const float*)(sm + UBIAS);
    const float* b2s = (const float*)(sm + UBIAS + 256);
    float* xd = g_xb[di];

    const int tig = lane & 3, gid = lane >> 2;
    const uint32_t aRowH = smb + UA + wid * 8704 + (lane & 15) * 272 + (lane & 16);
    const uint32_t aRowL = aRowH + 4352;
    const uint32_t bRow  = ((lane & 7) + ((lane & 16) >> 1));
    const uint32_t b1AddrH = smb + UB1H + bRow * 272 + (lane & 8) * 2;
    const uint32_t b1AddrL = b1AddrH + (UB1L - UB1H);
    const uint32_t b2AddrH = smb + UB2H + bRow * 144 + (lane & 8) * 2;
    const uint32_t b2AddrL = b2AddrH + (UB2L - UB2H);
    char* aRowPtr = sm + UA + wid * 8704;

    int gw = blockIdx.x * 8 + wid;
    int nw = gridDim.x * 8;
    for (int chunk = gw; chunk < NN / 16; chunk += nw) {
        int base16 = chunk * 16;
        #pragma unroll 4
        for (int t = 0; t < 16; t++) {
            int n = base16 + t;
            unsigned vxh = g_xh[n * 32 + lane];
            unsigned vxl = g_xl[n * 32 + lane];
            float2 ag = ((const float2*)(g_agg + (size_t)n * H))[lane];
            __nv_bfloat16 h0, l0, h1, l1;
            bf16_split(ag.x, h0, l0); bf16_split(ag.y, h1, l1);
            char* rp = aRowPtr + t * 272;
            ((unsigned*)rp)[lane]          = vxh;
            ((unsigned*)(rp + 128))[lane]  = pack_bf2(h0, h1);
            ((unsigned*)(rp + 4352))[lane] = vxl;
            ((unsigned*)(rp + 4480))[lane] = pack_bf2(l0, l1);
        }
        __syncwarp();

        float acc[8][4];
        #pragma unroll
        for (int n = 0; n < 8; n++)
            #pragma unroll
            for (int j = 0; j < 4; j++) acc[n][j] = 0.f;

        #pragma unroll 2
        for (int kt = 0; kt < 8; kt++) {
            uint32_t ah[4], al[4];
            LDSM4(ah, aRowH + kt * 32);
            LDSM4(al, aRowL + kt * 32);
            #pragma unroll
            for (int ng = 0; ng < 4; ng++) {
                uint32_t bh[4], bl[4];
                LDSM4(bh, b1AddrH + ng * 16 * 272 + kt * 32);
                LDSM4(bl, b1AddrL + ng * 16 * 272 + kt * 32);
                MMA16816(acc[2 * ng],     ah, bh[0], bh[1]);
                MMA16816(acc[2 * ng],     ah, bl[0], bl[1]);
                MMA16816(acc[2 * ng],     al, bh[0], bh[1]);
                MMA16816(acc[2 * ng + 1], ah, bh[2], bh[3]);
                MMA16816(acc[2 * ng + 1], ah, bl[2], bl[3]);
                MMA16816(acc[2 * ng + 1], al, bh[2], bh[3]);
            }
        }

        uint32_t a2h[4][4], a2l[4][4];
        #pragma unroll
        for (int kt = 0; kt < 4; kt++) {
            #pragma unroll
            for (int j = 0; j < 2; j++) {
                int nt = kt * 2 + j;
                float2 bb = *(const float2*)(b1s + nt * 8 + 2 * tig);
                float v0 = fmaxf(acc[nt][0] + bb.x, 0.f);
                float v1 = fmaxf(acc[nt][1] + bb.y, 0.f);
                float v2 = fmaxf(acc[nt][2] + bb.x, 0.f);
                float v3 = fmaxf(acc[nt][3] + bb.y, 0.f);
                __nv_bfloat16 h0, l0, h1, l1, h2, l2, h3, l3;
                bf16_split(v0, h0, l0); bf16_split(v1, h1, l1);
                bf16_split(v2, h2, l2); bf16_split(v3, h3, l3);
                a2h[kt][2 * j]     = pack_bf2(h0, h1);
                a2h[kt][2 * j + 1] = pack_bf2(h2, h3);
                a2l[kt][2 * j]     = pack_bf2(l0, l1);
                a2l[kt][2 * j + 1] = pack_bf2(l2, l3);
            }
        }

        float acc2[8][4];
        #pragma unroll
        for (int n = 0; n < 8; n++)
            #pragma unroll
            for (int j = 0; j < 4; j++) acc2[n][j] = 0.f;

        #pragma unroll
        for (int kt = 0; kt < 4; kt++) {
            #pragma unroll
            for (int ng = 0; ng < 4; ng++) {
                uint32_t bh[4], bl[4];
                LDSM4(bh, b2AddrH + ng * 16 * 144 + kt * 32);
                LDSM4(bl, b2AddrL + ng * 16 * 144 + kt * 32);
                MMA16816(acc2[2 * ng],     a2h[kt], bh[0], bh[1]);
                MMA16816(acc2[2 * ng],     a2h[kt], bl[0], bl[1]);
                MMA16816(acc2[2 * ng],     a2l[kt], bh[0], bh[1]);
                MMA16816(acc2[2 * ng + 1], a2h[kt], bh[2], bh[3]);
                MMA16816(acc2[2 * ng + 1], a2h[kt], bl[2], bl[3]);
                MMA16816(acc2[2 * ng + 1], a2l[kt], bh[2], bh[3]);
            }
        }

        int n0 = base16 + gid, n1 = base16 + gid + 8;
        #pragma unroll
        for (int nt = 0; nt < 8; nt++) {
            float2 bb = *(const float2*)(b2s + nt * 8 + 2 * tig);
            float f0 = acc2[nt][0] + bb.x, f1 = acc2[nt][1] + bb.y;
            float f2 = acc2[nt][2] + bb.x, f3 = acc2[nt][3] + bb.y;
            *(float2*)(xd + (size_t)n0 * H + nt * 8 + 2 * tig) = make_float2(f0, f1);
            *(float2*)(xd + (size_t)n1 * H + nt * 8 + 2 * tig) = make_float2(f2, f3);
            __nv_bfloat16 h0, l0, h1, l1, h2, l2, h3, l3;
            bf16_split(f0, h0, l0); bf16_split(f1, h1, l1);
            bf16_split(f2, h2, l2); bf16_split(f3, h3, l3);
            g_xh[n0 * 32 + nt * 4 + tig] = pack_bf2(h0, h1);
            g_xl[n0 * 32 + nt * 4 + tig] = pack_bf2(l0, l1);
            g_xh[n1 * 32 + nt * 4 + tig] = pack_bf2(h2, h3);
            g_xl[n1 * 32 + nt * 4 + tig] = pack_bf2(l2, l3);
        }
        __syncwarp();
    }
}

// ============================================================
// k_enc_edge_mma (unchanged from R6)
// ============================================================
#define EBH 0
#define EBL 9216
#define EBIAS 18432
#define EA 18944
#define ENC_SMEM (18944 + 8 * 4608)

__global__ void __launch_bounds__(256) k_enc_edge_mma(const float* __restrict__ ef,
        const float* __restrict__ W, const float* __restrict__ b) {
    extern __shared__ char sm[];
    const uint32_t smb = smem_u32(sm);
    int tid = threadIdx.x, lane = tid & 31, wid = tid >> 5;

    for (int i = tid; i < 64 * 64; i += blockDim.x) {
        int k = i >> 6, n = i & 63;
        __nv_bfloat16 h, l; bf16_split(W[i], h, l);
        ((__nv_bfloat16*)(sm + EBH))[n * 72 + k] = h;
        ((__nv_bfloat16*)(sm + EBL))[n * 72 + k] = l;
    }
    if (tid < 64) ((float*)(sm + EBIAS))[tid] = b[tid];
    __syncthreads();

    const float* bs = (const float*)(sm + EBIAS);
    const int tig = lane & 3;
    const int gi = lane >> 2;
    const uint32_t aRowH = smb + EA + wid * 4608 + (lane & 15) * 144 + (lane & 16);
    const uint32_t aRowL = aRowH + 2304;
    const uint32_t bRow  = ((lane & 7) + ((lane & 16) >> 1));
    const uint32_t bAddrH = smb + EBH + bRow * 144 + (lane & 8) * 2;
    const uint32_t bAddrL = bAddrH + (EBL - EBH);
    char* aRowPtr = sm + EA + wid * 4608;

    int gw = blockIdx.x * 8 + wid;
    int nw = gridDim.x * 8;
    for (int chunk = gw; chunk < NE / 16; chunk += nw) {
        int base16 = chunk * 16;
        #pragma unroll 4
        for (int t = 0; t < 16; t++) {
            float2 v = ((const float2*)(ef + (size_t)(base16 + t) * H))[lane];
            __nv_bfloat16 h0, l0, h1, l1;
            bf16_split(v.x, h0, l0); bf16_split(v.y, h1, l1);
            char* rp = aRowPtr + t * 144;
            ((unsigned*)rp)[lane]          = pack_bf2(h0, h1);
            ((unsigned*)(rp + 2304))[lane] = pack_bf2(l0, l1);
        }
        __syncwarp();

        float acc[8][4];
        #pragma unroll
        for (int n = 0; n < 8; n++)
            #pragma unroll
            for (int j = 0; j < 4; j++) acc[n][j] = 0.f;

        #pragma unroll
        for (int kt = 0; kt < 4; kt++) {
            uint32_t ah[4], al[4];
            LDSM4(ah, aRowH + kt * 32);
            LDSM4(al, aRowL + kt * 32);
            #pragma unroll
            for (int ng = 0; ng < 4; ng++) {
                uint32_t bh[4], bl[4];
                LDSM4(bh, bAddrH + ng * 16 * 144 + kt * 32);
                LDSM4(bl, bAddrL + ng * 16 * 144 + kt * 32);
                MMA16816(acc[2 * ng],     ah, bh[0], bh[1]);
                MMA16816(acc[2 * ng],     ah, bl[0], bl[1]);
                MMA16816(acc[2 * ng],     al, bh[0], bh[1]);
                MMA16816(acc[2 * ng + 1], ah, bh[2], bh[3]);
                MMA16816(acc[2 * ng + 1], ah, bl[2], bl[3]);
                MMA16816(acc[2 * ng + 1], al, bh[2], bh[3]);
            }
        }

        size_t e0 = (size_t)(base16 + gi), e1 = (size_t)(base16 + gi + 8);
        #pragma unroll
        for (int nt = 0; nt < 8; nt++) {
            float2 bb = *(const float2*)(bs + nt * 8 + 2 * tig);
            float f0 = acc[nt][0] + bb.x, f1 = acc[nt][1] + bb.y;
            float f2 = acc[nt][2] + bb.x, f3 = acc[nt][3] + bb.y;
            __nv_bfloat16 h0, l0, h1, l1, h2, l2, h3, l3;
            bf16_split(f0, h0, l0); bf16_split(f1, h1, l1);
            bf16_split(f2, h2, l2); bf16_split(f3, h3, l3);
            g_eh[e0 * 32 + nt * 4 + tig] = pack_bf2(h0, h1);
            g_el[e0 * 32 + nt * 4 + tig] = pack_bf2(l0, l1);
            g_eh[e1 * 32 + nt * 4 + tig] = pack_bf2(h2, h3);
            g_el[e1 * 32 + nt * 4 + tig] = pack_bf2(l2, l3);
        }
        __syncwarp();
    }
}

// ============================================================
// k_enc_node: scalar f32x2, writes fp32 x + split (unchanged)
// ============================================================
__device__ __forceinline__ void ffma2(ull& d, ull a, ull b) {
    asm("fma.rn.f32x2 %0, %1, %2, %0;" : "+l"(d) : "l"(a), "l"(b));
}
__device__ __forceinline__ float fin(ull a, float b) {
    return __uint_as_float((unsigned)a) + __uint_as_float((unsigned)(a >> 32)) + b;
}

__global__ void __launch_bounds__(256) k_enc_node(const float* __restrict__ nf,
        const float* __restrict__ W, const float* __restrict__ b) {
    extern __shared__ float smf[];
    float* Wp   = smf;
    float* winb = Wp + 8320;
    int tid = threadIdx.x;
    for (int i = tid; i < 128 * 64; i += 256) {
        int k = i >> 6, c = i & 63;
        Wp[(c >> 1) * 260 + (k >> 1) * 4 + ((c & 1) << 1) + (k & 1)] = W[i];
    }
    __syncthreads();
    int lane = tid & 31, wid = tid >> 5;
    float2 bb = ((const float2*)b)[lane];
    float* win = winb + wid * 8 * ND;
    const ulonglong2* wl = (const ulonglong2*)(Wp + (size_t)lane * 260);
    int gw = blockIdx.x * 8 + wid;
    int nw = gridDim.x * 8;
    for (int base = gw * 8; base < NN; base += nw * 8) {
        #pragma unroll
        for (int t = 0; t < 8; t++) {
            float4 v = *(const float4*)(nf + (size_t)(base + t) * ND + lane * 4);
            *(float4*)(win + t * ND + lane * 4) = v;
        }
        __syncwarp();
        ull a0[8], a1[8];
        #pragma unroll
        for (int t = 0; t < 8; t++) { a0[t] = 0ull; a1[t] = 0ull; }
        #pragma unroll 4
        for (int c = 0; c < 32; c++) {
            ulonglong2 wA = wl[2 * c];
            ulonglong2 wB = wl[2 * c + 1];
            #pragma unroll
            for (int t = 0; t < 8; t++) {
                ulonglong2 v = ((const ulonglong2*)(win + t * ND))[c];
                ffma2(a0[t], wA.x, v.x); ffma2(a1[t], wA.y, v.x);
                ffma2(a0[t], wB.x, v.y); ffma2(a1[t], wB.y, v.y);
            }
        }
        #pragma unroll
        for (int t = 0; t < 8; t++) {
            float o0 = fin(a0[t], bb.x);
            float o1 = fin(a1[t], bb.y);
            int n = base + t;
            *(float2*)(g_xb[0] + (size_t)n * H + 2 * lane) = make_float2(o0, o1);
            __nv_bfloat16 h0, l0, h1, l1;
            bf16_split(o0, h0, l0); bf16_split(o1, h1, l1);
            g_xh[n * 32 + lane] = pack_bf2(h0, h1);
            g_xl[n * 32 + lane] = pack_bf2(l0, l1);
        }
        __syncwarp();
    }
}

__global__ void k_con(const float* __restrict__ W1, const float* __restrict__ b1,
                      const float* __restrict__ w2, const float* __restrict__ b2,
                      int si, float* __restrict__ out) {
    __shared__ float Ws[H * H];
    __shared__ float bs[H];
    __shared__ float w2s[H];
    __shared__ float xb[8][H];
    __shared__ float b2v;
    int tid = threadIdx.x;
    for (int i = tid; i < H * H; i += blockDim.x) Ws[i] = W1[i];
    if (tid < H) { bs[tid] = b1[tid]; w2s[tid] = w2[tid]; }
    if (tid == 0) b2v = b2[0];
    __syncthreads();
    const float* xs = g_xb[si];
    int lane = tid & 31, wid = tid >> 5;
    int gw = blockIdx.x * 8 + wid;
    int nw = gridDim.x * 8;
    for (int n = gw; n < NN; n += nw) {
        float xv0 = xs[(size_t)n * H + lane];
        float xv1 = xs[(size_t)n * H + lane + 32];
        out[(size_t)n * H + lane]      = xv0;
        out[(size_t)n * H + lane + 32] = xv1;
        xb[wid][lane]      = xv0;
        xb[wid][lane + 32] = xv1;
        __syncwarp();
        float a0 = bs[lane], a1 = bs[lane + 32];
        #pragma unroll 4
        for (int k = 0; k < H; k++) {
            float v = xb[wid][k];
            a0 += v * Ws[k * H + lane];
            a1 += v * Ws[k * H + lane + 32];
        }
        float p = fmaxf(a0, 0.f) * w2s[lane] + fmaxf(a1, 0.f) * w2s[lane + 32];
        #pragma unroll
        for (int o = 16; o; o >>= 1) p += __shfl_xor_sync(0xffffffffu, p, o);
        if (lane == 0)
            out[(size_t)NN * H + n] = 1.f / (1.f + expf(-(p + b2v)));
        __syncwarp();
    }
}

extern "C" void kernel_launch(void* const* d_in, const int* in_sizes, int n_in,
                              void* d_out, int out_size) {
    const float* nf  = (const float*)d_in[0];
    const float* ef  = (const float*)d_in[1];
    const int*   ei  = (const int*)d_in[2];
    const float* enW = (const float*)d_in[3];
    const float* enb = (const float*)d_in[4];
    const float* eeW = (const float*)d_in[5];
    const float* eeb = (const float*)d_in[6];
    const float* mW1 = (const float*)d_in[7];
    const float* mb1 = (const float*)d_in[8];
    const float* mW2 = (const float*)d_in[9];
    const float* mb2 = (const float*)d_in[10];
    const float* uW1 = (const float*)d_in[11];
    const float* ub1 = (const float*)d_in[12];
    const float* uW2 = (const float*)d_in[13];
    const float* ub2 = (const float*)d_in[14];
    const float* cW1 = (const float*)d_in[15];
    const float* cb1 = (const float*)d_in[16];
    const float* cW2 = (const float*)d_in[17];
    const float* cb2 = (const float*)d_in[18];
    float* out = (float*)d_out;

    int dev = 0, smc = 148;
    cudaGetDevice(&dev);
    cudaDeviceGetAttribute(&smc, cudaDevAttrMultiProcessorCount, dev);

    const int ENN_SMEM = (8320 + 8192) * 4;
    cudaFuncSetAttribute(k_pre,          cudaFuncAttributeMaxDynamicSharedMemorySize, PRE_SMEM);
    cudaFuncSetAttribute(k_msg_mma,      cudaFuncAttributeMaxDynamicSharedMemorySize, MSG_SMEM);
    cudaFuncSetAttribute(k_upd_mma,      cudaFuncAttributeMaxDynamicSharedMemorySize, UPD_SMEM);
    cudaFuncSetAttribute(k_enc_edge_mma, cudaFuncAttributeMaxDynamicSharedMemorySize, ENC_SMEM);
    cudaFuncSetAttribute(k_enc_node,     cudaFuncAttributeMaxDynamicSharedMemorySize, ENN_SMEM);

    k_enc_node<<<smc * 2, 256, ENN_SMEM>>>(nf, enW, enb);
    k_enc_edge_mma<<<smc * 2, 256, ENC_SMEM>>>(ef, eeW, eeb);

    int cur = 0;
    for (int l = 0; l < 3; l++) {
        k_pre<<<smc * 2, 256, PRE_SMEM>>>(mW1 + (size_t)l * 192 * H, mb1 + l * H, cur);
        k_msg_mma<<<smc * 3, 256, MSG_SMEM>>>(ei,
                                              mW1 + (size_t)l * 192 * H,
                                              mW2 + (size_t)l * H * H, mb2 + l * H);
        k_upd_mma<<<smc * 2, 256, UPD_SMEM>>>(uW1 + (size_t)l * 128 * H, ub1 + l * H,
                                              uW2 + (size_t)l * H * H,   ub2 + l * H,
                                              cur, 1 - cur);
        cur = 1 - cur;
    }
    k_con<<<1184, 256>>>(cW1, cb1, cW2, cb2, cur, out);
}

// round 8
// speedup vs baseline: 2.8112x; 1.1246x over previous
#include <cuda_runtime.h>
#include <cuda_bf16.h>
#include <math.h>
#include <cstdint>

#define NN 50000
#define NE 800000
#define H  64
#define ND 128

__device__ float g_xb[2][NN * H];
__device__ float g_agg[NN * H];
__device__ float g_ps[NN * H];                  // permuted: [node][tig*16 + nt*2 + {0,1}]
__device__ float g_pd[NN * H];
__device__ unsigned g_eth[(size_t)NE * 32];     // e split-hi, tiled per 16-edge chunk (2KB)
__device__ unsigned g_etl[(size_t)NE * 32];     // e split-lo, tiled
__device__ unsigned g_xh[NN * 32];
__device__ unsigned g_xl[NN * 32];

typedef unsigned long long ull;

__device__ __forceinline__ uint32_t smem_u32(const void* p) {
    uint32_t a;
    asm("{ .reg .u64 t; cvta.to.shared.u64 t, %1; cvt.u32.u64 %0, t; }" : "=r"(a) : "l"(p));
    return a;
}

#define LDSM4(r, addr) \
    asm volatile("ldmatrix.sync.aligned.m8n8.x4.shared.b16 {%0,%1,%2,%3}, [%4];" \
        : "=r"((r)[0]), "=r"((r)[1]), "=r"((r)[2]), "=r"((r)[3]) : "r"(addr))

#define MMA16816(c, a, b0v, b1v) \
    asm volatile("mma.sync.aligned.m16n8k16.row.col.f32.bf16.bf16.f32 " \
        "{%0,%1,%2,%3},{%4,%5,%6,%7},{%8,%9},{%0,%1,%2,%3};" \
        : "+f"((c)[0]), "+f"((c)[1]), "+f"((c)[2]), "+f"((c)[3]) \
        : "r"((a)[0]), "r"((a)[1]), "r"((a)[2]), "r"((a)[3]), "r"(b0v), "r"(b1v))

__device__ __forceinline__ void bf16_split(float v, __nv_bfloat16& h, __nv_bfloat16& l) {
    h = __float2bfloat16(v);
    l = __float2bfloat16(v - __bfloat162float(h));
}
__device__ __forceinline__ unsigned pack_bf2(__nv_bfloat16 a, __nv_bfloat16 b) {
    __nv_bfloat162 t; t.x = a; t.y = b;
    return *reinterpret_cast<unsigned*>(&t);
}

// ============================================================
// k_pre: Ps = x@W1s + b1 (permuted), Pd = x@W1d (permuted); zeroes g_agg
// ============================================================
#define PBSH 0
#define PBSL 9216
#define PBDH 18432
#define PBDL 27648
#define PBIAS 36864
#define PA 37120
#define PRE_SMEM (37120 + 8 * 4608)

__global__ void __launch_bounds__(256) k_pre(const float* __restrict__ W1,
                                             const float* __restrict__ b1, int si) {
    extern __shared__ char sm[];
    const uint32_t smb = smem_u32(sm);
    int tid = threadIdx.x, lane = tid & 31, wid = tid >> 5;

    for (int i = tid; i < 64 * 64; i += blockDim.x) {
        int k = i >> 6, n = i & 63;
        __nv_bfloat16 h, l;
        bf16_split(W1[k * 64 + n], h, l);
        ((__nv_bfloat16*)(sm + PBSH))[n * 72 + k] = h;
        ((__nv_bfloat16*)(sm + PBSL))[n * 72 + k] = l;
        bf16_split(W1[(128 + k) * 64 + n], h, l);
        ((__nv_bfloat16*)(sm + PBDH))[n * 72 + k] = h;
        ((__nv_bfloat16*)(sm + PBDL))[n * 72 + k] = l;
    }
    if (tid < 64) ((float*)(sm + PBIAS))[tid] = b1[tid];
    __syncthreads();

    const float* b1s = (const float*)(sm + PBIAS);
    const int tig = lane & 3, gid = lane >> 2;
    const uint32_t aRowH = smb + PA + wid * 4608 + (lane & 15) * 144 + (lane & 16);
    const uint32_t aRowL = aRowH + 2304;
    const uint32_t bRow  = ((lane & 7) + ((lane & 16) >> 1));
    const uint32_t bsH = smb + PBSH + bRow * 144 + (lane & 8) * 2;
    const uint32_t bsL = bsH + (PBSL - PBSH);
    const uint32_t bdH = smb + PBDH + bRow * 144 + (lane & 8) * 2;
    const uint32_t bdL = bdH + (PBDL - PBDH);
    char* aRowPtr = sm + PA + wid * 4608;

    int gw = blockIdx.x * 8 + wid;
    int nw = gridDim.x * 8;
    for (int chunk = gw; chunk < NN / 16; chunk += nw) {
        int base16 = chunk * 16;
        #pragma unroll 4
        for (int t = 0; t < 16; t++) {
            int n = base16 + t;
            char* rp = aRowPtr + t * 144;
            ((unsigned*)rp)[lane]          = g_xh[n * 32 + lane];
            ((unsigned*)(rp + 2304))[lane] = g_xl[n * 32 + lane];
        }
        __syncwarp();

        float as[8][4], ad[8][4];
        #pragma unroll
        for (int n = 0; n < 8; n++)
            #pragma unroll
            for (int j = 0; j < 4; j++) { as[n][j] = 0.f; ad[n][j] = 0.f; }

        #pragma unroll
        for (int kt = 0; kt < 4; kt++) {
            uint32_t ah[4], al[4];
            LDSM4(ah, aRowH + kt * 32);
            LDSM4(al, aRowL + kt * 32);
            #pragma unroll
            for (int ng = 0; ng < 4; ng++) {
                uint32_t bh[4], bl[4];
                LDSM4(bh, bsH + ng * 16 * 144 + kt * 32);
                LDSM4(bl, bsL + ng * 16 * 144 + kt * 32);
                MMA16816(as[2 * ng],     ah, bh[0], bh[1]);
                MMA16816(as[2 * ng],     ah, bl[0], bl[1]);
                MMA16816(as[2 * ng],     al, bh[0], bh[1]);
                MMA16816(as[2 * ng + 1], ah, bh[2], bh[3]);
                MMA16816(as[2 * ng + 1], ah, bl[2], bl[3]);
                MMA16816(as[2 * ng + 1], al, bh[2], bh[3]);
                LDSM4(bh, bdH + ng * 16 * 144 + kt * 32);
                LDSM4(bl, bdL + ng * 16 * 144 + kt * 32);
                MMA16816(ad[2 * ng],     ah, bh[0], bh[1]);
                MMA16816(ad[2 * ng],     ah, bl[0], bl[1]);
                MMA16816(ad[2 * ng],     al, bh[0], bh[1]);
                MMA16816(ad[2 * ng + 1], ah, bh[2], bh[3]);
                MMA16816(ad[2 * ng + 1], ah, bl[2], bl[3]);
                MMA16816(ad[2 * ng + 1], al, bh[2], bh[3]);
            }
        }

        int n0 = base16 + gid, n1 = base16 + gid + 8;
        #pragma unroll
        for (int nt = 0; nt < 8; nt++) {
            float2 bb = *(const float2*)(b1s + nt * 8 + 2 * tig);
            int c = nt * 8 + 2 * tig;          // standard layout (g_agg)
            int pc = tig * 16 + nt * 2;        // permuted layout (g_ps/g_pd)
            *(float2*)(g_ps + (size_t)n0 * H + pc) = make_float2(as[nt][0] + bb.x, as[nt][1] + bb.y);
            *(float2*)(g_ps + (size_t)n1 * H + pc) = make_float2(as[nt][2] + bb.x, as[nt][3] + bb.y);
            *(float2*)(g_pd + (size_t)n0 * H + pc) = make_float2(ad[nt][0], ad[nt][1]);
            *(float2*)(g_pd + (size_t)n1 * H + pc) = make_float2(ad[nt][2], ad[nt][3]);
            *(float2*)(g_agg + (size_t)n0 * H + c) = make_float2(0.f, 0.f);
            *(float2*)(g_agg + (size_t)n1 * H + c) = make_float2(0.f, 0.f);
        }
        __syncwarp();
    }
}

// ============================================================
// k_msg_mma: cp.async double-buffered e, Ps/Pd register prefetch
// ============================================================
#define MB1H 0
#define MB1L 9216
#define MB2H 18432
#define MB2L 27648
#define MBIAS 36864
#define MA 37120
#define MSG_SMEM (37120 + 8 * 9216)   // 110848 -> 2 CTA/SM

__global__ void __launch_bounds__(256, 2) k_msg_mma(const int* __restrict__ ei,
        const float* __restrict__ W1, const float* __restrict__ W2,
        const float* __restrict__ b2) {
    extern __shared__ char sm[];
    const uint32_t smb = smem_u32(sm);
    int tid = threadIdx.x, lane = tid & 31, wid = tid >> 5;

    for (int i = tid; i < 64 * 64; i += blockDim.x) {
        int k = i >> 6, n = i & 63;
        __nv_bfloat16 h, l;
        bf16_split(W1[(64 + k) * 64 + n], h, l);
        ((__nv_bfloat16*)(sm + MB1H))[n * 72 + k] = h;
        ((__nv_bfloat16*)(sm + MB1L))[n * 72 + k] = l;
        bf16_split(W2[k * 64 + n], h, l);
        ((__nv_bfloat16*)(sm + MB2H))[n * 72 + k] = h;
        ((__nv_bfloat16*)(sm + MB2L))[n * 72 + k] = l;
    }
    if (tid < 64) ((float*)(sm + MBIAS))[tid] = b2[tid];
    __syncthreads();

    const float* b2s = (const float*)(sm + MBIAS);
    const int tig = lane & 3, gid = lane >> 2;
    const uint32_t bRow  = ((lane & 7) + ((lane & 16) >> 1));
    const uint32_t b1H = smb + MB1H + bRow * 144 + (lane & 8) * 2;
    const uint32_t b1L = b1H + (MB1L - MB1H);
    const uint32_t b2H = smb + MB2H + bRow * 144 + (lane & 8) * 2;
    const uint32_t b2L = b2H + (MB2L - MB2H);
    const uint32_t abuf0 = smb + MA + wid * 9216;

    const int NCH = NE / 16;
    int gw = blockIdx.x * 8 + wid;
    int nw = gridDim.x * 8;

    // async e-stage: 8 x 16B cp.async per chunk (hi+lo)
    auto issue_e = [&](int ch, int b) {
        const char* gh = ((const char*)g_eth) + (size_t)ch * 2048;
        const char* gl = ((const char*)g_etl) + (size_t)ch * 2048;
        uint32_t ab = abuf0 + b * 4608;
        #pragma unroll
        for (int j = 0; j < 4; j++) {
            int g = j * 512 + lane * 16;
            uint32_t da = ab + (g >> 7) * 144 + (g & 127);
            asm volatile("cp.async.cg.shared.global [%0], [%1], 16;" :: "r"(da), "l"(gh + g) : "memory");
            asm volatile("cp.async.cg.shared.global [%0], [%1], 16;" :: "r"(da + 2304), "l"(gl + g) : "memory");
        }
    };

    int chunk = gw, buf = 0;
    if (chunk < NCH) issue_e(chunk, 0);
    asm volatile("cp.async.commit_group;" ::: "memory");

    for (; chunk < NCH; chunk += nw) {
        int nxt = chunk + nw;
        if (nxt < NCH) issue_e(nxt, buf ^ 1);
        asm volatile("cp.async.commit_group;" ::: "memory");

        int base16 = chunk * 16;
        int s = 0, d = 0;
        if (lane < 16) { s = ei[base16 + lane]; d = ei[NE + base16 + lane]; }
        int s0 = __shfl_sync(0xffffffffu, s, gid), s1 = __shfl_sync(0xffffffffu, s, gid + 8);
        int d0 = __shfl_sync(0xffffffffu, d, gid), d1 = __shfl_sync(0xffffffffu, d, gid + 8);

        // prefetch Ps/Pd (permuted; 64B contiguous per lane per row)
        float4 P0[4], P1[4], Q0[4], Q1[4];
        {
            const float4* a0p = (const float4*)(g_ps + (size_t)s0 * H + tig * 16);
            const float4* a1p = (const float4*)(g_ps + (size_t)s1 * H + tig * 16);
            const float4* c0p = (const float4*)(g_pd + (size_t)d0 * H + tig * 16);
            const float4* c1p = (const float4*)(g_pd + (size_t)d1 * H + tig * 16);
            #pragma unroll
            for (int m = 0; m < 4; m++) {
                P0[m] = __ldg(a0p + m); P1[m] = __ldg(a1p + m);
                Q0[m] = __ldg(c0p + m); Q1[m] = __ldg(c1p + m);
            }
        }

        asm volatile("cp.async.wait_group 1;" ::: "memory");
        __syncwarp();

        const uint32_t aH = abuf0 + buf * 4608 + (lane & 15) * 144 + (lane & 16);
        const uint32_t aL = aH + 2304;

        // layer 1 (e-term): K=64
        float acc[8][4];
        #pragma unroll
        for (int n = 0; n < 8; n++)
            #pragma unroll
            for (int j = 0; j < 4; j++) acc[n][j] = 0.f;

        #pragma unroll
        for (int kt = 0; kt < 4; kt++) {
            uint32_t ah[4], al[4];
            LDSM4(ah, aH + kt * 32);
            LDSM4(al, aL + kt * 32);
            #pragma unroll
            for (int ng = 0; ng < 4; ng++) {
                uint32_t bh[4], bl[4];
                LDSM4(bh, b1H + ng * 16 * 144 + kt * 32);
                LDSM4(bl, b1L + ng * 16 * 144 + kt * 32);
                MMA16816(acc[2 * ng],     ah, bh[0], bh[1]);
                MMA16816(acc[2 * ng],     ah, bl[0], bl[1]);
                MMA16816(acc[2 * ng],     al, bh[0], bh[1]);
                MMA16816(acc[2 * ng + 1], ah, bh[2], bh[3]);
                MMA16816(acc[2 * ng + 1], ah, bl[2], bl[3]);
                MMA16816(acc[2 * ng + 1], al, bh[2], bh[3]);
            }
        }

        // layer 2 fused per kt: hidden -> a2 frags -> MMAs
        float acc2[8][4];
        #pragma unroll
        for (int n = 0; n < 8; n++)
            #pragma unroll
            for (int j = 0; j < 4; j++) acc2[n][j] = 0.f;

        #pragma unroll
        for (int kt = 0; kt < 4; kt++) {
            uint32_t a2h[4], a2l[4];
            #pragma unroll
            for (int j = 0; j < 2; j++) {
                int nt = 2 * kt + j;
                float pa0 = j ? P0[kt].z : P0[kt].x, pa1 = j ? P0[kt].w : P0[kt].y;
                float qa0 = j ? Q0[kt].z : Q0[kt].x, qa1 = j ? Q0[kt].w : Q0[kt].y;
                float pb0 = j ? P1[kt].z : P1[kt].x, pb1 = j ? P1[kt].w : P1[kt].y;
                float qb0 = j ? Q1[kt].z : Q1[kt].x, qb1 = j ? Q1[kt].w : Q1[kt].y;
                float v0 = fmaxf(acc[nt][0] + pa0 + qa0, 0.f);
                float v1 = fmaxf(acc[nt][1] + pa1 + qa1, 0.f);
                float v2 = fmaxf(acc[nt][2] + pb0 + qb0, 0.f);
                float v3 = fmaxf(acc[nt][3] + pb1 + qb1, 0.f);
                __nv_bfloat16 h0, l0, h1, l1, h2, l2, h3, l3;
                bf16_split(v0, h0, l0); bf16_split(v1, h1, l1);
                bf16_split(v2, h2, l2); bf16_split(v3, h3, l3);
                a2h[2 * j]     = pack_bf2(h0, h1);
                a2h[2 * j + 1] = pack_bf2(h2, h3);
                a2l[2 * j]     = pack_bf2(l0, l1);
                a2l[2 * j + 1] = pack_bf2(l2, l3);
            }
            #pragma unroll
            for (int ng = 0; ng < 4; ng++) {
                uint32_t bh[4], bl[4];
                LDSM4(bh, b2H + ng * 16 * 144 + kt * 32);
                LDSM4(bl, b2L + ng * 16 * 144 + kt * 32);
                MMA16816(acc2[2 * ng],     a2h, bh[0], bh[1]);
                MMA16816(acc2[2 * ng],     a2h, bl[0], bl[1]);
                MMA16816(acc2[2 * ng],     a2l, bh[0], bh[1]);
                MMA16816(acc2[2 * ng + 1], a2h, bh[2], bh[3]);
                MMA16816(acc2[2 * ng + 1], a2h, bl[2], bl[3]);
                MMA16816(acc2[2 * ng + 1], a2l, bh[2], bh[3]);
            }
        }

        float* plo = g_agg + (size_t)d0 * H + 2 * tig;
        float* phi = g_agg + (size_t)d1 * H + 2 * tig;
        #pragma unroll
        for (int nt = 0; nt < 8; nt++) {
            float2 bb = *(const float2*)(b2s + nt * 8 + 2 * tig);
            float f0 = acc2[nt][0] + bb.x, f1 = acc2[nt][1] + bb.y;
            float f2 = acc2[nt][2] + bb.x, f3 = acc2[nt][3] + bb.y;
            asm volatile("red.global.add.v2.f32 [%0], {%1,%2};"
                :: "l"(plo + nt * 8), "f"(f0), "f"(f1) : "memory");
            asm volatile("red.global.add.v2.f32 [%0], {%1,%2};"
                :: "l"(phi + nt * 8), "f"(f2), "f"(f3) : "memory");
        }
        buf ^= 1;
        __syncwarp();
    }
}

// ============================================================
// k_upd_mma: node update MLP via HMMA (unchanged)
// ============================================================
#define UB1H 0
#define UB1L 17408
#define UB2H 34816
#define UB2L 44032
#define UBIAS 53248
#define UA 53760
#define UPD_SMEM (53760 + 8 * 8704)

__global__ void __launch_bounds__(256) k_upd_mma(
        const float* __restrict__ W1, const float* __restrict__ b1,
        const float* __restrict__ W2, const float* __restrict__ b2,
        int si, int di) {
    extern __shared__ char sm[];
    const uint32_t smb = smem_u32(sm);
    int tid = threadIdx.x, lane = tid & 31, wid = tid >> 5;

    for (int i = tid; i < 128 * 64; i += blockDim.x) {
        int k = i >> 6, n = i & 63;
        __nv_bfloat16 h, l; bf16_split(W1[i], h, l);
        ((__nv_bfloat16*)(sm + UB1H))[n * 136 + k] = h;
        ((__nv_bfloat16*)(sm + UB1L))[n * 136 + k] = l;
    }
    for (int i = tid; i < 64 * 64; i += blockDim.x) {
        int k = i >> 6, n = i & 63;
        __nv_bfloat16 h, l; bf16_split(W2[i], h, l);
        ((__nv_bfloat16*)(sm + UB2H))[n * 72 + k] = h;
        ((__nv_bfloat16*)(sm + UB2L))[n * 72 + k] = l;
    }
    if (tid < 64) {
        ((float*)(sm + UBIAS))[tid] = b1[tid];
        ((float*)(sm + UBIAS + 256))[tid] = b2[tid];
    }
    __syncthreads();

    const float* b1s = (const float*)(sm + UBIAS);
    const float* b2s = (const float*)(sm + UBIAS + 256);
    float* xd = g_xb[di];

    const int tig = lane & 3, gid = lane >> 2;
    const uint32_t aRowH = smb + UA + wid * 8704 + (lane & 15) * 272 + (lane & 16);
    const uint32_t aRowL = aRowH + 4352;
    const uint32_t bRow  = ((lane & 7) + ((lane & 16) >> 1));
    const uint32_t b1AddrH = smb + UB1H + bRow * 272 + (lane & 8) * 2;
    const uint32_t b1AddrL = b1AddrH + (UB1L - UB1H);
    const uint32_t b2AddrH = smb + UB2H + bRow * 144 + (lane & 8) * 2;
    const uint32_t b2AddrL = b2AddrH + (UB2L - UB2H);
    char* aRowPtr = sm + UA + wid * 8704;

    int gw = blockIdx.x * 8 + wid;
    int nw = gridDim.x * 8;
    for (int chunk = gw; chunk < NN / 16; chunk += nw) {
        int base16 = chunk * 16;
        #pragma unroll 4
        for (int t = 0; t < 16; t++) {
            int n = base16 + t;
            unsigned vxh = g_xh[n * 32 + lane];
            unsigned vxl = g_xl[n * 32 + lane];
            float2 ag = ((const float2*)(g_agg + (size_t)n * H))[lane];
            __nv_bfloat16 h0, l0, h1, l1;
            bf16_split(ag.x, h0, l0); bf16_split(ag.y, h1, l1);
            char* rp = aRowPtr + t * 272;
            ((unsigned*)rp)[lane]          = vxh;
            ((unsigned*)(rp + 128))[lane]  = pack_bf2(h0, h1);
            ((unsigned*)(rp + 4352))[lane] = vxl;
            ((unsigned*)(rp + 4480))[lane] = pack_bf2(l0, l1);
        }
        __syncwarp();

        float acc[8][4];
        #pragma unroll
        for (int n = 0; n < 8; n++)
            #pragma unroll
            for (int j = 0; j < 4; j++) acc[n][j] = 0.f;

        #pragma unroll 2
        for (int kt = 0; kt < 8; kt++) {
            uint32_t ah[4], al[4];
            LDSM4(ah, aRowH + kt * 32);
            LDSM4(al, aRowL + kt * 32);
            #pragma unroll
            for (int ng = 0; ng < 4; ng++) {
                uint32_t bh[4], bl[4];
                LDSM4(bh, b1AddrH + ng * 16 * 272 + kt * 32);
                LDSM4(bl, b1AddrL + ng * 16 * 272 + kt * 32);
                MMA16816(acc[2 * ng],     ah, bh[0], bh[1]);
                MMA16816(acc[2 * ng],     ah, bl[0], bl[1]);
                MMA16816(acc[2 * ng],     al, bh[0], bh[1]);
                MMA16816(acc[2 * ng + 1], ah, bh[2], bh[3]);
                MMA16816(acc[2 * ng + 1], ah, bl[2], bl[3]);
                MMA16816(acc[2 * ng + 1], al, bh[2], bh[3]);
            }
        }

        uint32_t a2h[4][4], a2l[4][4];
        #pragma unroll
        for (int kt = 0; kt < 4; kt++) {
            #pragma unroll
            for (int j = 0; j < 2; j++) {
                int nt = kt * 2 + j;
                float2 bb = *(const float2*)(b1s + nt * 8 + 2 * tig);
                float v0 = fmaxf(acc[nt][0] + bb.x, 0.f);
                float v1 = fmaxf(acc[nt][1] + bb.y, 0.f);
                float v2 = fmaxf(acc[nt][2] + bb.x, 0.f);
                float v3 = fmaxf(acc[nt][3] + bb.y, 0.f);
                __nv_bfloat16 h0, l0, h1, l1, h2, l2, h3, l3;
                bf16_split(v0, h0, l0); bf16_split(v1, h1, l1);
                bf16_split(v2, h2, l2); bf16_split(v3, h3, l3);
                a2h[kt][2 * j]     = pack_bf2(h0, h1);
                a2h[kt][2 * j + 1] = pack_bf2(h2, h3);
                a2l[kt][2 * j]     = pack_bf2(l0, l1);
                a2l[kt][2 * j + 1] = pack_bf2(l2, l3);
            }
        }

        float acc2[8][4];
        #pragma unroll
        for (int n = 0; n < 8; n++)
            #pragma unroll
            for (int j = 0; j < 4; j++) acc2[n][j] = 0.f;

        #pragma unroll
        for (int kt = 0; kt < 4; kt++) {
            #pragma unroll
            for (int ng = 0; ng < 4; ng++) {
                uint32_t bh[4], bl[4];
                LDSM4(bh, b2AddrH + ng * 16 * 144 + kt * 32);
                LDSM4(bl, b2AddrL + ng * 16 * 144 + kt * 32);
                MMA16816(acc2[2 * ng],     a2h[kt], bh[0], bh[1]);
                MMA16816(acc2[2 * ng],     a2h[kt], bl[0], bl[1]);
                MMA16816(acc2[2 * ng],     a2l[kt], bh[0], bh[1]);
                MMA16816(acc2[2 * ng + 1], a2h[kt], bh[2], bh[3]);
                MMA16816(acc2[2 * ng + 1], a2h[kt], bl[2], bl[3]);
                MMA16816(acc2[2 * ng + 1], a2l[kt], bh[2], bh[3]);
            }
        }

        int n0 = base16 + gid, n1 = base16 + gid + 8;
        #pragma unroll
        for (int nt = 0; nt < 8; nt++) {
            float2 bb = *(const float2*)(b2s + nt * 8 + 2 * tig);
            float f0 = acc2[nt][0] + bb.x, f1 = acc2[nt][1] + bb.y;
            float f2 = acc2[nt][2] + bb.x, f3 = acc2[nt][3] + bb.y;
            *(float2*)(xd + (size_t)n0 * H + nt * 8 + 2 * tig) = make_float2(f0, f1);
            *(float2*)(xd + (size_t)n1 * H + nt * 8 + 2 * tig) = make_float2(f2, f3);
            __nv_bfloat16 h0, l0, h1, l1, h2, l2, h3, l3;
            bf16_split(f0, h0, l0); bf16_split(f1, h1, l1);
            bf16_split(f2, h2, l2); bf16_split(f3, h3, l3);
            g_xh[n0 * 32 + nt * 4 + tig] = pack_bf2(h0, h1);
            g_xl[n0 * 32 + nt * 4 + tig] = pack_bf2(l0, l1);
            g_xh[n1 * 32 + nt * 4 + tig] = pack_bf2(h2, h3);
            g_xl[n1 * 32 + nt * 4 + tig] = pack_bf2(l2, l3);
        }
        __syncwarp();
    }
}

// ============================================================
// k_enc_edge_mma: writes e split in tiled (LDSM-ready) layout
// ============================================================
#define EBH 0
#define EBL 9216
#define EBIAS 18432
#define EA 18944
#define ENC_SMEM (18944 + 8 * 4608)

__global__ void __launch_bounds__(256) k_enc_edge_mma(const float* __restrict__ ef,
        const float* __restrict__ W, const float* __restrict__ b) {
    extern __shared__ char sm[];
    const uint32_t smb = smem_u32(sm);
    int tid = threadIdx.x, lane = tid & 31, wid = tid >> 5;

    for (int i = tid; i < 64 * 64; i += blockDim.x) {
        int k = i >> 6, n = i & 63;
        __nv_bfloat16 h, l; bf16_split(W[i], h, l);
        ((__nv_bfloat16*)(sm + EBH))[n * 72 + k] = h;
        ((__nv_bfloat16*)(sm + EBL))[n * 72 + k] = l;
    }
    if (tid < 64) ((float*)(sm + EBIAS))[tid] = b[tid];
    __syncthreads();

    const float* bs = (const float*)(sm + EBIAS);
    const int tig = lane & 3;
    const int gi = lane >> 2;
    const uint32_t aRowH = smb + EA + wid * 4608 + (lane & 15) * 144 + (lane & 16);
    const uint32_t aRowL = aRowH + 2304;
    const uint32_t bRow  = ((lane & 7) + ((lane & 16) >> 1));
    const uint32_t bAddrH = smb + EBH + bRow * 144 + (lane & 8) * 2;
    const uint32_t bAddrL = bAddrH + (EBL - EBH);
    char* aRowPtr = sm + EA + wid * 4608;

    int gw = blockIdx.x * 8 + wid;
    int nw = gridDim.x * 8;
    for (int chunk = gw; chunk < NE / 16; chunk += nw) {
        int base16 = chunk * 16;
        #pragma unroll 4
        for (int t = 0; t < 16; t++) {
            float2 v = ((const float2*)(ef + (size_t)(base16 + t) * H))[lane];
            __nv_bfloat16 h0, l0, h1, l1;
            bf16_split(v.x, h0, l0); bf16_split(v.y, h1, l1);
            char* rp = aRowPtr + t * 144;
            ((unsigned*)rp)[lane]          = pack_bf2(h0, h1);
            ((unsigned*)(rp + 2304))[lane] = pack_bf2(l0, l1);
        }
        __syncwarp();

        float acc[8][4];
        #pragma unroll
        for (int n = 0; n < 8; n++)
            #pragma unroll
            for (int j = 0; j < 4; j++) acc[n][j] = 0.f;

        #pragma unroll
        for (int kt = 0; kt < 4; kt++) {
            uint32_t ah[4], al[4];
            LDSM4(ah, aRowH + kt * 32);
            LDSM4(al, aRowL + kt * 32);
            #pragma unroll
            for (int ng = 0; ng < 4; ng++) {
                uint32_t bh[4], bl[4];
                LDSM4(bh, bAddrH + ng * 16 * 144 + kt * 32);
                LDSM4(bl, bAddrL + ng * 16 * 144 + kt * 32);
                MMA16816(acc[2 * ng],     ah, bh[0], bh[1]);
                MMA16816(acc[2 * ng],     ah, bl[0], bl[1]);
                MMA16816(acc[2 * ng],     al, bh[0], bh[1]);
                MMA16816(acc[2 * ng + 1], ah, bh[2], bh[3]);
                MMA16816(acc[2 * ng + 1], ah, bl[2], bl[3]);
                MMA16816(acc[2 * ng + 1], al, bh[2], bh[3]);
            }
        }

        unsigned* dh = g_eth + (size_t)chunk * 512;
        unsigned* dl = g_etl + (size_t)chunk * 512;
        #pragma unroll
        for (int nt = 0; nt < 8; nt++) {
            float2 bb = *(const float2*)(bs + nt * 8 + 2 * tig);
            float f0 = acc[nt][0] + bb.x, f1 = acc[nt][1] + bb.y;
            float f2 = acc[nt][2] + bb.x, f3 = acc[nt][3] + bb.y;
            __nv_bfloat16 h0, l0, h1, l1, h2, l2, h3, l3;
            bf16_split(f0, h0, l0); bf16_split(f1, h1, l1);
            bf16_split(f2, h2, l2); bf16_split(f3, h3, l3);
            int w0 = gi * 32 + nt * 4 + tig, w1 = (gi + 8) * 32 + nt * 4 + tig;
            dh[w0] = pack_bf2(h0, h1);
            dl[w0] = pack_bf2(l0, l1);
            dh[w1] = pack_bf2(h2, h3);
            dl[w1] = pack_bf2(l2, l3);
        }
        __syncwarp();
    }
}

// ============================================================
// k_enc_node: scalar f32x2 (unchanged)
// ============================================================
__device__ __forceinline__ void ffma2(ull& d, ull a, ull b) {
    asm("fma.rn.f32x2 %0, %1, %2, %0;" : "+l"(d) : "l"(a), "l"(b));
}
__device__ __forceinline__ float fin(ull a, float b) {
    return __uint_as_float((unsigned)a) + __uint_as_float((unsigned)(a >> 32)) + b;
}

__global__ void __launch_bounds__(256) k_enc_node(const float* __restrict__ nf,
        const float* __restrict__ W, const float* __restrict__ b) {
    extern __shared__ float smf[];
    float* Wp   = smf;
    float* winb = Wp + 8320;
    int tid = threadIdx.x;
    for (int i = tid; i < 128 * 64; i += 256) {
        int k = i >> 6, c = i & 63;
        Wp[(c >> 1) * 260 + (k >> 1) * 4 + ((c & 1) << 1) + (k & 1)] = W[i];
    }
    __syncthreads();
    int lane = tid & 31, wid = tid >> 5;
    float2 bb = ((const float2*)b)[lane];
    float* win = winb + wid * 8 * ND;
    const ulonglong2* wl = (const ulonglong2*)(Wp + (size_t)lane * 260);
    int gw = blockIdx.x * 8 + wid;
    int nw = gridDim.x * 8;
    for (int base = gw * 8; base < NN; base += nw * 8) {
        #pragma unroll
        for (int t = 0; t < 8; t++) {
            float4 v = *(const float4*)(nf + (size_t)(base + t) * ND + lane * 4);
            *(float4*)(win + t * ND + lane * 4) = v;
        }
        __syncwarp();
        ull a0[8], a1[8];
        #pragma unroll
        for (int t = 0; t < 8; t++) { a0[t] = 0ull; a1[t] = 0ull; }
        #pragma unroll 4
        for (int c = 0; c < 32; c++) {
            ulonglong2 wA = wl[2 * c];
            ulonglong2 wB = wl[2 * c + 1];
            #pragma unroll
            for (int t = 0; t < 8; t++) {
                ulonglong2 v = ((const ulonglong2*)(win + t * ND))[c];
                ffma2(a0[t], wA.x, v.x); ffma2(a1[t], wA.y, v.x);
                ffma2(a0[t], wB.x, v.y); ffma2(a1[t], wB.y, v.y);
            }
        }
        #pragma unroll
        for (int t = 0; t < 8; t++) {
            float o0 = fin(a0[t], bb.x);
            float o1 = fin(a1[t], bb.y);
            int n = base + t;
            *(float2*)(g_xb[0] + (size_t)n * H + 2 * lane) = make_float2(o0, o1);
            __nv_bfloat16 h0, l0, h1, l1;
            bf16_split(o0, h0, l0); bf16_split(o1, h1, l1);
            g_xh[n * 32 + lane] = pack_bf2(h0, h1);
            g_xl[n * 32 + lane] = pack_bf2(l0, l1);
        }
        __syncwarp();
    }
}

__global__ void k_con(const float* __restrict__ W1, const float* __restrict__ b1,
                      const float* __restrict__ w2, const float* __restrict__ b2,
                      int si, float* __restrict__ out) {
    __shared__ float Ws[H * H];
    __shared__ float bs[H];
    __shared__ float w2s[H];
    __shared__ float xb[8][H];
    __shared__ float b2v;
    int tid = threadIdx.x;
    for (int i = tid; i < H * H; i += blockDim.x) Ws[i] = W1[i];
    if (tid < H) { bs[tid] = b1[tid]; w2s[tid] = w2[tid]; }
    if (tid == 0) b2v = b2[0];
    __syncthreads();
    const float* xs = g_xb[si];
    int lane = tid & 31, wid = tid >> 5;
    int gw = blockIdx.x * 8 + wid;
    int nw = gridDim.x * 8;
    for (int n = gw; n < NN; n += nw) {
        float xv0 = xs[(size_t)n * H + lane];
        float xv1 = xs[(size_t)n * H + lane + 32];
        out[(size_t)n * H + lane]      = xv0;
        out[(size_t)n * H + lane + 32] = xv1;
        xb[wid][lane]      = xv0;
        xb[wid][lane + 32] = xv1;
        __syncwarp();
        float a0 = bs[lane], a1 = bs[lane + 32];
        #pragma unroll 4
        for (int k = 0; k < H; k++) {
            float v = xb[wid][k];
            a0 += v * Ws[k * H + lane];
            a1 += v * Ws[k * H + lane + 32];
        }
        float p = fmaxf(a0, 0.f) * w2s[lane] + fmaxf(a1, 0.f) * w2s[lane + 32];
        #pragma unroll
        for (int o = 16; o; o >>= 1) p += __shfl_xor_sync(0xffffffffu, p, o);
        if (lane == 0)
            out[(size_t)NN * H + n] = 1.f / (1.f + expf(-(p + b2v)));
        __syncwarp();
    }
}

extern "C" void kernel_launch(void* const* d_in, const int* in_sizes, int n_in,
                              void* d_out, int out_size) {
    const float* nf  = (const float*)d_in[0];
    const float* ef  = (const float*)d_in[1];
    const int*   ei  = (const int*)d_in[2];
    const float* enW = (const float*)d_in[3];
    const float* enb = (const float*)d_in[4];
    const float* eeW = (const float*)d_in[5];
    const float* eeb = (const float*)d_in[6];
    const float* mW1 = (const float*)d_in[7];
    const float* mb1 = (const float*)d_in[8];
    const float* mW2 = (const float*)d_in[9];
    const float* mb2 = (const float*)d_in[10];
    const float* uW1 = (const float*)d_in[11];
    const float* ub1 = (const float*)d_in[12];
    const float* uW2 = (const float*)d_in[13];
    const float* ub2 = (const float*)d_in[14];
    const float* cW1 = (const float*)d_in[15];
    const float* cb1 = (const float*)d_in[16];
    const float* cW2 = (const float*)d_in[17];
    const float* cb2 = (const float*)d_in[18];
    float* out = (float*)d_out;

    int dev = 0, smc = 148;
    cudaGetDevice(&dev);
    cudaDeviceGetAttribute(&smc, cudaDevAttrMultiProcessorCount, dev);

    const int ENN_SMEM = (8320 + 8192) * 4;
    cudaFuncSetAttribute(k_pre,          cudaFuncAttributeMaxDynamicSharedMemorySize, PRE_SMEM);
    cudaFuncSetAttribute(k_msg_mma,      cudaFuncAttributeMaxDynamicSharedMemorySize, MSG_SMEM);
    cudaFuncSetAttribute(k_upd_mma,      cudaFuncAttributeMaxDynamicSharedMemorySize, UPD_SMEM);
    cudaFuncSetAttribute(k_enc_edge_mma, cudaFuncAttributeMaxDynamicSharedMemorySize, ENC_SMEM);
    cudaFuncSetAttribute(k_enc_node,     cudaFuncAttributeMaxDynamicSharedMemorySize, ENN_SMEM);

    k_enc_node<<<smc * 2, 256, ENN_SMEM>>>(nf, enW, enb);
    k_enc_edge_mma<<<smc * 2, 256, ENC_SMEM>>>(ef, eeW, eeb);

    int cur = 0;
    for (int l = 0; l < 3; l++) {
        k_pre<<<smc * 2, 256, PRE_SMEM>>>(mW1 + (size_t)l * 192 * H, mb1 + l * H, cur);
        k_msg_mma<<<smc * 2, 256, MSG_SMEM>>>(ei,
                                              mW1 + (size_t)l * 192 * H,
                                              mW2 + (size_t)l * H * H, mb2 + l * H);
        k_upd_mma<<<smc * 2, 256, UPD_SMEM>>>(uW1 + (size_t)l * 128 * H, ub1 + l * H,
                                              uW2 + (size_t)l * H * H,   ub2 + l * H,
                                              cur, 1 - cur);
        cur = 1 - cur;
    }
    k_con<<<1184, 256>>>(cW1, cb1, cW2, cb2, cur, out);
}

// round 9
// speedup vs baseline: 2.9784x; 1.0595x over previous
#include <cuda_runtime.h>
#include <cuda_fp16.h>
#include <math.h>
#include <cstdint>

#define NN 50000
#define NE 800000
#define H  64
#define ND 128

__device__ float g_xb[2][NN * H];
__device__ float g_agg[NN * H];
__device__ float g_ps[NN * H];               // permuted: [node][tig*16 + nt*2 + {0,1}]
__device__ float g_pd[NN * H];
__device__ unsigned g_et[(size_t)NE * 32];   // e fp16, tiled per 16-edge chunk (2KB)
__device__ unsigned g_xf[NN * 32];           // x fp16 (2 cols/word)

typedef unsigned long long ull;

__device__ __forceinline__ uint32_t smem_u32(const void* p) {
    uint32_t a;
    asm("{ .reg .u64 t; cvta.to.shared.u64 t, %1; cvt.u32.u64 %0, t; }" : "=r"(a) : "l"(p));
    return a;
}

#define LDSM4(r, addr) \
    asm volatile("ldmatrix.sync.aligned.m8n8.x4.shared.b16 {%0,%1,%2,%3}, [%4];" \
        : "=r"((r)[0]), "=r"((r)[1]), "=r"((r)[2]), "=r"((r)[3]) : "r"(addr))

#define MMA16816(c, a, b0v, b1v) \
    asm volatile("mma.sync.aligned.m16n8k16.row.col.f32.f16.f16.f32 " \
        "{%0,%1,%2,%3},{%4,%5,%6,%7},{%8,%9},{%0,%1,%2,%3};" \
        : "+f"((c)[0]), "+f"((c)[1]), "+f"((c)[2]), "+f"((c)[3]) \
        : "r"((a)[0]), "r"((a)[1]), "r"((a)[2]), "r"((a)[3]), "r"(b0v), "r"(b1v))

__device__ __forceinline__ void h_split(float v, __half& h, __half& l) {
    h = __float2half_rn(v);
    l = __float2half_rn(v - __half2float(h));
}
__device__ __forceinline__ unsigned pack_h2(float a, float b) {
    __half2 t = __floats2half2_rn(a, b);
    return *reinterpret_cast<unsigned*>(&t);
}
__device__ __forceinline__ unsigned pack_hh(__half a, __half b) {
    __half2 t; t.x = a; t.y = b;
    return *reinterpret_cast<unsigned*>(&t);
}

// ============================================================
// k_pre: Ps = x@W1s + b1 (permuted), Pd = x@W1d (permuted); zeroes g_agg
//   A = x fp16 (single), B = weights split fp16 (2-term)
// ============================================================
#define PBSH 0
#define PBSL 9216
#define PBDH 18432
#define PBDL 27648
#define PBIAS 36864
#define PA 37120
#define PRE_SMEM (37120 + 8 * 2304)

__global__ void __launch_bounds__(256) k_pre(const float* __restrict__ W1,
                                             const float* __restrict__ b1) {
    extern __shared__ char sm[];
    const uint32_t smb = smem_u32(sm);
    int tid = threadIdx.x, lane = tid & 31, wid = tid >> 5;

    for (int i = tid; i < 64 * 64; i += blockDim.x) {
        int k = i >> 6, n = i & 63;
        __half h, l;
        h_split(W1[k * 64 + n], h, l);
        ((__half*)(sm + PBSH))[n * 72 + k] = h;
        ((__half*)(sm + PBSL))[n * 72 + k] = l;
        h_split(W1[(128 + k) * 64 + n], h, l);
        ((__half*)(sm + PBDH))[n * 72 + k] = h;
        ((__half*)(sm + PBDL))[n * 72 + k] = l;
    }
    if (tid < 64) ((float*)(sm + PBIAS))[tid] = b1[tid];
    __syncthreads();

    const float* b1s = (const float*)(sm + PBIAS);
    const int tig = lane & 3, gid = lane >> 2;
    const uint32_t aRow = smb + PA + wid * 2304 + (lane & 15) * 144 + (lane & 16);
    const uint32_t bRow  = ((lane & 7) + ((lane & 16) >> 1));
    const uint32_t bsH = smb + PBSH + bRow * 144 + (lane & 8) * 2;
    const uint32_t bsL = bsH + (PBSL - PBSH);
    const uint32_t bdH = smb + PBDH + bRow * 144 + (lane & 8) * 2;
    const uint32_t bdL = bdH + (PBDL - PBDH);
    char* aRowPtr = sm + PA + wid * 2304;

    int gw = blockIdx.x * 8 + wid;
    int nw = gridDim.x * 8;
    for (int chunk = gw; chunk < NN / 16; chunk += nw) {
        int base16 = chunk * 16;
        #pragma unroll 4
        for (int t = 0; t < 16; t++)
            ((unsigned*)(aRowPtr + t * 144))[lane] = g_xf[(base16 + t) * 32 + lane];
        __syncwarp();

        float as[8][4], ad[8][4];
        #pragma unroll
        for (int n = 0; n < 8; n++)
            #pragma unroll
            for (int j = 0; j < 4; j++) { as[n][j] = 0.f; ad[n][j] = 0.f; }

        #pragma unroll
        for (int kt = 0; kt < 4; kt++) {
            uint32_t ah[4];
            LDSM4(ah, aRow + kt * 32);
            #pragma unroll
            for (int ng = 0; ng < 4; ng++) {
                uint32_t bh[4], bl[4];
                LDSM4(bh, bsH + ng * 16 * 144 + kt * 32);
                LDSM4(bl, bsL + ng * 16 * 144 + kt * 32);
                MMA16816(as[2 * ng],     ah, bh[0], bh[1]);
                MMA16816(as[2 * ng],     ah, bl[0], bl[1]);
                MMA16816(as[2 * ng + 1], ah, bh[2], bh[3]);
                MMA16816(as[2 * ng + 1], ah, bl[2], bl[3]);
                LDSM4(bh, bdH + ng * 16 * 144 + kt * 32);
                LDSM4(bl, bdL + ng * 16 * 144 + kt * 32);
                MMA16816(ad[2 * ng],     ah, bh[0], bh[1]);
                MMA16816(ad[2 * ng],     ah, bl[0], bl[1]);
                MMA16816(ad[2 * ng + 1], ah, bh[2], bh[3]);
                MMA16816(ad[2 * ng + 1], ah, bl[2], bl[3]);
            }
        }

        int n0 = base16 + gid, n1 = base16 + gid + 8;
        #pragma unroll
        for (int nt = 0; nt < 8; nt++) {
            float2 bb = *(const float2*)(b1s + nt * 8 + 2 * tig);
            int c = nt * 8 + 2 * tig;
            int pc = tig * 16 + nt * 2;
            *(float2*)(g_ps + (size_t)n0 * H + pc) = make_float2(as[nt][0] + bb.x, as[nt][1] + bb.y);
            *(float2*)(g_ps + (size_t)n1 * H + pc) = make_float2(as[nt][2] + bb.x, as[nt][3] + bb.y);
            *(float2*)(g_pd + (size_t)n0 * H + pc) = make_float2(ad[nt][0], ad[nt][1]);
            *(float2*)(g_pd + (size_t)n1 * H + pc) = make_float2(ad[nt][2], ad[nt][3]);
            *(float2*)(g_agg + (size_t)n0 * H + c) = make_float2(0.f, 0.f);
            *(float2*)(g_agg + (size_t)n1 * H + c) = make_float2(0.f, 0.f);
        }
        __syncwarp();
    }
}

// ============================================================
// k_msg_mma: fp16 2-term, cp.async double-buffered e
// ============================================================
#define MB1H 0
#define MB1L 9216
#define MB2H 18432
#define MB2L 27648
#define MBIAS 36864
#define MA 37120
#define MSG_SMEM (37120 + 8 * 4608)   // 73984 -> 2 CTA/SM

__global__ void __launch_bounds__(256, 2) k_msg_mma(const int* __restrict__ ei,
        const float* __restrict__ W1, const float* __restrict__ W2,
        const float* __restrict__ b2) {
    extern __shared__ char sm[];
    const uint32_t smb = smem_u32(sm);
    int tid = threadIdx.x, lane = tid & 31, wid = tid >> 5;

    for (int i = tid; i < 64 * 64; i += blockDim.x) {
        int k = i >> 6, n = i & 63;
        __half h, l;
        h_split(W1[(64 + k) * 64 + n], h, l);
        ((__half*)(sm + MB1H))[n * 72 + k] = h;
        ((__half*)(sm + MB1L))[n * 72 + k] = l;
        h_split(W2[k * 64 + n], h, l);
        ((__half*)(sm + MB2H))[n * 72 + k] = h;
        ((__half*)(sm + MB2L))[n * 72 + k] = l;
    }
    if (tid < 64) ((float*)(sm + MBIAS))[tid] = b2[tid];
    __syncthreads();

    const float* b2s = (const float*)(sm + MBIAS);
    const int tig = lane & 3, gid = lane >> 2;
    const uint32_t bRow  = ((lane & 7) + ((lane & 16) >> 1));
    const uint32_t b1H = smb + MB1H + bRow * 144 + (lane & 8) * 2;
    const uint32_t b1L = b1H + (MB1L - MB1H);
    const uint32_t b2H = smb + MB2H + bRow * 144 + (lane & 8) * 2;
    const uint32_t b2L = b2H + (MB2L - MB2H);
    const uint32_t abuf0 = smb + MA + wid * 4608;

    const int NCH = NE / 16;
    int gw = blockIdx.x * 8 + wid;
    int nw = gridDim.x * 8;

    auto issue_e = [&](int ch, int b) {
        const char* ge = ((const char*)g_et) + (size_t)ch * 2048;
        uint32_t ab = abuf0 + b * 2304;
        #pragma unroll
        for (int j = 0; j < 2; j++) {
            int g = j * 1024 + lane * 32;
            // two 16B segs per lane, contiguous 32B
            uint32_t da = ab + (g >> 7) * 144 + (g & 127);
            asm volatile("cp.async.cg.shared.global [%0], [%1], 16;" :: "r"(da), "l"(ge + g) : "memory");
            int g2 = g + 16;
            uint32_t da2 = ab + (g2 >> 7) * 144 + (g2 & 127);
            asm volatile("cp.async.cg.shared.global [%0], [%1], 16;" :: "r"(da2), "l"(ge + g2) : "memory");
        }
    };

    int chunk = gw, buf = 0;
    if (chunk < NCH) issue_e(chunk, 0);
    asm volatile("cp.async.commit_group;" ::: "memory");

    for (; chunk < NCH; chunk += nw) {
        int nxt = chunk + nw;
        if (nxt < NCH) issue_e(nxt, buf ^ 1);
        asm volatile("cp.async.commit_group;" ::: "memory");

        int base16 = chunk * 16;
        int s = 0, d = 0;
        if (lane < 16) { s = ei[base16 + lane]; d = ei[NE + base16 + lane]; }
        int s0 = __shfl_sync(0xffffffffu, s, gid), s1 = __shfl_sync(0xffffffffu, s, gid + 8);
        int d0 = __shfl_sync(0xffffffffu, d, gid), d1 = __shfl_sync(0xffffffffu, d, gid + 8);

        float4 P0[4], P1[4], Q0[4], Q1[4];
        {
            const float4* a0p = (const float4*)(g_ps + (size_t)s0 * H + tig * 16);
            const float4* a1p = (const float4*)(g_ps + (size_t)s1 * H + tig * 16);
            const float4* c0p = (const float4*)(g_pd + (size_t)d0 * H + tig * 16);
            const float4* c1p = (const float4*)(g_pd + (size_t)d1 * H + tig * 16);
            #pragma unroll
            for (int m = 0; m < 4; m++) {
                P0[m] = __ldg(a0p + m); P1[m] = __ldg(a1p + m);
                Q0[m] = __ldg(c0p + m); Q1[m] = __ldg(c1p + m);
            }
        }

        asm volatile("cp.async.wait_group 1;" ::: "memory");
        __syncwarp();

        const uint32_t aRow = abuf0 + buf * 2304 + (lane & 15) * 144 + (lane & 16);

        // layer 1 (e-term): K=64, fp16 2-term
        float acc[8][4];
        #pragma unroll
        for (int n = 0; n < 8; n++)
            #pragma unroll
            for (int j = 0; j < 4; j++) acc[n][j] = 0.f;

        #pragma unroll
        for (int kt = 0; kt < 4; kt++) {
            uint32_t ah[4];
            LDSM4(ah, aRow + kt * 32);
            #pragma unroll
            for (int ng = 0; ng < 4; ng++) {
                uint32_t bh[4], bl[4];
                LDSM4(bh, b1H + ng * 16 * 144 + kt * 32);
                LDSM4(bl, b1L + ng * 16 * 144 + kt * 32);
                MMA16816(acc[2 * ng],     ah, bh[0], bh[1]);
                MMA16816(acc[2 * ng],     ah, bl[0], bl[1]);
                MMA16816(acc[2 * ng + 1], ah, bh[2], bh[3]);
                MMA16816(acc[2 * ng + 1], ah, bl[2], bl[3]);
            }
        }

        // layer 2 fused per kt
        float acc2[8][4];
        #pragma unroll
        for (int n = 0; n < 8; n++)
            #pragma unroll
            for (int j = 0; j < 4; j++) acc2[n][j] = 0.f;

        #pragma unroll
        for (int kt = 0; kt < 4; kt++) {
            uint32_t a2[4];
            #pragma unroll
            for (int j = 0; j < 2; j++) {
                int nt = 2 * kt + j;
                float pa0 = j ? P0[kt].z : P0[kt].x, pa1 = j ? P0[kt].w : P0[kt].y;
                float qa0 = j ? Q0[kt].z : Q0[kt].x, qa1 = j ? Q0[kt].w : Q0[kt].y;
                float pb0 = j ? P1[kt].z : P1[kt].x, pb1 = j ? P1[kt].w : P1[kt].y;
                float qb0 = j ? Q1[kt].z : Q1[kt].x, qb1 = j ? Q1[kt].w : Q1[kt].y;
                float v0 = fmaxf(acc[nt][0] + pa0 + qa0, 0.f);
                float v1 = fmaxf(acc[nt][1] + pa1 + qa1, 0.f);
                float v2 = fmaxf(acc[nt][2] + pb0 + qb0, 0.f);
                float v3 = fmaxf(acc[nt][3] + pb1 + qb1, 0.f);
                a2[2 * j]     = pack_h2(v0, v1);
                a2[2 * j + 1] = pack_h2(v2, v3);
            }
            #pragma unroll
            for (int ng = 0; ng < 4; ng++) {
                uint32_t bh[4], bl[4];
                LDSM4(bh, b2H + ng * 16 * 144 + kt * 32);
                LDSM4(bl, b2L + ng * 16 * 144 + kt * 32);
                MMA16816(acc2[2 * ng],     a2, bh[0], bh[1]);
                MMA16816(acc2[2 * ng],     a2, bl[0], bl[1]);
                MMA16816(acc2[2 * ng + 1], a2, bh[2], bh[3]);
                MMA16816(acc2[2 * ng + 1], a2, bl[2], bl[3]);
            }
        }

        float* plo = g_agg + (size_t)d0 * H + 2 * tig;
        float* phi = g_agg + (size_t)d1 * H + 2 * tig;
        #pragma unroll
        for (int nt = 0; nt < 8; nt++) {
            float2 bb = *(const float2*)(b2s + nt * 8 + 2 * tig);
            float f0 = acc2[nt][0] + bb.x, f1 = acc2[nt][1] + bb.y;
            float f2 = acc2[nt][2] + bb.x, f3 = acc2[nt][3] + bb.y;
            asm volatile("red.global.add.v2.f32 [%0], {%1,%2};"
                :: "l"(plo + nt * 8), "f"(f0), "f"(f1) : "memory");
            asm volatile("red.global.add.v2.f32 [%0], {%1,%2};"
                :: "l"(phi + nt * 8), "f"(f2), "f"(f3) : "memory");
        }
        buf ^= 1;
        __syncwarp();
    }
}

// ============================================================
// k_upd_mma: fp16 2-term; re-zeroes g_agg after reading
// ============================================================
#define UB1H 0
#define UB1L 17408
#define UB2H 34816
#define UB2L 44032
#define UBIAS 53248
#define UA 53760
#define UPD_SMEM (53760 + 8 * 4352)   // 88576 -> 2 CTA/SM

__global__ void __launch_bounds__(256, 2) k_upd_mma(
        const float* __restrict__ W1, const float* __restrict__ b1,
        const float* __restrict__ W2, const float* __restrict__ b2,
        int si, int di) {
    extern __shared__ char sm[];
    const uint32_t smb = smem_u32(sm);
    int tid = threadIdx.x, lane = tid & 31, wid = tid >> 5;

    for (int i = tid; i < 128 * 64; i += blockDim.x) {
        int k = i >> 6, n = i & 63;
        __half h, l; h_split(W1[i], h, l);
        ((__half*)(sm + UB1H))[n * 136 + k] = h;
        ((__half*)(sm + UB1L))[n * 136 + k] = l;
    }
    for (int i = tid; i < 64 * 64; i += blockDim.x) {
        int k = i >> 6, n = i & 63;
        __half h, l; h_split(W2[i], h, l);
        ((__half*)(sm + UB2H))[n * 72 + k] = h;
        ((__half*)(sm + UB2L))[n * 72 + k] = l;
    }
    if (tid < 64) {
        ((float*)(sm + UBIAS))[tid] = b1[tid];
        ((float*)(sm + UBIAS + 256))[tid] = b2[tid];
    }
    __syncthreads();

    const float* b1s = (const float*)(sm + UBIAS);
    const float* b2s = (const float*)(sm + UBIAS + 256);
    float* xd = g_xb[di];

    const int tig = lane & 3, gid = lane >> 2;
    const uint32_t aRow = smb + UA + wid * 4352 + (lane & 15) * 272 + (lane & 16);
    const uint32_t bRow  = ((lane & 7) + ((lane & 16) >> 1));
    const uint32_t b1AddrH = smb + UB1H + bRow * 272 + (lane & 8) * 2;
    const uint32_t b1AddrL = b1AddrH + (UB1L - UB1H);
    const uint32_t b2AddrH = smb + UB2H + bRow * 144 + (lane & 8) * 2;
    const uint32_t b2AddrL = b2AddrH + (UB2L - UB2H);
    char* aRowPtr = sm + UA + wid * 4352;

    int gw = blockIdx.x * 8 + wid;
    int nw = gridDim.x * 8;
    for (int chunk = gw; chunk < NN / 16; chunk += nw) {
        int base16 = chunk * 16;
        #pragma unroll 4
        for (int t = 0; t < 16; t++) {
            int n = base16 + t;
            float2* agp = (float2*)(g_agg + (size_t)n * H) + lane;
            float2 ag = *agp;
            *agp = make_float2(0.f, 0.f);       // re-zero for next layer's scatter
            char* rp = aRowPtr + t * 272;
            ((unsigned*)rp)[lane]         = g_xf[n * 32 + lane];
            ((unsigned*)(rp + 128))[lane] = pack_h2(ag.x, ag.y);
        }
        __syncwarp();

        float acc[8][4];
        #pragma unroll
        for (int n = 0; n < 8; n++)
            #pragma unroll
            for (int j = 0; j < 4; j++) acc[n][j] = 0.f;

        #pragma unroll 2
        for (int kt = 0; kt < 8; kt++) {
            uint32_t ah[4];
            LDSM4(ah, aRow + kt * 32);
            #pragma unroll
            for (int ng = 0; ng < 4; ng++) {
                uint32_t bh[4], bl[4];
                LDSM4(bh, b1AddrH + ng * 16 * 272 + kt * 32);
                LDSM4(bl, b1AddrL + ng * 16 * 272 + kt * 32);
                MMA16816(acc[2 * ng],     ah, bh[0], bh[1]);
                MMA16816(acc[2 * ng],     ah, bl[0], bl[1]);
                MMA16816(acc[2 * ng + 1], ah, bh[2], bh[3]);
                MMA16816(acc[2 * ng + 1], ah, bl[2], bl[3]);
            }
        }

        float acc2[8][4];
        #pragma unroll
        for (int n = 0; n < 8; n++)
            #pragma unroll
            for (int j = 0; j < 4; j++) acc2[n][j] = 0.f;

        #pragma unroll
        for (int kt = 0; kt < 4; kt++) {
            uint32_t a2[4];
            #pragma unroll
            for (int j = 0; j < 2; j++) {
                int nt = kt * 2 + j;
                float2 bb = *(const float2*)(b1s + nt * 8 + 2 * tig);
                float v0 = fmaxf(acc[nt][0] + bb.x, 0.f);
                float v1 = fmaxf(acc[nt][1] + bb.y, 0.f);
                float v2 = fmaxf(acc[nt][2] + bb.x, 0.f);
                float v3 = fmaxf(acc[nt][3] + bb.y, 0.f);
                a2[2 * j]     = pack_h2(v0, v1);
                a2[2 * j + 1] = pack_h2(v2, v3);
            }
            #pragma unroll
            for (int ng = 0; ng < 4; ng++) {
                uint32_t bh[4], bl[4];
                LDSM4(bh, b2AddrH + ng * 16 * 144 + kt * 32);
                LDSM4(bl, b2AddrL + ng * 16 * 144 + kt * 32);
                MMA16816(acc2[2 * ng],     a2, bh[0], bh[1]);
                MMA16816(acc2[2 * ng],     a2, bl[0], bl[1]);
                MMA16816(acc2[2 * ng + 1], a2, bh[2], bh[3]);
                MMA16816(acc2[2 * ng + 1], a2, bl[2], bl[3]);
            }
        }

        int n0 = base16 + gid, n1 = base16 + gid + 8;
        #pragma unroll
        for (int nt = 0; nt < 8; nt++) {
            float2 bb = *(const float2*)(b2s + nt * 8 + 2 * tig);
            float f0 = acc2[nt][0] + bb.x, f1 = acc2[nt][1] + bb.y;
            float f2 = acc2[nt][2] + bb.x, f3 = acc2[nt][3] + bb.y;
            *(float2*)(xd + (size_t)n0 * H + nt * 8 + 2 * tig) = make_float2(f0, f1);
            *(float2*)(xd + (size_t)n1 * H + nt * 8 + 2 * tig) = make_float2(f2, f3);
            g_xf[n0 * 32 + nt * 4 + tig] = pack_h2(f0, f1);
            g_xf[n1 * 32 + nt * 4 + tig] = pack_h2(f2, f3);
        }
        __syncwarp();
    }
}

// ============================================================
// k_enc_edge_mma: fp16 2-term; writes e fp16 in tiled layout
// ============================================================
#define EBH 0
#define EBL 9216
#define EBIAS 18432
#define EA 18688
#define ENC_SMEM (18688 + 8 * 2304)

__global__ void __launch_bounds__(256) k_enc_edge_mma(const float* __restrict__ ef,
        const float* __restrict__ W, const float* __restrict__ b) {
    extern __shared__ char sm[];
    const uint32_t smb = smem_u32(sm);
    int tid = threadIdx.x, lane = tid & 31, wid = tid >> 5;

    for (int i = tid; i < 64 * 64; i += blockDim.x) {
        int k = i >> 6, n = i & 63;
        __half h, l; h_split(W[i], h, l);
        ((__half*)(sm + EBH))[n * 72 + k] = h;
        ((__half*)(sm + EBL))[n * 72 + k] = l;
    }
    if (tid < 64) ((float*)(sm + EBIAS))[tid] = b[tid];
    __syncthreads();

    const float* bs = (const float*)(sm + EBIAS);
    const int tig = lane & 3;
    const int gi = lane >> 2;
    const uint32_t aRow = smb + EA + wid * 2304 + (lane & 15) * 144 + (lane & 16);
    const uint32_t bRow  = ((lane & 7) + ((lane & 16) >> 1));
    const uint32_t bAddrH = smb + EBH + bRow * 144 + (lane & 8) * 2;
    const uint32_t bAddrL = bAddrH + (EBL - EBH);
    char* aRowPtr = sm + EA + wid * 2304;

    int gw = blockIdx.x * 8 + wid;
    int nw = gridDim.x * 8;
    for (int chunk = gw; chunk < NE / 16; chunk += nw) {
        int base16 = chunk * 16;
        #pragma unroll 4
        for (int t = 0; t < 16; t++) {
            float2 v = ((const float2*)(ef + (size_t)(base16 + t) * H))[lane];
            ((unsigned*)(aRowPtr + t * 144))[lane] = pack_h2(v.x, v.y);
        }
        __syncwarp();

        float acc[8][4];
        #pragma unroll
        for (int n = 0; n < 8; n++)
            #pragma unroll
            for (int j = 0; j < 4; j++) acc[n][j] = 0.f;

        #pragma unroll
        for (int kt = 0; kt < 4; kt++) {
            uint32_t ah[4];
            LDSM4(ah, aRow + kt * 32);
            #pragma unroll
            for (int ng = 0; ng < 4; ng++) {
                uint32_t bh[4], bl[4];
                LDSM4(bh, bAddrH + ng * 16 * 144 + kt * 32);
                LDSM4(bl, bAddrL + ng * 16 * 144 + kt * 32);
                MMA16816(acc[2 * ng],     ah, bh[0], bh[1]);
                MMA16816(acc[2 * ng],     ah, bl[0], bl[1]);
                MMA16816(acc[2 * ng + 1], ah, bh[2], bh[3]);
                MMA16816(acc[2 * ng + 1], ah, bl[2], bl[3]);
            }
        }

        unsigned* de = g_et + (size_t)chunk * 512;
        #pragma unroll
        for (int nt = 0; nt < 8; nt++) {
            float2 bb = *(const float2*)(bs + nt * 8 + 2 * tig);
            float f0 = acc[nt][0] + bb.x, f1 = acc[nt][1] + bb.y;
            float f2 = acc[nt][2] + bb.x, f3 = acc[nt][3] + bb.y;
            de[gi * 32 + nt * 4 + tig]       = pack_h2(f0, f1);
            de[(gi + 8) * 32 + nt * 4 + tig] = pack_h2(f2, f3);
        }
        __syncwarp();
    }
}

// ============================================================
// k_enc_node: scalar f32x2; writes fp32 x + fp16 x
// ============================================================
__device__ __forceinline__ void ffma2(ull& d, ull a, ull b) {
    asm("fma.rn.f32x2 %0, %1, %2, %0;" : "+l"(d) : "l"(a), "l"(b));
}
__device__ __forceinline__ float fin(ull a, float b) {
    return __uint_as_float((unsigned)a) + __uint_as_float((unsigned)(a >> 32)) + b;
}

__global__ void __launch_bounds__(256) k_enc_node(const float* __restrict__ nf,
        const float* __restrict__ W, const float* __restrict__ b) {
    extern __shared__ float smf[];
    float* Wp   = smf;
    float* winb = Wp + 8320;
    int tid = threadIdx.x;
    for (int i = tid; i < 128 * 64; i += 256) {
        int k = i >> 6, c = i & 63;
        Wp[(c >> 1) * 260 + (k >> 1) * 4 + ((c & 1) << 1) + (k & 1)] = W[i];
    }
    __syncthreads();
    int lane = tid & 31, wid = tid >> 5;
    float2 bb = ((const float2*)b)[lane];
    float* win = winb + wid * 8 * ND;
    const ulonglong2* wl = (const ulonglong2*)(Wp + (size_t)lane * 260);
    int gw = blockIdx.x * 8 + wid;
    int nw = gridDim.x * 8;
    for (int base = gw * 8; base < NN; base += nw * 8) {
        #pragma unroll
        for (int t = 0; t < 8; t++) {
            float4 v = *(const float4*)(nf + (size_t)(base + t) * ND + lane * 4);
            *(float4*)(win + t * ND + lane * 4) = v;
        }
        __syncwarp();
        ull a0[8], a1[8];
        #pragma unroll
        for (int t = 0; t < 8; t++) { a0[t] = 0ull; a1[t] = 0ull; }
        #pragma unroll 4
        for (int c = 0; c < 32; c++) {
            ulonglong2 wA = wl[2 * c];
            ulonglong2 wB = wl[2 * c + 1];
            #pragma unroll
            for (int t = 0; t < 8; t++) {
                ulonglong2 v = ((const ulonglong2*)(win + t * ND))[c];
                ffma2(a0[t], wA.x, v.x); ffma2(a1[t], wA.y, v.x);
                ffma2(a0[t], wB.x, v.y); ffma2(a1[t], wB.y, v.y);
            }
        }
        #pragma unroll
        for (int t = 0; t < 8; t++) {
            float o0 = fin(a0[t], bb.x);
            float o1 = fin(a1[t], bb.y);
            int n = base + t;
            *(float2*)(g_xb[0] + (size_t)n * H + 2 * lane) = make_float2(o0, o1);
            g_xf[n * 32 + lane] = pack_h2(o0, o1);
        }
        __syncwarp();
    }
}

__global__ void k_con(const float* __restrict__ W1, const float* __restrict__ b1,
                      const float* __restrict__ w2, const float* __restrict__ b2,
                      int si, float* __restrict__ out) {
    __shared__ float Ws[H * H];
    __shared__ float bs[H];
    __shared__ float w2s[H];
    __shared__ float xb[8][H];
    __shared__ float b2v;
    int tid = threadIdx.x;
    for (int i = tid; i < H * H; i += blockDim.x) Ws[i] = W1[i];
    if (tid < H) { bs[tid] = b1[tid]; w2s[tid] = w2[tid]; }
    if (tid == 0) b2v = b2[0];
    __syncthreads();
    const float* xs = g_xb[si];
    int lane = tid & 31, wid = tid >> 5;
    int gw = blockIdx.x * 8 + wid;
    int nw = gridDim.x * 8;
    for (int n = gw; n < NN; n += nw) {
        float xv0 = xs[(size_t)n * H + lane];
        float xv1 = xs[(size_t)n * H + lane + 32];
        out[(size_t)n * H + lane]      = xv0;
        out[(size_t)n * H + lane + 32] = xv1;
        xb[wid][lane]      = xv0;
        xb[wid][lane + 32] = xv1;
        __syncwarp();
        float a0 = bs[lane], a1 = bs[lane + 32];
        #pragma unroll 4
        for (int k = 0; k < H; k++) {
            float v = xb[wid][k];
            a0 += v * Ws[k * H + lane];
            a1 += v * Ws[k * H + lane + 32];
        }
        float p = fmaxf(a0, 0.f) * w2s[lane] + fmaxf(a1, 0.f) * w2s[lane + 32];
        #pragma unroll
        for (int o = 16; o; o >>= 1) p += __shfl_xor_sync(0xffffffffu, p, o);
        if (lane == 0)
            out[(size_t)NN * H + n] = 1.f / (1.f + expf(-(p + b2v)));
        __syncwarp();
    }
}

extern "C" void kernel_launch(void* const* d_in, const int* in_sizes, int n_in,
                              void* d_out, int out_size) {
    const float* nf  = (const float*)d_in[0];
    const float* ef  = (const float*)d_in[1];
    const int*   ei  = (const int*)d_in[2];
    const float* enW = (const float*)d_in[3];
    const float* enb = (const float*)d_in[4];
    const float* eeW = (const float*)d_in[5];
    const float* eeb = (const float*)d_in[6];
    const float* mW1 = (const float*)d_in[7];
    const float* mb1 = (const float*)d_in[8];
    const float* mW2 = (const float*)d_in[9];
    const float* mb2 = (const float*)d_in[10];
    const float* uW1 = (const float*)d_in[11];
    const float* ub1 = (const float*)d_in[12];
    const float* uW2 = (const float*)d_in[13];
    const float* ub2 = (const float*)d_in[14];
    const float* cW1 = (const float*)d_in[15];
    const float* cb1 = (const float*)d_in[16];
    const float* cW2 = (const float*)d_in[17];
    const float* cb2 = (const float*)d_in[18];
    float* out = (float*)d_out;

    int dev = 0, smc = 148;
    cudaGetDevice(&dev);
    cudaDeviceGetAttribute(&smc, cudaDevAttrMultiProcessorCount, dev);

    const int ENN_SMEM = (8320 + 8192) * 4;
    cudaFuncSetAttribute(k_pre,          cudaFuncAttributeMaxDynamicSharedMemorySize, PRE_SMEM);
    cudaFuncSetAttribute(k_msg_mma,      cudaFuncAttributeMaxDynamicSharedMemorySize, MSG_SMEM);
    cudaFuncSetAttribute(k_upd_mma,      cudaFuncAttributeMaxDynamicSharedMemorySize, UPD_SMEM);
    cudaFuncSetAttribute(k_enc_edge_mma, cudaFuncAttributeMaxDynamicSharedMemorySize, ENC_SMEM);
    cudaFuncSetAttribute(k_enc_node,     cudaFuncAttributeMaxDynamicSharedMemorySize, ENN_SMEM);

    k_enc_node<<<smc * 2, 256, ENN_SMEM>>>(nf, enW, enb);
    k_enc_edge_mma<<<smc * 2, 256, ENC_SMEM>>>(ef, eeW, eeb);

    int cur = 0;
    for (int l = 0; l < 3; l++) {
        k_pre<<<smc * 2, 256, PRE_SMEM>>>(mW1 + (size_t)l * 192 * H, mb1 + l * H);
        k_msg_mma<<<smc * 2, 256, MSG_SMEM>>>(ei,
                                              mW1 + (size_t)l * 192 * H,
                                              mW2 + (size_t)l * H * H, mb2 + l * H);
        k_upd_mma<<<smc * 2, 256, UPD_SMEM>>>(uW1 + (size_t)l * 128 * H, ub1 + l * H,
                                              uW2 + (size_t)l * H * H,   ub2 + l * H,
                                              cur, 1 - cur);
        cur = 1 - cur;
    }
    k_con<<<1184, 256>>>(cW1, cb1, cW2, cb2, cur, out);
}

// round 10
// speedup vs baseline: 3.1621x; 1.0617x over previous
#include <cuda_runtime.h>
#include <cuda_fp16.h>
#include <math.h>
#include <cstdint>

#define NN 50000
#define NE 800000
#define H  64
#define ND 128

__device__ float g_xb[2][NN * H];
__device__ float g_agg[NN * H];              // PERMUTED cols: [m][tig][e][j] (see k_msg epi)
__device__ float g_ps[NN * H];               // permuted: [node][tig*16 + nt*2 + {0,1}]
__device__ float g_pd[NN * H];
__device__ unsigned g_et[(size_t)NE * 32];   // e fp16 in MMA A-fragment order per 16-edge chunk
__device__ unsigned g_xf[NN * 32];           // x fp16 (2 cols/word)

typedef unsigned long long ull;

__device__ __forceinline__ uint32_t smem_u32(const void* p) {
    uint32_t a;
    asm("{ .reg .u64 t; cvta.to.shared.u64 t, %1; cvt.u32.u64 %0, t; }" : "=r"(a) : "l"(p));
    return a;
}

#define LDSM4(r, addr) \
    asm volatile("ldmatrix.sync.aligned.m8n8.x4.shared.b16 {%0,%1,%2,%3}, [%4];" \
        : "=r"((r)[0]), "=r"((r)[1]), "=r"((r)[2]), "=r"((r)[3]) : "r"(addr))

#define MMA16816(c, a, b0v, b1v) \
    asm volatile("mma.sync.aligned.m16n8k16.row.col.f32.f16.f16.f32 " \
        "{%0,%1,%2,%3},{%4,%5,%6,%7},{%8,%9},{%0,%1,%2,%3};" \
        : "+f"((c)[0]), "+f"((c)[1]), "+f"((c)[2]), "+f"((c)[3]) \
        : "r"((a)[0]), "r"((a)[1]), "r"((a)[2]), "r"((a)[3]), "r"(b0v), "r"(b1v))

__device__ __forceinline__ void h_split(float v, __half& h, __half& l) {
    h = __float2half_rn(v);
    l = __float2half_rn(v - __half2float(h));
}
__device__ __forceinline__ unsigned pack_h2(float a, float b) {
    __half2 t = __floats2half2_rn(a, b);
    return *reinterpret_cast<unsigned*>(&t);
}

// ============================================================
// k_pre: Ps = x@W1s + b1 (permuted), Pd = x@W1d; zeroes g_agg
// ============================================================
#define PBSH 0
#define PBSL 9216
#define PBDH 18432
#define PBDL 27648
#define PBIAS 36864
#define PA 37120
#define PRE_SMEM (37120 + 8 * 2304)

__global__ void __launch_bounds__(256) k_pre(const float* __restrict__ W1,
                                             const float* __restrict__ b1) {
    extern __shared__ char sm[];
    const uint32_t smb = smem_u32(sm);
    int tid = threadIdx.x, lane = tid & 31, wid = tid >> 5;

    for (int i = tid; i < 64 * 64; i += blockDim.x) {
        int k = i >> 6, n = i & 63;
        __half h, l;
        h_split(W1[k * 64 + n], h, l);
        ((__half*)(sm + PBSH))[n * 72 + k] = h;
        ((__half*)(sm + PBSL))[n * 72 + k] = l;
        h_split(W1[(128 + k) * 64 + n], h, l);
        ((__half*)(sm + PBDH))[n * 72 + k] = h;
        ((__half*)(sm + PBDL))[n * 72 + k] = l;
    }
    if (tid < 64) ((float*)(sm + PBIAS))[tid] = b1[tid];
    __syncthreads();

    const float* b1s = (const float*)(sm + PBIAS);
    const int tig = lane & 3, gid = lane >> 2;
    const uint32_t aRow = smb + PA + wid * 2304 + (lane & 15) * 144 + (lane & 16);
    const uint32_t bRow  = ((lane & 7) + ((lane & 16) >> 1));
    const uint32_t bsH = smb + PBSH + bRow * 144 + (lane & 8) * 2;
    const uint32_t bsL = bsH + (PBSL - PBSH);
    const uint32_t bdH = smb + PBDH + bRow * 144 + (lane & 8) * 2;
    const uint32_t bdL = bdH + (PBDL - PBDH);
    char* aRowPtr = sm + PA + wid * 2304;

    int gw = blockIdx.x * 8 + wid;
    int nw = gridDim.x * 8;
    for (int chunk = gw; chunk < NN / 16; chunk += nw) {
        int base16 = chunk * 16;
        #pragma unroll 4
        for (int t = 0; t < 16; t++)
            ((unsigned*)(aRowPtr + t * 144))[lane] = g_xf[(base16 + t) * 32 + lane];
        __syncwarp();

        float as[8][4], ad[8][4];
        #pragma unroll
        for (int n = 0; n < 8; n++)
            #pragma unroll
            for (int j = 0; j < 4; j++) { as[n][j] = 0.f; ad[n][j] = 0.f; }

        #pragma unroll
        for (int kt = 0; kt < 4; kt++) {
            uint32_t ah[4];
            LDSM4(ah, aRow + kt * 32);
            #pragma unroll
            for (int ng = 0; ng < 4; ng++) {
                uint32_t bh[4], bl[4];
                LDSM4(bh, bsH + ng * 16 * 144 + kt * 32);
                LDSM4(bl, bsL + ng * 16 * 144 + kt * 32);
                MMA16816(as[2 * ng],     ah, bh[0], bh[1]);
                MMA16816(as[2 * ng],     ah, bl[0], bl[1]);
                MMA16816(as[2 * ng + 1], ah, bh[2], bh[3]);
                MMA16816(as[2 * ng + 1], ah, bl[2], bl[3]);
                LDSM4(bh, bdH + ng * 16 * 144 + kt * 32);
                LDSM4(bl, bdL + ng * 16 * 144 + kt * 32);
                MMA16816(ad[2 * ng],     ah, bh[0], bh[1]);
                MMA16816(ad[2 * ng],     ah, bl[0], bl[1]);
                MMA16816(ad[2 * ng + 1], ah, bh[2], bh[3]);
                MMA16816(ad[2 * ng + 1], ah, bl[2], bl[3]);
            }
        }

        int n0 = base16 + gid, n1 = base16 + gid + 8;
        #pragma unroll
        for (int nt = 0; nt < 8; nt++) {
            float2 bb = *(const float2*)(b1s + nt * 8 + 2 * tig);
            int c = nt * 8 + 2 * tig;
            int pc = tig * 16 + nt * 2;
            *(float2*)(g_ps + (size_t)n0 * H + pc) = make_float2(as[nt][0] + bb.x, as[nt][1] + bb.y);
            *(float2*)(g_ps + (size_t)n1 * H + pc) = make_float2(as[nt][2] + bb.x, as[nt][3] + bb.y);
            *(float2*)(g_pd + (size_t)n0 * H + pc) = make_float2(ad[nt][0], ad[nt][1]);
            *(float2*)(g_pd + (size_t)n1 * H + pc) = make_float2(ad[nt][2], ad[nt][3]);
            *(float2*)(g_agg + (size_t)n0 * H + c) = make_float2(0.f, 0.f);
            *(float2*)(g_agg + (size_t)n1 * H + c) = make_float2(0.f, 0.f);
        }
        __syncwarp();
    }
}

// ============================================================
// k_msg_mma: A from global (fragment order), red.v4 epilogue
// ============================================================
#define MB1H 0
#define MB1L 9216
#define MB2H 18432
#define MB2L 27648
#define MBIAS 36864
#define MSG_SMEM 37376

__global__ void __launch_bounds__(256, 2) k_msg_mma(const int* __restrict__ ei,
        const float* __restrict__ W1, const float* __restrict__ W2,
        const float* __restrict__ b2) {
    extern __shared__ char sm[];
    const uint32_t smb = smem_u32(sm);
    int tid = threadIdx.x, lane = tid & 31, wid = tid >> 5;

    for (int i = tid; i < 64 * 64; i += blockDim.x) {
        int k = i >> 6, n = i & 63;
        __half h, l;
        h_split(W1[(64 + k) * 64 + n], h, l);
        ((__half*)(sm + MB1H))[n * 72 + k] = h;
        ((__half*)(sm + MB1L))[n * 72 + k] = l;
        h_split(W2[k * 64 + n], h, l);
        ((__half*)(sm + MB2H))[n * 72 + k] = h;
        ((__half*)(sm + MB2L))[n * 72 + k] = l;
    }
    if (tid < 64) ((float*)(sm + MBIAS))[tid] = b2[tid];
    __syncthreads();

    const float* b2s = (const float*)(sm + MBIAS);
    const int tig = lane & 3, gid = lane >> 2;
    const uint32_t bRow  = ((lane & 7) + ((lane & 16) >> 1));
    const uint32_t b1H = smb + MB1H + bRow * 144 + (lane & 8) * 2;
    const uint32_t b1L = b1H + (MB1L - MB1H);
    const uint32_t b2H = smb + MB2H + bRow * 144 + (lane & 8) * 2;
    const uint32_t b2L = b2H + (MB2L - MB2H);

    const uint4* et4 = (const uint4*)g_et;
    const int NCH = NE / 16;
    int gw = blockIdx.x * 8 + wid;
    int nw = gridDim.x * 8;

    for (int chunk = gw; chunk < NCH; chunk += nw) {
        int base16 = chunk * 16;
        int s = 0, d = 0;
        if (lane < 16) { s = ei[base16 + lane]; d = ei[NE + base16 + lane]; }
        int s0 = __shfl_sync(0xffffffffu, s, gid), s1 = __shfl_sync(0xffffffffu, s, gid + 8);
        int d0 = __shfl_sync(0xffffffffu, d, gid), d1 = __shfl_sync(0xffffffffu, d, gid + 8);

        // A fragments straight from global (4 x LDG.128)
        uint4 A[4];
        #pragma unroll
        for (int kt = 0; kt < 4; kt++)
            A[kt] = __ldg(et4 + (size_t)chunk * 128 + kt * 32 + lane);

        // layer 1 (e-term): K=64, fp16 2-term
        float acc[8][4];
        #pragma unroll
        for (int n = 0; n < 8; n++)
            #pragma unroll
            for (int j = 0; j < 4; j++) acc[n][j] = 0.f;

        #pragma unroll
        for (int kt = 0; kt < 4; kt++) {
            uint32_t ah[4] = {A[kt].x, A[kt].y, A[kt].z, A[kt].w};
            #pragma unroll
            for (int ng = 0; ng < 4; ng++) {
                uint32_t bh[4], bl[4];
                LDSM4(bh, b1H + ng * 16 * 144 + kt * 32);
                LDSM4(bl, b1L + ng * 16 * 144 + kt * 32);
                MMA16816(acc[2 * ng],     ah, bh[0], bh[1]);
                MMA16816(acc[2 * ng],     ah, bl[0], bl[1]);
                MMA16816(acc[2 * ng + 1], ah, bh[2], bh[3]);
                MMA16816(acc[2 * ng + 1], ah, bl[2], bl[3]);
            }
        }

        // Ps/Pd gathers (permuted; 64B contiguous per lane per row)
        float4 P0[4], P1[4], Q0[4], Q1[4];
        {
            const float4* a0p = (const float4*)(g_ps + (size_t)s0 * H + tig * 16);
            const float4* a1p = (const float4*)(g_ps + (size_t)s1 * H + tig * 16);
            const float4* c0p = (const float4*)(g_pd + (size_t)d0 * H + tig * 16);
            const float4* c1p = (const float4*)(g_pd + (size_t)d1 * H + tig * 16);
            #pragma unroll
            for (int m = 0; m < 4; m++) {
                P0[m] = __ldg(a0p + m); P1[m] = __ldg(a1p + m);
                Q0[m] = __ldg(c0p + m); Q1[m] = __ldg(c1p + m);
            }
        }

        // layer 2 fused per kt
        float acc2[8][4];
        #pragma unroll
        for (int n = 0; n < 8; n++)
            #pragma unroll
            for (int j = 0; j < 4; j++) acc2[n][j] = 0.f;

        #pragma unroll
        for (int kt = 0; kt < 4; kt++) {
            uint32_t a2[4];
            #pragma unroll
            for (int j = 0; j < 2; j++) {
                int nt = 2 * kt + j;
                float pa0 = j ? P0[kt].z : P0[kt].x, pa1 = j ? P0[kt].w : P0[kt].y;
                float qa0 = j ? Q0[kt].z : Q0[kt].x, qa1 = j ? Q0[kt].w : Q0[kt].y;
                float pb0 = j ? P1[kt].z : P1[kt].x, pb1 = j ? P1[kt].w : P1[kt].y;
                float qb0 = j ? Q1[kt].z : Q1[kt].x, qb1 = j ? Q1[kt].w : Q1[kt].y;
                float v0 = fmaxf(acc[nt][0] + pa0 + qa0, 0.f);
                float v1 = fmaxf(acc[nt][1] + pa1 + qa1, 0.f);
                float v2 = fmaxf(acc[nt][2] + pb0 + qb0, 0.f);
                float v3 = fmaxf(acc[nt][3] + pb1 + qb1, 0.f);
                a2[2 * j]     = pack_h2(v0, v1);
                a2[2 * j + 1] = pack_h2(v2, v3);
            }
            #pragma unroll
            for (int ng = 0; ng < 4; ng++) {
                uint32_t bh[4], bl[4];
                LDSM4(bh, b2H + ng * 16 * 144 + kt * 32);
                LDSM4(bl, b2L + ng * 16 * 144 + kt * 32);
                MMA16816(acc2[2 * ng],     a2, bh[0], bh[1]);
                MMA16816(acc2[2 * ng],     a2, bl[0], bl[1]);
                MMA16816(acc2[2 * ng + 1], a2, bh[2], bh[3]);
                MMA16816(acc2[2 * ng + 1], a2, bl[2], bl[3]);
            }
        }

        // epilogue: permuted agg cols -> red.v4
        float* plo = g_agg + (size_t)d0 * H + tig * 4;
        float* phi = g_agg + (size_t)d1 * H + tig * 4;
        #pragma unroll
        for (int m = 0; m < 4; m++) {
            float2 be = *(const float2*)(b2s + (2 * m) * 8 + 2 * tig);
            float2 bo = *(const float2*)(b2s + (2 * m + 1) * 8 + 2 * tig);
            float e0 = acc2[2 * m][0] + be.x, e1 = acc2[2 * m][1] + be.y;
            float o0 = acc2[2 * m + 1][0] + bo.x, o1 = acc2[2 * m + 1][1] + bo.y;
            asm volatile("red.global.add.v4.f32 [%0], {%1,%2,%3,%4};"
                :: "l"(plo + m * 16), "f"(e0), "f"(e1), "f"(o0), "f"(o1) : "memory");
            float e2 = acc2[2 * m][2] + be.x, e3 = acc2[2 * m][3] + be.y;
            float o2 = acc2[2 * m + 1][2] + bo.x, o3 = acc2[2 * m + 1][3] + bo.y;
            asm volatile("red.global.add.v4.f32 [%0], {%1,%2,%3,%4};"
                :: "l"(phi + m * 16), "f"(e2), "f"(e3), "f"(o2), "f"(o3) : "memory");
        }
        __syncwarp();
    }
}

// ============================================================
// k_upd_mma: reads agg with inverse permutation; re-zeroes agg
// ============================================================
#define UB1H 0
#define UB1L 17408
#define UB2H 34816
#define UB2L 44032
#define UBIAS 53248
#define UA 53760
#define UPD_SMEM (53760 + 8 * 4352)

__global__ void __launch_bounds__(256, 2) k_upd_mma(
        const float* __restrict__ W1, const float* __restrict__ b1,
        const float* __restrict__ W2, const float* __restrict__ b2,
        int si, int di) {
    extern __shared__ char sm[];
    const uint32_t smb = smem_u32(sm);
    int tid = threadIdx.x, lane = tid & 31, wid = tid >> 5;

    for (int i = tid; i < 128 * 64; i += blockDim.x) {
        int k = i >> 6, n = i & 63;
        __half h, l; h_split(W1[i], h, l);
        ((__half*)(sm + UB1H))[n * 136 + k] = h;
        ((__half*)(sm + UB1L))[n * 136 + k] = l;
    }
    for (int i = tid; i < 64 * 64; i += blockDim.x) {
        int k = i >> 6, n = i & 63;
        __half h, l; h_split(W2[i], h, l);
        ((__half*)(sm + UB2H))[n * 72 + k] = h;
        ((__half*)(sm + UB2L))[n * 72 + k] = l;
    }
    if (tid < 64) {
        ((float*)(sm + UBIAS))[tid] = b1[tid];
        ((float*)(sm + UBIAS + 256))[tid] = b2[tid];
    }
    __syncthreads();

    const float* b1s = (const float*)(sm + UBIAS);
    const float* b2s = (const float*)(sm + UBIAS + 256);
    float* xd = g_xb[di];

    const int tig = lane & 3, gid = lane >> 2;
    // inverse perm: phys float2 at word L holds logical word (2*(L>>3)+(L&1))*4 + ((L>>1)&3)
    const int wagg = (2 * (lane >> 3) + (lane & 1)) * 4 + ((lane >> 1) & 3);
    const uint32_t aRow = smb + UA + wid * 4352 + (lane & 15) * 272 + (lane & 16);
    const uint32_t bRow  = ((lane & 7) + ((lane & 16) >> 1));
    const uint32_t b1AddrH = smb + UB1H + bRow * 272 + (lane & 8) * 2;
    const uint32_t b1AddrL = b1AddrH + (UB1L - UB1H);
    const uint32_t b2AddrH = smb + UB2H + bRow * 144 + (lane & 8) * 2;
    const uint32_t b2AddrL = b2AddrH + (UB2L - UB2H);
    char* aRowPtr = sm + UA + wid * 4352;

    int gw = blockIdx.x * 8 + wid;
    int nw = gridDim.x * 8;
    for (int chunk = gw; chunk < NN / 16; chunk += nw) {
        int base16 = chunk * 16;
        #pragma unroll 4
        for (int t = 0; t < 16; t++) {
            int n = base16 + t;
            float2* agp = (float2*)(g_agg + (size_t)n * H) + lane;
            float2 ag = *agp;
            *agp = make_float2(0.f, 0.f);
            char* rp = aRowPtr + t * 272;
            ((unsigned*)rp)[lane]         = g_xf[n * 32 + lane];
            ((unsigned*)(rp + 128))[wagg] = pack_h2(ag.x, ag.y);
        }
        __syncwarp();

        float acc[8][4];
        #pragma unroll
        for (int n = 0; n < 8; n++)
            #pragma unroll
            for (int j = 0; j < 4; j++) acc[n][j] = 0.f;

        #pragma unroll 2
        for (int kt = 0; kt < 8; kt++) {
            uint32_t ah[4];
            LDSM4(ah, aRow + kt * 32);
            #pragma unroll
            for (int ng = 0; ng < 4; ng++) {
                uint32_t bh[4], bl[4];
                LDSM4(bh, b1AddrH + ng * 16 * 272 + kt * 32);
                LDSM4(bl, b1AddrL + ng * 16 * 272 + kt * 32);
                MMA16816(acc[2 * ng],     ah, bh[0], bh[1]);
                MMA16816(acc[2 * ng],     ah, bl[0], bl[1]);
                MMA16816(acc[2 * ng + 1], ah, bh[2], bh[3]);
                MMA16816(acc[2 * ng + 1], ah, bl[2], bl[3]);
            }
        }

        float acc2[8][4];
        #pragma unroll
        for (int n = 0; n < 8; n++)
            #pragma unroll
            for (int j = 0; j < 4; j++) acc2[n][j] = 0.f;

        #pragma unroll
        for (int kt = 0; kt < 4; kt++) {
            uint32_t a2[4];
            #pragma unroll
            for (int j = 0; j < 2; j++) {
                int nt = kt * 2 + j;
                float2 bb = *(const float2*)(b1s + nt * 8 + 2 * tig);
                float v0 = fmaxf(acc[nt][0] + bb.x, 0.f);
                float v1 = fmaxf(acc[nt][1] + bb.y, 0.f);
                float v2 = fmaxf(acc[nt][2] + bb.x, 0.f);
                float v3 = fmaxf(acc[nt][3] + bb.y, 0.f);
                a2[2 * j]     = pack_h2(v0, v1);
                a2[2 * j + 1] = pack_h2(v2, v3);
            }
            #pragma unroll
            for (int ng = 0; ng < 4; ng++) {
                uint32_t bh[4], bl[4];
                LDSM4(bh, b2AddrH + ng * 16 * 144 + kt * 32);
                LDSM4(bl, b2AddrL + ng * 16 * 144 + kt * 32);
                MMA16816(acc2[2 * ng],     a2, bh[0], bh[1]);
                MMA16816(acc2[2 * ng],     a2, bl[0], bl[1]);
                MMA16816(acc2[2 * ng + 1], a2, bh[2], bh[3]);
                MMA16816(acc2[2 * ng + 1], a2, bl[2], bl[3]);
            }
        }

        int n0 = base16 + gid, n1 = base16 + gid + 8;
        #pragma unroll
        for (int nt = 0; nt < 8; nt++) {
            float2 bb = *(const float2*)(b2s + nt * 8 + 2 * tig);
            float f0 = acc2[nt][0] + bb.x, f1 = acc2[nt][1] + bb.y;
            float f2 = acc2[nt][2] + bb.x, f3 = acc2[nt][3] + bb.y;
            *(float2*)(xd + (size_t)n0 * H + nt * 8 + 2 * tig) = make_float2(f0, f1);
            *(float2*)(xd + (size_t)n1 * H + nt * 8 + 2 * tig) = make_float2(f2, f3);
            g_xf[n0 * 32 + nt * 4 + tig] = pack_h2(f0, f1);
            g_xf[n1 * 32 + nt * 4 + tig] = pack_h2(f2, f3);
        }
        __syncwarp();
    }
}

// ============================================================
// k_enc_edge_mma: writes e fp16 in MMA A-fragment order
// ============================================================
#define EBH 0
#define EBL 9216
#define EBIAS 18432
#define EA 18688
#define ENC_SMEM (18688 + 8 * 2304)

__global__ void __launch_bounds__(256) k_enc_edge_mma(const float* __restrict__ ef,
        const float* __restrict__ W, const float* __restrict__ b) {
    extern __shared__ char sm[];
    const uint32_t smb = smem_u32(sm);
    int tid = threadIdx.x, lane = tid & 31, wid = tid >> 5;

    for (int i = tid; i < 64 * 64; i += blockDim.x) {
        int k = i >> 6, n = i & 63;
        __half h, l; h_split(W[i], h, l);
        ((__half*)(sm + EBH))[n * 72 + k] = h;
        ((__half*)(sm + EBL))[n * 72 + k] = l;
    }
    if (tid < 64) ((float*)(sm + EBIAS))[tid] = b[tid];
    __syncthreads();

    const float* bs = (const float*)(sm + EBIAS);
    const int tig = lane & 3;
    const int gi = lane >> 2;
    const uint32_t aRow = smb + EA + wid * 2304 + (lane & 15) * 144 + (lane & 16);
    const uint32_t bRow  = ((lane & 7) + ((lane & 16) >> 1));
    const uint32_t bAddrH = smb + EBH + bRow * 144 + (lane & 8) * 2;
    const uint32_t bAddrL = bAddrH + (EBL - EBH);
    char* aRowPtr = sm + EA + wid * 2304;

    int gw = blockIdx.x * 8 + wid;
    int nw = gridDim.x * 8;
    for (int chunk = gw; chunk < NE / 16; chunk += nw) {
        int base16 = chunk * 16;
        #pragma unroll 4
        for (int t = 0; t < 16; t++) {
            float2 v = ((const float2*)(ef + (size_t)(base16 + t) * H))[lane];
            ((unsigned*)(aRowPtr + t * 144))[lane] = pack_h2(v.x, v.y);
        }
        __syncwarp();

        float acc[8][4];
        #pragma unroll
        for (int n = 0; n < 8; n++)
            #pragma unroll
            for (int j = 0; j < 4; j++) acc[n][j] = 0.f;

        #pragma unroll
        for (int kt = 0; kt < 4; kt++) {
            uint32_t ah[4];
            LDSM4(ah, aRow + kt * 32);
            #pragma unroll
            for (int ng = 0; ng < 4; ng++) {
                uint32_t bh[4], bl[4];
                LDSM4(bh, bAddrH + ng * 16 * 144 + kt * 32);
                LDSM4(bl, bAddrL + ng * 16 * 144 + kt * 32);
                MMA16816(acc[2 * ng],     ah, bh[0], bh[1]);
                MMA16816(acc[2 * ng],     ah, bl[0], bl[1]);
                MMA16816(acc[2 * ng + 1], ah, bh[2], bh[3]);
                MMA16816(acc[2 * ng + 1], ah, bl[2], bl[3]);
            }
        }

        // write A-fragment order: word(row r, colpair p): kt=p>>3, jj=(p>>2)&1, t=p&3
        //   idx = kt*128 + ((r&7)*4 + t)*4 + 2*jj + (r>>3)
        unsigned* de = g_et + (size_t)chunk * 512;
        #pragma unroll
        for (int nt = 0; nt < 8; nt++) {
            float2 bb = *(const float2*)(bs + nt * 8 + 2 * tig);
            float f0 = acc[nt][0] + bb.x, f1 = acc[nt][1] + bb.y;
            float f2 = acc[nt][2] + bb.x, f3 = acc[nt][3] + bb.y;
            int idx = (nt >> 1) * 128 + (gi * 4 + tig) * 4 + 2 * (nt & 1);
            de[idx]     = pack_h2(f0, f1);   // row gi
            de[idx + 1] = pack_h2(f2, f3);   // row gi+8
        }
        __syncwarp();
    }
}

// ============================================================
// k_enc_node: scalar f32x2; writes fp32 x + fp16 x
// ============================================================
__device__ __forceinline__ void ffma2(ull& d, ull a, ull b) {
    asm("fma.rn.f32x2 %0, %1, %2, %0;" : "+l"(d) : "l"(a), "l"(b));
}
__device__ __forceinline__ float fin(ull a, float b) {
    return __uint_as_float((unsigned)a) + __uint_as_float((unsigned)(a >> 32)) + b;
}

__global__ void __launch_bounds__(256) k_enc_node(const float* __restrict__ nf,
        const float* __restrict__ W, const float* __restrict__ b) {
    extern __shared__ float smf[];
    float* Wp   = smf;
    float* winb = Wp + 8320;
    int tid = threadIdx.x;
    for (int i = tid; i < 128 * 64; i += 256) {
        int k = i >> 6, c = i & 63;
        Wp[(c >> 1) * 260 + (k >> 1) * 4 + ((c & 1) << 1) + (k & 1)] = W[i];
    }
    __syncthreads();
    int lane = tid & 31, wid = tid >> 5;
    float2 bb = ((const float2*)b)[lane];
    float* win = winb + wid * 8 * ND;
    const ulonglong2* wl = (const ulonglong2*)(Wp + (size_t)lane * 260);
    int gw = blockIdx.x * 8 + wid;
    int nw = gridDim.x * 8;
    for (int base = gw * 8; base < NN; base += nw * 8) {
        #pragma unroll
        for (int t = 0; t < 8; t++) {
            float4 v = *(const float4*)(nf + (size_t)(base + t) * ND + lane * 4);
            *(float4*)(win + t * ND + lane * 4) = v;
        }
        __syncwarp();
        ull a0[8], a1[8];
        #pragma unroll
        for (int t = 0; t < 8; t++) { a0[t] = 0ull; a1[t] = 0ull; }
        #pragma unroll 4
        for (int c = 0; c < 32; c++) {
            ulonglong2 wA = wl[2 * c];
            ulonglong2 wB = wl[2 * c + 1];
            #pragma unroll
            for (int t = 0; t < 8; t++) {
                ulonglong2 v = ((const ulonglong2*)(win + t * ND))[c];
                ffma2(a0[t], wA.x, v.x); ffma2(a1[t], wA.y, v.x);
                ffma2(a0[t], wB.x, v.y); ffma2(a1[t], wB.y, v.y);
            }
        }
        #pragma unroll
        for (int t = 0; t < 8; t++) {
            float o0 = fin(a0[t], bb.x);
            float o1 = fin(a1[t], bb.y);
            int n = base + t;
            *(float2*)(g_xb[0] + (size_t)n * H + 2 * lane) = make_float2(o0, o1);
            g_xf[n * 32 + lane] = pack_h2(o0, o1);
        }
        __syncwarp();
    }
}

__global__ void k_con(const float* __restrict__ W1, const float* __restrict__ b1,
                      const float* __restrict__ w2, const float* __restrict__ b2,
                      int si, float* __restrict__ out) {
    __shared__ float Ws[H * H];
    __shared__ float bs[H];
    __shared__ float w2s[H];
    __shared__ float xb[8][H];
    __shared__ float b2v;
    int tid = threadIdx.x;
    for (int i = tid; i < H * H; i += blockDim.x) Ws[i] = W1[i];
    if (tid < H) { bs[tid] = b1[tid]; w2s[tid] = w2[tid]; }
    if (tid == 0) b2v = b2[0];
    __syncthreads();
    const float* xs = g_xb[si];
    int lane = tid & 31, wid = tid >> 5;
    int gw = blockIdx.x * 8 + wid;
    int nw = gridDim.x * 8;
    for (int n = gw; n < NN; n += nw) {
        float xv0 = xs[(size_t)n * H + lane];
        float xv1 = xs[(size_t)n * H + lane + 32];
        out[(size_t)n * H + lane]      = xv0;
        out[(size_t)n * H + lane + 32] = xv1;
        xb[wid][lane]      = xv0;
        xb[wid][lane + 32] = xv1;
        __syncwarp();
        float a0 = bs[lane], a1 = bs[lane + 32];
        #pragma unroll 4
        for (int k = 0; k < H; k++) {
            float v = xb[wid][k];
            a0 += v * Ws[k * H + lane];
            a1 += v * Ws[k * H + lane + 32];
        }
        float p = fmaxf(a0, 0.f) * w2s[lane] + fmaxf(a1, 0.f) * w2s[lane + 32];
        #pragma unroll
        for (int o = 16; o; o >>= 1) p += __shfl_xor_sync(0xffffffffu, p, o);
        if (lane == 0)
            out[(size_t)NN * H + n] = 1.f / (1.f + expf(-(p + b2v)));
        __syncwarp();
    }
}

extern "C" void kernel_launch(void* const* d_in, const int* in_sizes, int n_in,
                              void* d_out, int out_size) {
    const float* nf  = (const float*)d_in[0];
    const float* ef  = (const float*)d_in[1];
    const int*   ei  = (const int*)d_in[2];
    const float* enW = (const float*)d_in[3];
    const float* enb = (const float*)d_in[4];
    const float* eeW = (const float*)d_in[5];
    const float* eeb = (const float*)d_in[6];
    const float* mW1 = (const float*)d_in[7];
    const float* mb1 = (const float*)d_in[8];
    const float* mW2 = (const float*)d_in[9];
    const float* mb2 = (const float*)d_in[10];
    const float* uW1 = (const float*)d_in[11];
    const float* ub1 = (const float*)d_in[12];
    const float* uW2 = (const float*)d_in[13];
    const float* ub2 = (const float*)d_in[14];
    const float* cW1 = (const float*)d_in[15];
    const float* cb1 = (const float*)d_in[16];
    const float* cW2 = (const float*)d_in[17];
    const float* cb2 = (const float*)d_in[18];
    float* out = (float*)d_out;

    int dev = 0, smc = 148;
    cudaGetDevice(&dev);
    cudaDeviceGetAttribute(&smc, cudaDevAttrMultiProcessorCount, dev);

    const int ENN_SMEM = (8320 + 8192) * 4;
    cudaFuncSetAttribute(k_pre,          cudaFuncAttributeMaxDynamicSharedMemorySize, PRE_SMEM);
    cudaFuncSetAttribute(k_msg_mma,      cudaFuncAttributeMaxDynamicSharedMemorySize, MSG_SMEM);
    cudaFuncSetAttribute(k_upd_mma,      cudaFuncAttributeMaxDynamicSharedMemorySize, UPD_SMEM);
    cudaFuncSetAttribute(k_enc_edge_mma, cudaFuncAttributeMaxDynamicSharedMemorySize, ENC_SMEM);
    cudaFuncSetAttribute(k_enc_node,     cudaFuncAttributeMaxDynamicSharedMemorySize, ENN_SMEM);

    k_enc_node<<<smc * 2, 256, ENN_SMEM>>>(nf, enW, enb);
    k_enc_edge_mma<<<smc * 2, 256, ENC_SMEM>>>(ef, eeW, eeb);

    int cur = 0;
    for (int l = 0; l < 3; l++) {
        k_pre<<<smc * 2, 256, PRE_SMEM>>>(mW1 + (size_t)l * 192 * H, mb1 + l * H);
        k_msg_mma<<<smc * 2, 256, MSG_SMEM>>>(ei,
                                              mW1 + (size_t)l * 192 * H,
                                              mW2 + (size_t)l * H * H, mb2 + l * H);
        k_upd_mma<<<smc * 2, 256, UPD_SMEM>>>(uW1 + (size_t)l * 128 * H, ub1 + l * H,
                                              uW2 + (size_t)l * H * H,   ub2 + l * H,
                                              cur, 1 - cur);
        cur = 1 - cur;
    }
    k_con<<<1184, 256>>>(cW1, cb1, cW2, cb2, cur, out);
}